// round 1
// baseline (speedup 1.0000x reference)
#include <cuda_runtime.h>
#include <cuda_bf16.h>
#include <math.h>

#define NROWS 131072
#define EDGES 1048576
#define CC 64
#define TT 128
#define BB 128
#define NNODE 8

// ---------------- scratch (device globals: no allocation allowed) ----------------
__device__ float g_bufA[NROWS * CC];
__device__ float g_bufB[NROWS * CC];
__device__ float g_bufC[NROWS * CC];
__device__ float g_deg[NROWS];      // holds deg, then dinv
__device__ float g_stats[256];      // [0:64) sum, [64:128) sumsq, [128:192) scale, [192:256) shift
__device__ float g_wbar[65];        // mean over 8 reg cols + mean bias

// ---------------- small utility kernels ----------------
__global__ void zero_kernel() {
    int i = blockIdx.x * blockDim.x + threadIdx.x;
    if (i < NROWS) g_deg[i] = 0.0f;
    if (i < 256) g_stats[i] = 0.0f;
}

__global__ void deg_count_kernel(const int* __restrict__ dst) {
    int e = blockIdx.x * blockDim.x + threadIdx.x;
    if (e < EDGES) atomicAdd(&g_deg[dst[e]], 1.0f);
}

__global__ void dinv_kernel() {
    int i = blockIdx.x * blockDim.x + threadIdx.x;
    if (i < NROWS) g_deg[i] = rsqrtf(g_deg[i] + 1.0f);   // self loop
}

__global__ void wbar_kernel(const float* __restrict__ rw, const float* __restrict__ rb) {
    int c = threadIdx.x;
    if (c < 64) {
        float s = 0.f;
        #pragma unroll
        for (int j = 0; j < 8; j++) s += rw[c * 8 + j];
        g_wbar[c] = s * 0.125f;
    }
    if (c == 0) {
        float s = 0.f;
        #pragma unroll
        for (int j = 0; j < 8; j++) s += rb[j];
        g_wbar[64] = s * 0.125f;
    }
}

// ---------------- dense GEMM: O[N,64] = A[N,K] @ W[K,64] ----------------
template <int K>
__global__ void gemm_kernel(const float* __restrict__ A, const float* __restrict__ W,
                            float* __restrict__ O) {
    __shared__ float As[64][K + 1];
    __shared__ float Ws[K][68];
    int tid = threadIdx.x;           // 256
    int row0 = blockIdx.x * 64;

    for (int i = tid; i < K * 64; i += 256) Ws[i / 64][i & 63] = W[i];
    for (int i = tid; i < 64 * K; i += 256) {
        int r = i / K, c = i % K;
        As[r][c] = A[(row0 + r) * K + c];
    }
    __syncthreads();

    int tr = (tid >> 4) << 2;        // 0..60
    int tc = (tid & 15) << 2;        // 0..60
    float acc[4][4];
    #pragma unroll
    for (int i = 0; i < 4; i++)
        #pragma unroll
        for (int j = 0; j < 4; j++) acc[i][j] = 0.f;

    #pragma unroll 8
    for (int k = 0; k < K; k++) {
        float a[4], b[4];
        #pragma unroll
        for (int i = 0; i < 4; i++) a[i] = As[tr + i][k];
        #pragma unroll
        for (int j = 0; j < 4; j++) b[j] = Ws[k][tc + j];
        #pragma unroll
        for (int i = 0; i < 4; i++)
            #pragma unroll
            for (int j = 0; j < 4; j++) acc[i][j] = fmaf(a[i], b[j], acc[i][j]);
    }
    #pragma unroll
    for (int i = 0; i < 4; i++)
        #pragma unroll
        for (int j = 0; j < 4; j++)
            O[(row0 + tr + i) * 64 + tc + j] = acc[i][j];
}

// ---------------- GCN aggregation ----------------
// agg[i,:] = h[i,:] * dinv[i]^2 + bias   (self loop + PyG bias)
__global__ void agg_init_kernel(const float* __restrict__ h, const float* __restrict__ bias,
                                float* __restrict__ agg) {
    int idx = blockIdx.x * blockDim.x + threadIdx.x;   // NROWS*16 float4 slots
    int row = idx >> 4, q = idx & 15;
    float s = g_deg[row]; s = s * s;
    float4 v = ((const float4*)h)[idx];
    float4 b = ((const float4*)bias)[q];
    float4 o;
    o.x = fmaf(v.x, s, b.x); o.y = fmaf(v.y, s, b.y);
    o.z = fmaf(v.z, s, b.z); o.w = fmaf(v.w, s, b.w);
    ((float4*)agg)[idx] = o;
}

// agg[d,:] += h[s,:] * dinv[s]*dinv[d]  (16 threads/edge, float4 atomics)
__global__ void edge_agg_kernel(const float* __restrict__ h, const int* __restrict__ src,
                                const int* __restrict__ dst, float* __restrict__ agg) {
    int idx = blockIdx.x * blockDim.x + threadIdx.x;   // EDGES*16
    int e = idx >> 4, q = idx & 15;
    int s = __ldg(&src[e]);
    int d = __ldg(&dst[e]);
    float w = g_deg[s] * g_deg[d];
    float4 v = ((const float4*)h)[s * 16 + q];
    float4 m = make_float4(v.x * w, v.y * w, v.z * w, v.w * w);
    atomicAdd((float4*)(agg + d * 64 + q * 4), m);
}

// ---------------- temporal (1,3) conv, pad (0,1) ----------------
// in  : [row=(b*T+t)*8+n, c]
// out : same layout, channels c2, + bias
#define TCONV_SMEM ((130 * 64 + 64 * 3 * 64) * 4)
__global__ void tconv_kernel(const float* __restrict__ in, const float* __restrict__ tw,
                             const float* __restrict__ tb, float* __restrict__ out) {
    extern __shared__ float sm[];
    float* xs = sm;                  // [130][64], t index shifted by +1, rows 0 & 129 zero
    float* ws = sm + 130 * 64;       // [(c*3+k)][c2]
    int bn = blockIdx.x;
    int b = bn >> 3, n = bn & 7;
    int tid = threadIdx.x;           // 256

    for (int i = tid; i < 64; i += 256) { xs[i] = 0.f; xs[129 * 64 + i] = 0.f; }
    const float4* in4 = (const float4*)in;
    for (int i = tid; i < 128 * 16; i += 256) {
        int t = i >> 4, q = i & 15;
        ((float4*)xs)[(t + 1) * 16 + q] = in4[((b * 128 + t) * 8 + n) * 16 + q];
    }
    // tw[(c2*64+c)*3+k] -> ws[(c*3+k)*64+c2]
    for (int i = tid; i < 12288; i += 256) {
        int c2 = i & 63, rest = i >> 6;
        int c = rest / 3, k = rest - 3 * c;
        ws[i] = tw[(c2 * 64 + c) * 3 + k];
    }
    __syncthreads();

    int c2 = tid & 63, tq = tid >> 6;
    float bias = tb[c2];
    for (int chunk = 0; chunk < 4; chunk++) {
        int t0 = tq * 32 + chunk * 8;
        float acc[8];
        #pragma unroll
        for (int j = 0; j < 8; j++) acc[j] = bias;
        for (int c = 0; c < 64; c++) {
            float w0 = ws[(c * 3 + 0) * 64 + c2];
            float w1 = ws[(c * 3 + 1) * 64 + c2];
            float w2 = ws[(c * 3 + 2) * 64 + c2];
            float xv[10];
            #pragma unroll
            for (int j = 0; j < 10; j++) xv[j] = xs[(t0 + j) * 64 + c];
            #pragma unroll
            for (int j = 0; j < 8; j++)
                acc[j] = fmaf(w0, xv[j], fmaf(w1, xv[j + 1], fmaf(w2, xv[j + 2], acc[j])));
        }
        #pragma unroll
        for (int j = 0; j < 8; j++)
            out[((b * 128 + t0 + j) * 8 + n) * 64 + c2] = acc[j];
    }
}

// ---------------- batch-norm statistics ----------------
__global__ void bn_stats_kernel(const float* __restrict__ tmp) {
    int c = threadIdx.x & 63, g = threadIdx.x >> 6;   // 256 threads
    int base = blockIdx.x * 512;                      // 256 blocks
    float s = 0.f, q = 0.f;
    for (int i = g; i < 512; i += 4) {
        float v = tmp[(base + i) * 64 + c];
        s += v; q = fmaf(v, v, q);
    }
    __shared__ float shs[4][64], shq[4][64];
    shs[g][c] = s; shq[g][c] = q;
    __syncthreads();
    if (g == 0) {
        s = shs[0][c] + shs[1][c] + shs[2][c] + shs[3][c];
        q = shq[0][c] + shq[1][c] + shq[2][c] + shq[3][c];
        atomicAdd(&g_stats[c], s);
        atomicAdd(&g_stats[64 + c], q);
    }
}

__global__ void bn_final_kernel(const float* __restrict__ gam, const float* __restrict__ beta) {
    int c = threadIdx.x;   // 64
    const float inv_cnt = 1.0f / 131072.0f;
    float mu = g_stats[c] * inv_cnt;
    float var = g_stats[64 + c] * inv_cnt - mu * mu;
    float sc = gam[c] * rsqrtf(var + 1e-5f);
    g_stats[128 + c] = sc;
    g_stats[192 + c] = beta[c] - mu * sc;
    g_stats[c] = 0.f;           // reset sums for next layer
    g_stats[64 + c] = 0.f;
}

// ---------------- fused bn->relu->1x1 conv->tanh, scrambled store ----------------
// z flat layout = [B,C2,NN,T] : addr = ((b*64+c2)*8+n)*128 + t  (faithful to view(-1,C))
__global__ void fused_out_kernel(const float* __restrict__ tmp, const float* __restrict__ ow,
                                 const float* __restrict__ ob, float* __restrict__ z) {
    __shared__ float ys[64][65];
    __shared__ float ws[64][68];   // ws[c][c2] = ow[c2*64+c]
    __shared__ float sc[64], sh[64], obs[64];
    int tid = threadIdx.x;         // 256
    int row0 = blockIdx.x * 64;

    if (tid < 64) {
        sc[tid] = g_stats[128 + tid];
        sh[tid] = g_stats[192 + tid];
        obs[tid] = ob[tid];
    }
    for (int i = tid; i < 4096; i += 256) {
        int c2 = i >> 6, c = i & 63;
        ws[c][c2] = ow[i];
    }
    __syncthreads();
    for (int i = tid; i < 4096; i += 256) {
        int r = i >> 6, c = i & 63;
        float v = tmp[(row0 + r) * 64 + c];
        ys[r][c] = fmaxf(0.f, fmaf(v, sc[c], sh[c]));
    }
    __syncthreads();

    int tr = (tid >> 4) << 2, tc = (tid & 15) << 2;
    float acc[4][4];
    #pragma unroll
    for (int i = 0; i < 4; i++)
        #pragma unroll
        for (int j = 0; j < 4; j++) acc[i][j] = 0.f;

    #pragma unroll 8
    for (int k = 0; k < 64; k++) {
        float a[4], b[4];
        #pragma unroll
        for (int i = 0; i < 4; i++) a[i] = ys[tr + i][k];
        #pragma unroll
        for (int j = 0; j < 4; j++) b[j] = ws[k][tc + j];
        #pragma unroll
        for (int i = 0; i < 4; i++)
            #pragma unroll
            for (int j = 0; j < 4; j++) acc[i][j] = fmaf(a[i], b[j], acc[i][j]);
    }
    #pragma unroll
    for (int i = 0; i < 4; i++) {
        int r = row0 + tr + i;
        int b = r >> 10, t = (r >> 3) & 127, n = r & 7;
        #pragma unroll
        for (int j = 0; j < 4; j++) {
            int c2 = tc + j;
            z[((b * 64 + c2) * 8 + n) * 128 + t] = tanhf(acc[i][j] + obs[c2]);
        }
    }
}

// ---------------- final regression + mean ----------------
// out[b,n] = (1/T) sum_t ( z[(b*T+t)*8+n, :] . wbar ) + bbar
__global__ void final_kernel(const float* __restrict__ z, float* __restrict__ out) {
    int bn = blockIdx.x;            // 1024
    int b = bn >> 3, n = bn & 7;
    int t = threadIdx.x;            // 128
    __shared__ float wb[64];
    if (t < 64) wb[t] = g_wbar[t];
    __syncthreads();

    const float4* row = (const float4*)(z + ((b * 128 + t) * 8 + n) * 64);
    const float4* w4 = (const float4*)wb;
    float s = 0.f;
    #pragma unroll
    for (int i = 0; i < 16; i++) {
        float4 v = row[i], w = w4[i];
        s += v.x * w.x + v.y * w.y + v.z * w.z + v.w * w.w;
    }
    #pragma unroll
    for (int o = 16; o > 0; o >>= 1) s += __shfl_down_sync(0xffffffffu, s, o);
    __shared__ float part[4];
    if ((t & 31) == 0) part[t >> 5] = s;
    __syncthreads();
    if (t == 0) {
        float tot = part[0] + part[1] + part[2] + part[3];
        out[bn] = tot * (1.0f / 128.0f) + g_wbar[64];
    }
}

// ---------------- host launcher ----------------
extern "C" void kernel_launch(void* const* d_in, const int* in_sizes, int n_in,
                              void* d_out, int out_size) {
    const float* x      = (const float*)d_in[0];
    const int*   ei     = (const int*)d_in[1];
    const float* gcn1_w = (const float*)d_in[2];
    const float* gcn1_b = (const float*)d_in[3];
    const float* t1_w   = (const float*)d_in[4];
    const float* t1_b   = (const float*)d_in[5];
    const float* bn1_g  = (const float*)d_in[6];
    const float* bn1_b  = (const float*)d_in[7];
    const float* o1_w   = (const float*)d_in[8];
    const float* o1_b   = (const float*)d_in[9];
    const float* gcn2_w = (const float*)d_in[10];
    const float* gcn2_b = (const float*)d_in[11];
    const float* t2_w   = (const float*)d_in[12];
    const float* t2_b   = (const float*)d_in[13];
    const float* bn2_g  = (const float*)d_in[14];
    const float* bn2_b  = (const float*)d_in[15];
    const float* o2_w   = (const float*)d_in[16];
    const float* o2_b   = (const float*)d_in[17];
    const float* reg_w  = (const float*)d_in[18];
    const float* reg_b  = (const float*)d_in[19];
    float* out = (float*)d_out;

    const int* src = ei;
    const int* dst = ei + EDGES;

    static bool attr_set = false;
    cudaFuncSetAttribute(tconv_kernel, cudaFuncAttributeMaxDynamicSharedMemorySize, TCONV_SMEM);
    (void)attr_set;

    float* bufA; cudaGetSymbolAddress((void**)&bufA, g_bufA);
    float* bufB; cudaGetSymbolAddress((void**)&bufB, g_bufB);
    float* bufC; cudaGetSymbolAddress((void**)&bufC, g_bufC);

    zero_kernel<<<512, 256>>>();
    deg_count_kernel<<<EDGES / 256, 256>>>(dst);
    dinv_kernel<<<NROWS / 256, 256>>>();
    wbar_kernel<<<1, 64>>>(reg_w, reg_b);

    // -------- layer 1 --------
    gemm_kernel<32><<<NROWS / 64, 256>>>(x, gcn1_w, bufA);
    agg_init_kernel<<<NROWS * 16 / 256, 256>>>(bufA, gcn1_b, bufB);
    edge_agg_kernel<<<EDGES * 16 / 256, 256>>>(bufA, src, dst, bufB);
    tconv_kernel<<<BB * NNODE, 256, TCONV_SMEM>>>(bufB, t1_w, t1_b, bufC);
    bn_stats_kernel<<<NROWS / 512, 256>>>(bufC);
    bn_final_kernel<<<1, 64>>>(bn1_g, bn1_b);
    fused_out_kernel<<<NROWS / 64, 256>>>(bufC, o1_w, o1_b, bufA);

    // -------- layer 2 --------
    gemm_kernel<64><<<NROWS / 64, 256>>>(bufA, gcn2_w, bufB);
    agg_init_kernel<<<NROWS * 16 / 256, 256>>>(bufB, gcn2_b, bufC);
    edge_agg_kernel<<<EDGES * 16 / 256, 256>>>(bufB, src, dst, bufC);
    tconv_kernel<<<BB * NNODE, 256, TCONV_SMEM>>>(bufC, t2_w, t2_b, bufA);
    bn_stats_kernel<<<NROWS / 512, 256>>>(bufA);
    bn_final_kernel<<<1, 64>>>(bn2_g, bn2_b);
    fused_out_kernel<<<NROWS / 64, 256>>>(bufA, o2_w, o2_b, bufB);

    // -------- regression + mean --------
    final_kernel<<<BB * NNODE, 128>>>(bufB, out);
}

// round 2
// speedup vs baseline: 1.0096x; 1.0096x over previous
#include <cuda_runtime.h>
#include <cuda_bf16.h>
#include <math.h>

#define NROWS 131072
#define EDGES 1048576
#define CC 64
#define BB 128
#define NNODE 8

// ---------------- scratch (device globals: no allocation allowed) ----------------
__device__ float g_bufA[NROWS * CC];
__device__ float g_bufB[NROWS * CC];
__device__ float g_bufC[NROWS * CC];
__device__ float g_deg[NROWS];      // holds deg, then dinv
__device__ float g_stats[256];      // layer1: [0:64) sum [64:128) sumsq ; layer2: [128:192) sum [192:256) sumsq
__device__ float g_wbar[65];        // mean over 8 reg cols + mean bias
__device__ float g_tw1[12288];      // transposed temporal weights layer1: [(c*3+k)*64 + c2]
__device__ float g_tw2[12288];

// ---------------- f32x2 packed math helpers ----------------
typedef unsigned long long ull;
__device__ __forceinline__ ull pk2(float x) {
    ull u; asm("mov.b64 %0,{%1,%2};" : "=l"(u) : "f"(x), "f"(x)); return u;
}
__device__ __forceinline__ ull pk(float x, float y) {
    ull u; asm("mov.b64 %0,{%1,%2};" : "=l"(u) : "f"(x), "f"(y)); return u;
}
__device__ __forceinline__ float2 upk(ull u) {
    float2 r; asm("mov.b64 {%0,%1},%2;" : "=f"(r.x), "=f"(r.y) : "l"(u)); return r;
}
__device__ __forceinline__ ull fma2_(ull a, ull b, ull c) {
    ull d; asm("fma.rn.f32x2 %0,%1,%2,%3;" : "=l"(d) : "l"(a), "l"(b), "l"(c)); return d;
}

// ---------------- prologue: zero + wbar + weight transpose ----------------
__global__ void prologue_kernel(const float* __restrict__ rw, const float* __restrict__ rb,
                                const float* __restrict__ t1w, const float* __restrict__ t2w) {
    int i = blockIdx.x * blockDim.x + threadIdx.x;      // 131072 threads
    if (i < NROWS) g_deg[i] = 0.0f;
    if (i < 256) g_stats[i] = 0.0f;
    if (i < 12288) {
        // dst layout (c*3+k)*64 + c2  <-  src tw[(c2*64+c)*3+k]
        int c2 = i & 63, rest = i >> 6;
        int c = rest / 3, k = rest - 3 * c;
        int s = (c2 * 64 + c) * 3 + k;
        g_tw1[i] = t1w[s];
        g_tw2[i] = t2w[s];
    }
    if (i < 64) {
        float s = 0.f;
        #pragma unroll
        for (int j = 0; j < 8; j++) s += rw[i * 8 + j];
        g_wbar[i] = s * 0.125f;
    }
    if (i == 64) {
        float s = 0.f;
        #pragma unroll
        for (int j = 0; j < 8; j++) s += rb[j];
        g_wbar[64] = s * 0.125f;
    }
}

__global__ void deg_count_kernel(const int* __restrict__ dst) {
    int e = blockIdx.x * blockDim.x + threadIdx.x;
    if (e < EDGES) atomicAdd(&g_deg[dst[e]], 1.0f);
}

__global__ void dinv_kernel() {
    int i = blockIdx.x * blockDim.x + threadIdx.x;
    if (i < NROWS) g_deg[i] = rsqrtf(g_deg[i] + 1.0f);   // self loop
}

// ---------------- dense GEMM fused with GCN init ----------------
// hs[r,:]  = (A@W)[r,:] * dinv[r]                (edge gather source)
// agg[r,:] = (A@W)[r,:] * dinv[r]^2 + bias       (self-loop + bias init)
template <int K>
__global__ void gemm_gcn_kernel(const float* __restrict__ A, const float* __restrict__ W,
                                const float* __restrict__ bias,
                                float* __restrict__ hs, float* __restrict__ agg) {
    __shared__ float As[64][K + 1];
    __shared__ float Ws[K][68];
    __shared__ float bs[64];
    int tid = threadIdx.x;           // 256
    int row0 = blockIdx.x * 64;

    if (tid < 64) bs[tid] = bias[tid];
    for (int i = tid; i < K * 64; i += 256) Ws[i / 64][i & 63] = W[i];
    for (int i = tid; i < 64 * K; i += 256) {
        int r = i / K, c = i % K;
        As[r][c] = A[(row0 + r) * K + c];
    }
    __syncthreads();

    int tr = (tid >> 4) << 2;
    int tc = (tid & 15) << 2;
    float acc[4][4];
    #pragma unroll
    for (int i = 0; i < 4; i++)
        #pragma unroll
        for (int j = 0; j < 4; j++) acc[i][j] = 0.f;

    #pragma unroll 8
    for (int k = 0; k < K; k++) {
        float a[4], b[4];
        #pragma unroll
        for (int i = 0; i < 4; i++) a[i] = As[tr + i][k];
        #pragma unroll
        for (int j = 0; j < 4; j++) b[j] = Ws[k][tc + j];
        #pragma unroll
        for (int i = 0; i < 4; i++)
            #pragma unroll
            for (int j = 0; j < 4; j++) acc[i][j] = fmaf(a[i], b[j], acc[i][j]);
    }
    #pragma unroll
    for (int i = 0; i < 4; i++) {
        int r = row0 + tr + i;
        float dv = g_deg[r];
        float dv2 = dv * dv;
        #pragma unroll
        for (int j = 0; j < 4; j++) {
            float v = acc[i][j];
            hs[r * 64 + tc + j]  = v * dv;
            agg[r * 64 + tc + j] = fmaf(v, dv2, bs[tc + j]);
        }
    }
}

// ---------------- edge aggregation: agg[d,:] += hs[s,:] * dinv[d] ----------------
__global__ void edge_agg_kernel(const float* __restrict__ hs, const int* __restrict__ src,
                                const int* __restrict__ dst, float* __restrict__ agg) {
    int idx = blockIdx.x * blockDim.x + threadIdx.x;   // EDGES*8
    int e = idx >> 3, q = idx & 7;
    int s = __ldg(&src[e]);
    int d = __ldg(&dst[e]);
    float w = g_deg[d];
    const float4* hv = ((const float4*)hs) + s * 16 + q * 2;
    float4 a = hv[0], b = hv[1];
    float4 ma = make_float4(a.x * w, a.y * w, a.z * w, a.w * w);
    float4 mb = make_float4(b.x * w, b.y * w, b.z * w, b.w * w);
    float4* dp = (float4*)(agg + d * 64 + q * 8);
    atomicAdd(dp, ma);
    atomicAdd(dp + 1, mb);
}

// ---------------- temporal (1,3) conv with f32x2 + fused BN stats ----------------
// x stored t-contiguous, TWO shifted copies so every conv tap is an aligned LDS.64 pair.
//   copy1: x[t] at s = t+1  (zeros at s=0, s=129)     -> taps k=0 (pairs at s=o)   and k=2 (s=o+2)
//   copy2: x[t] at s = t+2                            -> tap  k=1 (pairs at s=o+2, aligned)
#define XSTR 134
#define CPSZ (64 * XSTR)            // 8576 floats per copy
#define HALFSZ (2 * CPSZ)           // 17152 floats per (b,n)
#define WS_OFF (2 * HALFSZ)         // 34304
#define ST_OFF (WS_OFF + 12288)     // 46592
#define TCONV_SMEM ((ST_OFF + 1024) * 4)   // 190464 bytes

__global__ void tconv_kernel(const float* __restrict__ in, const float* __restrict__ wsg,
                             const float* __restrict__ tb, float* __restrict__ out,
                             int statOff) {
    extern __shared__ float sm[];
    float* ws = sm + WS_OFF;
    int tid = threadIdx.x;           // 512
    int half = tid >> 8;
    int lt = tid & 255;
    int p = blockIdx.x;              // 512 blocks
    int b = p >> 2;
    int n = ((p & 3) << 1) | half;
    float* xs1 = sm + half * HALFSZ;
    float* xs2 = xs1 + CPSZ;

    // weights (pre-transposed, coalesced)
    for (int i = tid; i < 3072; i += 512)
        ((float4*)ws)[i] = ((const float4*)wsg)[i];

    // pads for copy1: s=0 and s=129 per c
    if (lt < 128) {
        int c = lt >> 1, s = (lt & 1) ? 129 : 0;
        xs1[c * XSTR + s] = 0.f;
    }
    // load x transposed into both shifted copies
    const float4* in4 = (const float4*)in;
    for (int i = lt; i < 2048; i += 256) {
        int t = i >> 4, q = i & 15;
        float4 v = in4[((b * 128 + t) * 8 + n) * 16 + q];
        float* r1 = xs1 + (q * 4) * XSTR + (t + 1);
        float* r2 = xs2 + (q * 4) * XSTR + (t + 2);
        r1[0] = v.x; r1[XSTR] = v.y; r1[2 * XSTR] = v.z; r1[3 * XSTR] = v.w;
        r2[0] = v.x; r2[XSTR] = v.y; r2[2 * XSTR] = v.z; r2[3 * XSTR] = v.w;
    }
    __syncthreads();

    int c2 = tid & 63;
    int tq = (tid >> 6) & 3;
    float bias = tb[c2];
    float s_sum = 0.f, s_sq = 0.f;

    for (int chunk = 0; chunk < 4; chunk++) {
        int t0 = tq * 32 + chunk * 8;           // even
        ull acc0 = pk2(bias), acc1 = acc0, acc2 = acc0, acc3 = acc0;
        const float* w0p = ws + c2;
        for (int c = 0; c < 64; c++) {
            const ull* p1 = (const ull*)(xs1 + c * XSTR + t0);
            const ull* p2 = (const ull*)(xs2 + c * XSTR + t0);
            ull A0 = p1[0], A1 = p1[1], A2 = p1[2], A3 = p1[3], A4 = p1[4];
            ull O0 = p2[1], O1 = p2[2], O2 = p2[3], O3 = p2[4];
            const float* wp = w0p + c * 192;
            ull W0 = pk2(wp[0]);
            ull W1 = pk2(wp[64]);
            ull W2 = pk2(wp[128]);
            acc0 = fma2_(W0, A0, fma2_(W1, O0, fma2_(W2, A1, acc0)));
            acc1 = fma2_(W0, A1, fma2_(W1, O1, fma2_(W2, A2, acc1)));
            acc2 = fma2_(W0, A2, fma2_(W1, O2, fma2_(W2, A3, acc2)));
            acc3 = fma2_(W0, A3, fma2_(W1, O3, fma2_(W2, A4, acc3)));
        }
        float2 r0 = upk(acc0), r1 = upk(acc1), r2 = upk(acc2), r3 = upk(acc3);
        float yv[8] = {r0.x, r0.y, r1.x, r1.y, r2.x, r2.y, r3.x, r3.y};
        int base = ((b * 128 + t0) * 8 + n) * 64 + c2;
        #pragma unroll
        for (int j = 0; j < 8; j++) {
            float v = yv[j];
            out[base + j * 512] = v;
            s_sum += v;
            s_sq = fmaf(v, v, s_sq);
        }
    }

    // fused BN statistics: reduce 8 threads per c2, atomicAdd to globals
    float* st = sm + ST_OFF;                    // [8][64] sum, [8][64] sq
    int g = tid >> 6;                            // 0..7
    st[g * 64 + c2] = s_sum;
    st[512 + g * 64 + c2] = s_sq;
    __syncthreads();
    if (tid < 64) {
        float s = 0.f;
        #pragma unroll
        for (int k = 0; k < 8; k++) s += st[k * 64 + tid];
        atomicAdd(&g_stats[statOff + tid], s);
    } else if (tid < 128) {
        int c = tid - 64;
        float s = 0.f;
        #pragma unroll
        for (int k = 0; k < 8; k++) s += st[512 + k * 64 + c];
        atomicAdd(&g_stats[statOff + 64 + c], s);
    }
}

// ---------------- fused bn->relu->1x1 conv->tanh, scrambled store ----------------
__global__ void fused_out_kernel(const float* __restrict__ tmp, const float* __restrict__ ow,
                                 const float* __restrict__ ob, const float* __restrict__ gam,
                                 const float* __restrict__ beta, float* __restrict__ z,
                                 int statOff) {
    __shared__ float ys[64][65];
    __shared__ float ws[64][68];   // ws[c][c2] = ow[c2*64+c]
    __shared__ float sc[64], sh[64], obs[64];
    int tid = threadIdx.x;         // 256
    int row0 = blockIdx.x * 64;

    if (tid < 64) {
        const float inv_cnt = 1.0f / 131072.0f;
        float mu = g_stats[statOff + tid] * inv_cnt;
        float var = g_stats[statOff + 64 + tid] * inv_cnt - mu * mu;
        float scv = gam[tid] * rsqrtf(var + 1e-5f);
        sc[tid] = scv;
        sh[tid] = beta[tid] - mu * scv;
        obs[tid] = ob[tid];
    }
    for (int i = tid; i < 4096; i += 256) {
        int c2 = i >> 6, c = i & 63;
        ws[c][c2] = ow[i];
    }
    __syncthreads();
    for (int i = tid; i < 4096; i += 256) {
        int r = i >> 6, c = i & 63;
        float v = tmp[(row0 + r) * 64 + c];
        ys[r][c] = fmaxf(0.f, fmaf(v, sc[c], sh[c]));
    }
    __syncthreads();

    int tr = (tid >> 4) << 2, tc = (tid & 15) << 2;
    float acc[4][4];
    #pragma unroll
    for (int i = 0; i < 4; i++)
        #pragma unroll
        for (int j = 0; j < 4; j++) acc[i][j] = 0.f;

    #pragma unroll 8
    for (int k = 0; k < 64; k++) {
        float a[4], b[4];
        #pragma unroll
        for (int i = 0; i < 4; i++) a[i] = ys[tr + i][k];
        #pragma unroll
        for (int j = 0; j < 4; j++) b[j] = ws[k][tc + j];
        #pragma unroll
        for (int i = 0; i < 4; i++)
            #pragma unroll
            for (int j = 0; j < 4; j++) acc[i][j] = fmaf(a[i], b[j], acc[i][j]);
    }
    #pragma unroll
    for (int i = 0; i < 4; i++) {
        int r = row0 + tr + i;
        int b = r >> 10, t = (r >> 3) & 127, n = r & 7;
        #pragma unroll
        for (int j = 0; j < 4; j++) {
            int c2 = tc + j;
            z[((b * 64 + c2) * 8 + n) * 128 + t] = tanhf(acc[i][j] + obs[c2]);
        }
    }
}

// ---------------- final regression + mean ----------------
__global__ void final_kernel(const float* __restrict__ z, float* __restrict__ out) {
    int bn = blockIdx.x;            // 1024
    int b = bn >> 3, n = bn & 7;
    int t = threadIdx.x;            // 128
    __shared__ float wb[64];
    if (t < 64) wb[t] = g_wbar[t];
    __syncthreads();

    const float4* row = (const float4*)(z + ((b * 128 + t) * 8 + n) * 64);
    const float4* w4 = (const float4*)wb;
    float s = 0.f;
    #pragma unroll
    for (int i = 0; i < 16; i++) {
        float4 v = row[i], w = w4[i];
        s += v.x * w.x + v.y * w.y + v.z * w.z + v.w * w.w;
    }
    #pragma unroll
    for (int o = 16; o > 0; o >>= 1) s += __shfl_down_sync(0xffffffffu, s, o);
    __shared__ float part[4];
    if ((t & 31) == 0) part[t >> 5] = s;
    __syncthreads();
    if (t == 0) {
        float tot = part[0] + part[1] + part[2] + part[3];
        out[bn] = tot * (1.0f / 128.0f) + g_wbar[64];
    }
}

// ---------------- host launcher ----------------
extern "C" void kernel_launch(void* const* d_in, const int* in_sizes, int n_in,
                              void* d_out, int out_size) {
    const float* x      = (const float*)d_in[0];
    const int*   ei     = (const int*)d_in[1];
    const float* gcn1_w = (const float*)d_in[2];
    const float* gcn1_b = (const float*)d_in[3];
    const float* t1_w   = (const float*)d_in[4];
    const float* t1_b   = (const float*)d_in[5];
    const float* bn1_g  = (const float*)d_in[6];
    const float* bn1_b  = (const float*)d_in[7];
    const float* o1_w   = (const float*)d_in[8];
    const float* o1_b   = (const float*)d_in[9];
    const float* gcn2_w = (const float*)d_in[10];
    const float* gcn2_b = (const float*)d_in[11];
    const float* t2_w   = (const float*)d_in[12];
    const float* t2_b   = (const float*)d_in[13];
    const float* bn2_g  = (const float*)d_in[14];
    const float* bn2_b  = (const float*)d_in[15];
    const float* o2_w   = (const float*)d_in[16];
    const float* o2_b   = (const float*)d_in[17];
    const float* reg_w  = (const float*)d_in[18];
    const float* reg_b  = (const float*)d_in[19];
    float* out = (float*)d_out;

    const int* src = ei;
    const int* dst = ei + EDGES;

    cudaFuncSetAttribute(tconv_kernel, cudaFuncAttributeMaxDynamicSharedMemorySize, TCONV_SMEM);

    float* bufA; cudaGetSymbolAddress((void**)&bufA, g_bufA);
    float* bufB; cudaGetSymbolAddress((void**)&bufB, g_bufB);
    float* bufC; cudaGetSymbolAddress((void**)&bufC, g_bufC);
    float* tw1;  cudaGetSymbolAddress((void**)&tw1, g_tw1);
    float* tw2;  cudaGetSymbolAddress((void**)&tw2, g_tw2);

    prologue_kernel<<<512, 256>>>(reg_w, reg_b, t1_w, t2_w);
    deg_count_kernel<<<EDGES / 256, 256>>>(dst);
    dinv_kernel<<<NROWS / 256, 256>>>();

    // -------- layer 1 --------
    gemm_gcn_kernel<32><<<NROWS / 64, 256>>>(x, gcn1_w, gcn1_b, bufA, bufB);
    edge_agg_kernel<<<EDGES * 8 / 256, 256>>>(bufA, src, dst, bufB);
    tconv_kernel<<<512, 512, TCONV_SMEM>>>(bufB, tw1, t1_b, bufC, 0);
    fused_out_kernel<<<NROWS / 64, 256>>>(bufC, o1_w, o1_b, bn1_g, bn1_b, bufA, 0);

    // -------- layer 2 --------
    gemm_gcn_kernel<64><<<NROWS / 64, 256>>>(bufA, gcn2_w, gcn2_b, bufB, bufC);
    edge_agg_kernel<<<EDGES * 8 / 256, 256>>>(bufB, src, dst, bufC);
    tconv_kernel<<<512, 512, TCONV_SMEM>>>(bufC, tw2, t2_b, bufB, 128);
    fused_out_kernel<<<NROWS / 64, 256>>>(bufB, o2_w, o2_b, bn2_g, bn2_b, bufC, 128);

    // -------- regression + mean --------
    final_kernel<<<BB * NNODE, 128>>>(bufC, out);
}

// round 4
// speedup vs baseline: 1.1456x; 1.1347x over previous
#include <cuda_runtime.h>
#include <cuda_bf16.h>
#include <math.h>

#define NROWS 131072
#define EDGES 1048576
#define BB 128

// ---------------- scratch (device globals) ----------------
__device__ float g_bufA[NROWS * 64];
__device__ float g_bufB[NROWS * 64];
__device__ float g_bufC[NROWS * 64];
__device__ float g_deg[NROWS];
__device__ float g_stats[256];      // layer1: [0:64) sum [64:128) sq ; layer2: [128..256)
__device__ float g_wbar[65];
__device__ float g_tw1[12288];      // [(c*3+k)*64 + c2]
__device__ float g_tw2[12288];

// ---------------- f32x2 helpers ----------------
typedef unsigned long long ull;
__device__ __forceinline__ ull pk2(float x) {
    ull u; asm("mov.b64 %0,{%1,%2};" : "=l"(u) : "f"(x), "f"(x)); return u;
}
__device__ __forceinline__ float2 upk(ull u) {
    float2 r; asm("mov.b64 {%0,%1},%2;" : "=f"(r.x), "=f"(r.y) : "l"(u)); return r;
}
__device__ __forceinline__ ull fma2_(ull a, ull b, ull c) {
    ull d; asm("fma.rn.f32x2 %0,%1,%2,%3;" : "=l"(d) : "l"(a), "l"(b), "l"(c)); return d;
}
__device__ __forceinline__ float tanh_ap(float x) {
    float y; asm("tanh.approx.f32 %0,%1;" : "=f"(y) : "f"(x)); return y;
}

// ---------------- prologue ----------------
__global__ void prologue_kernel(const float* __restrict__ rw, const float* __restrict__ rb,
                                const float* __restrict__ t1w, const float* __restrict__ t2w) {
    int i = blockIdx.x * blockDim.x + threadIdx.x;
    if (i < NROWS) g_deg[i] = 0.0f;
    if (i < 256) g_stats[i] = 0.0f;
    if (i < 12288) {
        int c2 = i & 63, rest = i >> 6;
        int c = rest / 3, k = rest - 3 * c;
        int s = (c2 * 64 + c) * 3 + k;
        g_tw1[i] = t1w[s];
        g_tw2[i] = t2w[s];
    }
    if (i < 64) {
        float s = 0.f;
        #pragma unroll
        for (int j = 0; j < 8; j++) s += rw[i * 8 + j];
        g_wbar[i] = s * 0.125f;
    }
    if (i == 64) {
        float s = 0.f;
        #pragma unroll
        for (int j = 0; j < 8; j++) s += rb[j];
        g_wbar[64] = s * 0.125f;
    }
}

__global__ void deg_count_kernel(const int* __restrict__ dst) {
    int e = blockIdx.x * blockDim.x + threadIdx.x;
    if (e < EDGES) atomicAdd(&g_deg[dst[e]], 1.0f);
}

__global__ void dinv_kernel() {
    int i = blockIdx.x * blockDim.x + threadIdx.x;
    if (i < NROWS) g_deg[i] = rsqrtf(g_deg[i] + 1.0f);
}

// ---------------- dense GEMM fused with GCN init (f32x2 micro-kernel) ----------------
template <int K>
__global__ void gemm_gcn_kernel(const float* __restrict__ A, const float* __restrict__ W,
                                const float* __restrict__ bias,
                                float* __restrict__ hs, float* __restrict__ agg) {
    __shared__ float As[64][K + 1];
    __shared__ float Ws[K][68];
    __shared__ float bs[64];
    int tid = threadIdx.x;           // 256
    int row0 = blockIdx.x * 64;

    if (tid < 64) bs[tid] = bias[tid];
    for (int i = tid; i < K * 64; i += 256) Ws[i >> 6][i & 63] = W[i];
    for (int i = tid; i < 64 * K; i += 256) {
        int r = i / K, c = i - r * K;
        As[r][c] = A[(row0 + r) * K + c];
    }
    __syncthreads();

    int tr = (tid >> 4) << 2;
    int tc = (tid & 15) << 2;
    ull acc[4][2];
    #pragma unroll
    for (int i = 0; i < 4; i++) { acc[i][0] = 0ULL; acc[i][1] = 0ULL; }

    #pragma unroll 4
    for (int k = 0; k < K; k++) {
        ulonglong2 bv = *(const ulonglong2*)&Ws[k][tc];   // LDS.128: (b0,b1),(b2,b3)
        ull a0 = pk2(As[tr + 0][k]);
        ull a1 = pk2(As[tr + 1][k]);
        ull a2 = pk2(As[tr + 2][k]);
        ull a3 = pk2(As[tr + 3][k]);
        acc[0][0] = fma2_(a0, bv.x, acc[0][0]); acc[0][1] = fma2_(a0, bv.y, acc[0][1]);
        acc[1][0] = fma2_(a1, bv.x, acc[1][0]); acc[1][1] = fma2_(a1, bv.y, acc[1][1]);
        acc[2][0] = fma2_(a2, bv.x, acc[2][0]); acc[2][1] = fma2_(a2, bv.y, acc[2][1]);
        acc[3][0] = fma2_(a3, bv.x, acc[3][0]); acc[3][1] = fma2_(a3, bv.y, acc[3][1]);
    }

    float4 bq = *(const float4*)&bs[tc];
    #pragma unroll
    for (int i = 0; i < 4; i++) {
        int r = row0 + tr + i;
        float dv = g_deg[r];
        float dv2 = dv * dv;
        float2 p0 = upk(acc[i][0]), p1 = upk(acc[i][1]);
        float4 h4 = make_float4(p0.x * dv, p0.y * dv, p1.x * dv, p1.y * dv);
        float4 g4 = make_float4(fmaf(p0.x, dv2, bq.x), fmaf(p0.y, dv2, bq.y),
                                fmaf(p1.x, dv2, bq.z), fmaf(p1.y, dv2, bq.w));
        *(float4*)(hs + r * 64 + tc) = h4;
        *(float4*)(agg + r * 64 + tc) = g4;
    }
}

// ---------------- edge aggregation: agg[d,:] += hs[s,:] * dinv[d] ----------------
__global__ void edge_agg_kernel(const float* __restrict__ hs, const int* __restrict__ src,
                                const int* __restrict__ dst, float* __restrict__ agg) {
    int idx = blockIdx.x * blockDim.x + threadIdx.x;   // EDGES*8
    int e = idx >> 3, q = idx & 7;
    int s = __ldg(&src[e]);
    int d = __ldg(&dst[e]);
    float w = g_deg[d];
    const float4* hv = ((const float4*)hs) + s * 16 + q * 2;
    float4 a = hv[0], b = hv[1];
    float4 ma = make_float4(a.x * w, a.y * w, a.z * w, a.w * w);
    float4 mb = make_float4(b.x * w, b.y * w, b.z * w, b.w * w);
    float4* dp = (float4*)(agg + d * 64 + q * 8);
    atomicAdd(dp, ma);
    atomicAdd(dp + 1, mb);
}

// ---------------- temporal (1,3) conv: 4x4 register tile + f32x2 + fused BN stats ----
#define XSTR 134
#define CPSZ (64 * XSTR)
#define HALFSZ (2 * CPSZ)
#define WS_OFF (2 * HALFSZ)               // 34304
#define ST_OFF (WS_OFF + 12288)           // 46592
#define TCONV_SMEM ((ST_OFF + 4096) * 4)  // 202752 bytes

__global__ void __launch_bounds__(512, 1)
tconv_kernel(const float* __restrict__ in, const float* __restrict__ wsg,
             const float* __restrict__ tb, float* __restrict__ out, int statOff) {
    extern __shared__ float sm[];
    float* ws = sm + WS_OFF;
    int tid = threadIdx.x;           // 512
    int half = tid >> 8;
    int lt = tid & 255;
    int p = blockIdx.x;              // 512 blocks
    int b = p >> 2;
    int n = ((p & 3) << 1) | half;
    float* xs1 = sm + half * HALFSZ;
    float* xs2 = xs1 + CPSZ;

    for (int i = tid; i < 3072; i += 512)
        ((float4*)ws)[i] = ((const float4*)wsg)[i];

    if (lt < 128) {
        int c = lt >> 1, s = (lt & 1) ? 129 : 0;
        xs1[c * XSTR + s] = 0.f;
    }
    const float4* in4 = (const float4*)in;
    for (int i = lt; i < 2048; i += 256) {
        int t = i >> 4, q = i & 15;
        float4 v = in4[((b * 128 + t) * 8 + n) * 16 + q];
        float* r1 = xs1 + (q * 4) * XSTR + (t + 1);
        float* r2 = xs2 + (q * 4) * XSTR + (t + 2);
        r1[0] = v.x; r1[XSTR] = v.y; r1[2 * XSTR] = v.z; r1[3 * XSTR] = v.w;
        r2[0] = v.x; r2[XSTR] = v.y; r2[2 * XSTR] = v.z; r2[3 * XSTR] = v.w;
    }
    __syncthreads();

    int tc = lt & 15;                // c2 group (4 cols)
    int tp = lt >> 4;                // t-pair group (4 pairs = 8 t)
    int t0 = tp * 8;
    int c2b = tc * 4;

    float4 tb4 = *(const float4*)(tb + c2b);
    ull acc[4][4];
    #pragma unroll
    for (int j = 0; j < 4; j++) {
        acc[j][0] = pk2(tb4.x); acc[j][1] = pk2(tb4.y);
        acc[j][2] = pk2(tb4.z); acc[j][3] = pk2(tb4.w);
    }

    const float4* ws4 = (const float4*)ws;
    #pragma unroll 1
    for (int c = 0; c < 64; c++) {
        const ull* p1 = (const ull*)(xs1 + c * XSTR + t0);
        const ull* p2 = (const ull*)(xs2 + c * XSTR + t0);
        ull A0 = p1[0], A1 = p1[1], A2 = p1[2], A3 = p1[3], A4 = p1[4];
        ull O0 = p2[1], O1 = p2[2], O2 = p2[3], O3 = p2[4];
        float4 w0 = ws4[(c * 3 + 0) * 16 + tc];
        float4 w1 = ws4[(c * 3 + 1) * 16 + tc];
        float4 w2 = ws4[(c * 3 + 2) * 16 + tc];

        ull W00 = pk2(w0.x), W01 = pk2(w0.y), W02 = pk2(w0.z), W03 = pk2(w0.w);
        ull W10 = pk2(w1.x), W11 = pk2(w1.y), W12 = pk2(w1.z), W13 = pk2(w1.w);
        ull W20 = pk2(w2.x), W21 = pk2(w2.y), W22 = pk2(w2.z), W23 = pk2(w2.w);

        acc[0][0] = fma2_(W00, A0, fma2_(W10, O0, fma2_(W20, A1, acc[0][0])));
        acc[0][1] = fma2_(W01, A0, fma2_(W11, O0, fma2_(W21, A1, acc[0][1])));
        acc[0][2] = fma2_(W02, A0, fma2_(W12, O0, fma2_(W22, A1, acc[0][2])));
        acc[0][3] = fma2_(W03, A0, fma2_(W13, O0, fma2_(W23, A1, acc[0][3])));

        acc[1][0] = fma2_(W00, A1, fma2_(W10, O1, fma2_(W20, A2, acc[1][0])));
        acc[1][1] = fma2_(W01, A1, fma2_(W11, O1, fma2_(W21, A2, acc[1][1])));
        acc[1][2] = fma2_(W02, A1, fma2_(W12, O1, fma2_(W22, A2, acc[1][2])));
        acc[1][3] = fma2_(W03, A1, fma2_(W13, O1, fma2_(W23, A2, acc[1][3])));

        acc[2][0] = fma2_(W00, A2, fma2_(W10, O2, fma2_(W20, A3, acc[2][0])));
        acc[2][1] = fma2_(W01, A2, fma2_(W11, O2, fma2_(W21, A3, acc[2][1])));
        acc[2][2] = fma2_(W02, A2, fma2_(W12, O2, fma2_(W22, A3, acc[2][2])));
        acc[2][3] = fma2_(W03, A2, fma2_(W13, O2, fma2_(W23, A3, acc[2][3])));

        acc[3][0] = fma2_(W00, A3, fma2_(W10, O3, fma2_(W20, A4, acc[3][0])));
        acc[3][1] = fma2_(W01, A3, fma2_(W11, O3, fma2_(W21, A4, acc[3][1])));
        acc[3][2] = fma2_(W02, A3, fma2_(W12, O3, fma2_(W22, A4, acc[3][2])));
        acc[3][3] = fma2_(W03, A3, fma2_(W13, O3, fma2_(W23, A4, acc[3][3])));
    }

    // epilogue: store + per-thread BN partial sums (4 c2 columns)
    float s_sum[4] = {0.f, 0.f, 0.f, 0.f};
    float s_sq[4] = {0.f, 0.f, 0.f, 0.f};
    #pragma unroll
    for (int j = 0; j < 4; j++) {
        float2 q0 = upk(acc[j][0]), q1 = upk(acc[j][1]);
        float2 q2 = upk(acc[j][2]), q3 = upk(acc[j][3]);
        float4 ya = make_float4(q0.x, q1.x, q2.x, q3.x);   // t = t0+2j
        float4 yb = make_float4(q0.y, q1.y, q2.y, q3.y);   // t = t0+2j+1
        int ra = ((b * 128 + t0 + 2 * j) * 8 + n) * 64 + c2b;
        *(float4*)(out + ra) = ya;
        *(float4*)(out + ra + 512) = yb;
        s_sum[0] += ya.x + yb.x; s_sq[0] += ya.x * ya.x + yb.x * yb.x;
        s_sum[1] += ya.y + yb.y; s_sq[1] += ya.y * ya.y + yb.y * yb.y;
        s_sum[2] += ya.z + yb.z; s_sq[2] += ya.z * ya.z + yb.z * yb.z;
        s_sum[3] += ya.w + yb.w; s_sq[3] += ya.w * ya.w + yb.w * yb.w;
    }

    float* st = sm + ST_OFF;        // [32 slots][64 c2] sum, then sq
    int slot = half * 16 + tp;
    __syncthreads();
    #pragma unroll
    for (int l = 0; l < 4; l++) {
        st[slot * 64 + c2b + l] = s_sum[l];
        st[2048 + slot * 64 + c2b + l] = s_sq[l];
    }
    __syncthreads();
    if (tid < 64) {
        float s = 0.f;
        #pragma unroll
        for (int k = 0; k < 32; k++) s += st[k * 64 + tid];
        atomicAdd(&g_stats[statOff + tid], s);
    } else if (tid < 128) {
        int c = tid - 64;
        float s = 0.f;
        #pragma unroll
        for (int k = 0; k < 32; k++) s += st[2048 + k * 64 + c];
        atomicAdd(&g_stats[statOff + 64 + c], s);
    }
}

// ---------------- fused bn->relu->1x1->tanh, scrambled store ----------------
__global__ void fused_out_kernel(const float* __restrict__ tmp, const float* __restrict__ ow,
                                 const float* __restrict__ ob, const float* __restrict__ gam,
                                 const float* __restrict__ beta, float* __restrict__ z,
                                 int statOff) {
    __shared__ float ys[64][65];
    __shared__ float ws[64][68];
    __shared__ float sc[64], sh[64], obs[64];
    int tid = threadIdx.x;         // 256
    int row0 = blockIdx.x * 64;

    if (tid < 64) {
        const float inv_cnt = 1.0f / 131072.0f;
        float mu = g_stats[statOff + tid] * inv_cnt;
        float var = g_stats[statOff + 64 + tid] * inv_cnt - mu * mu;
        float scv = gam[tid] * rsqrtf(var + 1e-5f);
        sc[tid] = scv;
        sh[tid] = beta[tid] - mu * scv;
        obs[tid] = ob[tid];
    }
    for (int i = tid; i < 4096; i += 256) {
        int c2 = i >> 6, c = i & 63;
        ws[c][c2] = ow[i];
    }
    __syncthreads();
    for (int i = tid; i < 4096; i += 256) {
        int r = i >> 6, c = i & 63;
        float v = tmp[(row0 + r) * 64 + c];
        ys[r][c] = fmaxf(0.f, fmaf(v, sc[c], sh[c]));
    }
    __syncthreads();

    int tr = (tid >> 4) << 2, tc = (tid & 15) << 2;
    ull acc[4][2];
    #pragma unroll
    for (int i = 0; i < 4; i++) { acc[i][0] = 0ULL; acc[i][1] = 0ULL; }

    #pragma unroll 4
    for (int k = 0; k < 64; k++) {
        ulonglong2 bv = *(const ulonglong2*)&ws[k][tc];
        ull a0 = pk2(ys[tr + 0][k]);
        ull a1 = pk2(ys[tr + 1][k]);
        ull a2 = pk2(ys[tr + 2][k]);
        ull a3 = pk2(ys[tr + 3][k]);
        acc[0][0] = fma2_(a0, bv.x, acc[0][0]); acc[0][1] = fma2_(a0, bv.y, acc[0][1]);
        acc[1][0] = fma2_(a1, bv.x, acc[1][0]); acc[1][1] = fma2_(a1, bv.y, acc[1][1]);
        acc[2][0] = fma2_(a2, bv.x, acc[2][0]); acc[2][1] = fma2_(a2, bv.y, acc[2][1]);
        acc[3][0] = fma2_(a3, bv.x, acc[3][0]); acc[3][1] = fma2_(a3, bv.y, acc[3][1]);
    }

    float4 oq = *(const float4*)&obs[tc];
    #pragma unroll
    for (int i = 0; i < 4; i++) {
        int r = row0 + tr + i;
        int b = r >> 10, t = (r >> 3) & 127, n = r & 7;
        float2 p0 = upk(acc[i][0]), p1 = upk(acc[i][1]);
        int base = ((b * 64 + tc) * 8 + n) * 128 + t;
        z[base]          = tanh_ap(p0.x + oq.x);
        z[base + 1024]   = tanh_ap(p0.y + oq.y);
        z[base + 2048]   = tanh_ap(p1.x + oq.z);
        z[base + 3072]   = tanh_ap(p1.y + oq.w);
    }
}

// ---------------- final regression + mean ----------------
__global__ void final_kernel(const float* __restrict__ z, float* __restrict__ out) {
    int bn = blockIdx.x;            // 1024
    int b = bn >> 3, n = bn & 7;
    int t = threadIdx.x;            // 128
    __shared__ float wb[64];
    if (t < 64) wb[t] = g_wbar[t];
    __syncthreads();

    const float4* row = (const float4*)(z + ((b * 128 + t) * 8 + n) * 64);
    const float4* w4 = (const float4*)wb;
    float s = 0.f;
    #pragma unroll
    for (int i = 0; i < 16; i++) {
        float4 v = row[i], w = w4[i];
        s += v.x * w.x + v.y * w.y + v.z * w.z + v.w * w.w;
    }
    #pragma unroll
    for (int o = 16; o > 0; o >>= 1) s += __shfl_down_sync(0xffffffffu, s, o);
    __shared__ float part[4];
    if ((t & 31) == 0) part[t >> 5] = s;
    __syncthreads();
    if (t == 0) {
        float tot = part[0] + part[1] + part[2] + part[3];
        out[bn] = tot * (1.0f / 128.0f) + g_wbar[64];
    }
}

// ---------------- host launcher ----------------
extern "C" void kernel_launch(void* const* d_in, const int* in_sizes, int n_in,
                              void* d_out, int out_size) {
    const float* x      = (const float*)d_in[0];
    const int*   ei     = (const int*)d_in[1];
    const float* gcn1_w = (const float*)d_in[2];
    const float* gcn1_b = (const float*)d_in[3];
    const float* t1_w   = (const float*)d_in[4];
    const float* t1_b   = (const float*)d_in[5];
    const float* bn1_g  = (const float*)d_in[6];
    const float* bn1_b  = (const float*)d_in[7];
    const float* o1_w   = (const float*)d_in[8];
    const float* o1_b   = (const float*)d_in[9];
    const float* gcn2_w = (const float*)d_in[10];
    const float* gcn2_b = (const float*)d_in[11];
    const float* t2_w   = (const float*)d_in[12];
    const float* t2_b   = (const float*)d_in[13];
    const float* bn2_g  = (const float*)d_in[14];
    const float* bn2_b  = (const float*)d_in[15];
    const float* o2_w   = (const float*)d_in[16];
    const float* o2_b   = (const float*)d_in[17];
    const float* reg_w  = (const float*)d_in[18];
    const float* reg_b  = (const float*)d_in[19];
    float* out = (float*)d_out;

    const int* src = ei;
    const int* dst = ei + EDGES;

    cudaFuncSetAttribute(tconv_kernel, cudaFuncAttributeMaxDynamicSharedMemorySize, TCONV_SMEM);

    float* bufA; cudaGetSymbolAddress((void**)&bufA, g_bufA);
    float* bufB; cudaGetSymbolAddress((void**)&bufB, g_bufB);
    float* bufC; cudaGetSymbolAddress((void**)&bufC, g_bufC);
    float* tw1;  cudaGetSymbolAddress((void**)&tw1, g_tw1);
    float* tw2;  cudaGetSymbolAddress((void**)&tw2, g_tw2);

    prologue_kernel<<<512, 256>>>(reg_w, reg_b, t1_w, t2_w);
    deg_count_kernel<<<EDGES / 256, 256>>>(dst);
    dinv_kernel<<<NROWS / 256, 256>>>();

    // -------- layer 1 --------
    gemm_gcn_kernel<32><<<NROWS / 64, 256>>>(x, gcn1_w, gcn1_b, bufA, bufB);
    edge_agg_kernel<<<EDGES * 8 / 256, 256>>>(bufA, src, dst, bufB);
    tconv_kernel<<<512, 512, TCONV_SMEM>>>(bufB, tw1, t1_b, bufC, 0);
    fused_out_kernel<<<NROWS / 64, 256>>>(bufC, o1_w, o1_b, bn1_g, bn1_b, bufA, 0);

    // -------- layer 2 --------
    gemm_gcn_kernel<64><<<NROWS / 64, 256>>>(bufA, gcn2_w, gcn2_b, bufB, bufC);
    edge_agg_kernel<<<EDGES * 8 / 256, 256>>>(bufB, src, dst, bufC);
    tconv_kernel<<<512, 512, TCONV_SMEM>>>(bufC, tw2, t2_b, bufB, 128);
    fused_out_kernel<<<NROWS / 64, 256>>>(bufB, o2_w, o2_b, bn2_g, bn2_b, bufC, 128);

    // -------- regression + mean --------
    final_kernel<<<1024, 128>>>(bufC, out);
}

// round 5
// speedup vs baseline: 1.3642x; 1.1909x over previous
#include <cuda_runtime.h>
#include <cuda_bf16.h>
#include <math.h>

#define NROWS 131072
#define EDGES 1048576

// ---------------- scratch (device globals) ----------------
__device__ float g_bufA[NROWS * 64];
__device__ float g_bufB[NROWS * 64];
__device__ float g_bufC[NROWS * 64];
__device__ float g_deg[NROWS];      // dinv
__device__ int   g_hist[NROWS];
__device__ int   g_off[NROWS];
__device__ int   g_cursor[NROWS];
__device__ int   g_bsum[128];
__device__ int   g_srcs[EDGES];
__device__ float g_stats[256];
__device__ float g_wbar[65];
__device__ float g_tw1[12288];      // [(c*3+k)*64 + c2]
__device__ float g_tw2[12288];

// ---------------- f32x2 helpers ----------------
typedef unsigned long long ull;
__device__ __forceinline__ ull pk2(float x) {
    ull u; asm("mov.b64 %0,{%1,%2};" : "=l"(u) : "f"(x), "f"(x)); return u;
}
__device__ __forceinline__ float2 upk(ull u) {
    float2 r; asm("mov.b64 {%0,%1},%2;" : "=f"(r.x), "=f"(r.y) : "l"(u)); return r;
}
__device__ __forceinline__ ull fma2_(ull a, ull b, ull c) {
    ull d; asm("fma.rn.f32x2 %0,%1,%2,%3;" : "=l"(d) : "l"(a), "l"(b), "l"(c)); return d;
}
__device__ __forceinline__ float tanh_ap(float x) {
    float y; asm("tanh.approx.f32 %0,%1;" : "=f"(y) : "f"(x)); return y;
}

// ---------------- prologue: zero + wbar + weight transpose ----------------
__global__ void prologue_kernel(const float* __restrict__ rw, const float* __restrict__ rb,
                                const float* __restrict__ t1w, const float* __restrict__ t2w) {
    int i = blockIdx.x * blockDim.x + threadIdx.x;
    if (i < NROWS) g_hist[i] = 0;
    if (i < 256) g_stats[i] = 0.0f;
    if (i < 12288) {
        int c2 = i & 63, rest = i >> 6;
        int c = rest / 3, k = rest - 3 * c;
        int s = (c2 * 64 + c) * 3 + k;
        g_tw1[i] = t1w[s];
        g_tw2[i] = t2w[s];
    }
    if (i < 64) {
        float s = 0.f;
        #pragma unroll
        for (int j = 0; j < 8; j++) s += rw[i * 8 + j];
        g_wbar[i] = s * 0.125f;
    }
    if (i == 64) {
        float s = 0.f;
        #pragma unroll
        for (int j = 0; j < 8; j++) s += rb[j];
        g_wbar[64] = s * 0.125f;
    }
}

__global__ void hist_kernel(const int* __restrict__ dst) {
    int e = blockIdx.x * blockDim.x + threadIdx.x;
    if (e < EDGES) atomicAdd(&g_hist[dst[e]], 1);
}

// exclusive scan over 131072 ints: 128 segments of 1024
__global__ void scan1_kernel() {
    __shared__ int sh[256];
    int tid = threadIdx.x;
    int base = blockIdx.x * 1024 + tid * 4;
    int4 v = *(const int4*)&g_hist[base];
    int s0 = v.x, s1 = s0 + v.y, s2 = s1 + v.z, s3 = s2 + v.w;
    sh[tid] = s3;
    __syncthreads();
    #pragma unroll
    for (int o = 1; o < 256; o <<= 1) {
        int t = (tid >= o) ? sh[tid - o] : 0;
        __syncthreads();
        sh[tid] += t;
        __syncthreads();
    }
    int excl = tid ? sh[tid - 1] : 0;
    int4 w = make_int4(excl, excl + s0, excl + s1, excl + s2);
    *(int4*)&g_off[base] = w;
    if (tid == 255) g_bsum[blockIdx.x] = sh[255];
}

__global__ void scan2_kernel() {
    __shared__ int sh[128];
    int tid = threadIdx.x;   // 128
    sh[tid] = g_bsum[tid];
    __syncthreads();
    #pragma unroll
    for (int o = 1; o < 128; o <<= 1) {
        int t = (tid >= o) ? sh[tid - o] : 0;
        __syncthreads();
        sh[tid] += t;
        __syncthreads();
    }
    g_bsum[tid] = tid ? sh[tid - 1] : 0;
}

__global__ void scan3_kernel() {
    int i = blockIdx.x * blockDim.x + threadIdx.x;
    if (i < NROWS) {
        int o = g_off[i] + g_bsum[i >> 10];
        g_off[i] = o;
        g_cursor[i] = o;
        g_deg[i] = rsqrtf((float)g_hist[i] + 1.0f);
    }
}

__global__ void scatter_kernel(const int* __restrict__ src, const int* __restrict__ dst) {
    int e = blockIdx.x * blockDim.x + threadIdx.x;
    if (e < EDGES) {
        int d = dst[e];
        int pos = atomicAdd(&g_cursor[d], 1);
        g_srcs[pos] = src[e];
    }
}

// ---------------- dense GEMM -> hs = (A@W)*dinv  (8x4 register tile, f32x2) --------
template <int K>
__global__ void gemm_hs_kernel(const float* __restrict__ A, const float* __restrict__ W,
                               float* __restrict__ hs) {
    __shared__ float As[128][K + 4];
    __shared__ float Ws[K][68];
    int tid = threadIdx.x;           // 256
    int row0 = blockIdx.x * 128;

    // weights
    for (int i = tid; i < K * 16; i += 256) {
        int r = i / 16, cq = i & 15;
        *(float4*)&Ws[r][cq * 4] = ((const float4*)W)[i];
    }
    // A rows (float4 coalesced)
    constexpr int KQ = K / 4;
    for (int i = tid; i < 128 * KQ; i += 256) {
        int r = i / KQ, cq = i - r * KQ;
        *(float4*)&As[r][cq * 4] = ((const float4*)(A + (long)(row0 + r) * K))[cq];
    }
    __syncthreads();

    int tr = (tid >> 4) << 3;        // 0..120
    int tc = (tid & 15) << 2;        // 0..60
    ull acc[8][2];
    #pragma unroll
    for (int i = 0; i < 8; i++) { acc[i][0] = 0ULL; acc[i][1] = 0ULL; }

    #pragma unroll 4
    for (int k = 0; k < K; k++) {
        ulonglong2 bv = *(const ulonglong2*)&Ws[k][tc];
        #pragma unroll
        for (int i = 0; i < 8; i++) {
            ull a = pk2(As[tr + i][k]);
            acc[i][0] = fma2_(a, bv.x, acc[i][0]);
            acc[i][1] = fma2_(a, bv.y, acc[i][1]);
        }
    }

    #pragma unroll
    for (int i = 0; i < 8; i++) {
        int r = row0 + tr + i;
        float dv = g_deg[r];
        float2 p0 = upk(acc[i][0]), p1 = upk(acc[i][1]);
        float4 h4 = make_float4(p0.x * dv, p0.y * dv, p1.x * dv, p1.y * dv);
        *(float4*)(hs + (long)r * 64 + tc) = h4;
    }
}

// ---------------- sorted gather aggregation (atomic-free) ----------------
// agg[d,:] = dinv[d] * ( sum_{s in srcs[d]} hs[s,:] + hs[d,:] ) + bias
__global__ void gather_agg_kernel(const float* __restrict__ hs, const float* __restrict__ bias,
                                  float* __restrict__ agg) {
    int tid = threadIdx.x;              // 256
    int r = blockIdx.x * 16 + (tid >> 4);
    int q = tid & 15;
    int off = __ldg(&g_off[r]);
    int cnt = __ldg(&g_hist[r]);
    float dv = g_deg[r];
    const float4* h4 = (const float4*)hs;

    float4 acc = __ldg(&h4[(long)r * 16 + q]);   // self loop
    int i = 0;
    for (; i + 2 <= cnt; i += 2) {
        int s0 = __ldg(&g_srcs[off + i]);
        int s1 = __ldg(&g_srcs[off + i + 1]);
        float4 v0 = __ldg(&h4[(long)s0 * 16 + q]);
        float4 v1 = __ldg(&h4[(long)s1 * 16 + q]);
        acc.x += v0.x + v1.x; acc.y += v0.y + v1.y;
        acc.z += v0.z + v1.z; acc.w += v0.w + v1.w;
    }
    if (i < cnt) {
        int s0 = __ldg(&g_srcs[off + i]);
        float4 v0 = __ldg(&h4[(long)s0 * 16 + q]);
        acc.x += v0.x; acc.y += v0.y; acc.z += v0.z; acc.w += v0.w;
    }
    float4 b = __ldg(&((const float4*)bias)[q]);
    float4 o = make_float4(fmaf(acc.x, dv, b.x), fmaf(acc.y, dv, b.y),
                           fmaf(acc.z, dv, b.z), fmaf(acc.w, dv, b.w));
    ((float4*)agg)[(long)r * 16 + q] = o;
}

// ---------------- temporal (1,3) conv: 4x4 register tile + f32x2 + fused BN stats ----
#define XSTR 134
#define CPSZ (64 * XSTR)
#define HALFSZ (2 * CPSZ)
#define WS_OFF (2 * HALFSZ)               // 34304
#define ST_OFF (WS_OFF + 12288)           // 46592
#define TCONV_SMEM ((ST_OFF + 4096) * 4)  // 202752 bytes

__global__ void __launch_bounds__(512, 1)
tconv_kernel(const float* __restrict__ in, const float* __restrict__ wsg,
             const float* __restrict__ tb, float* __restrict__ out, int statOff) {
    extern __shared__ float sm[];
    float* ws = sm + WS_OFF;
    int tid = threadIdx.x;           // 512
    int half = tid >> 8;
    int lt = tid & 255;
    int p = blockIdx.x;              // 512 blocks
    int b = p >> 2;
    int n = ((p & 3) << 1) | half;
    float* xs1 = sm + half * HALFSZ;
    float* xs2 = xs1 + CPSZ;

    for (int i = tid; i < 3072; i += 512)
        ((float4*)ws)[i] = ((const float4*)wsg)[i];

    if (lt < 128) {
        int c = lt >> 1, s = (lt & 1) ? 129 : 0;
        xs1[c * XSTR + s] = 0.f;
    }
    const float4* in4 = (const float4*)in;
    for (int i = lt; i < 2048; i += 256) {
        int t = i >> 4, q = i & 15;
        float4 v = in4[((b * 128 + t) * 8 + n) * 16 + q];
        float* r1 = xs1 + (q * 4) * XSTR + (t + 1);
        float* r2 = xs2 + (q * 4) * XSTR + (t + 2);
        r1[0] = v.x; r1[XSTR] = v.y; r1[2 * XSTR] = v.z; r1[3 * XSTR] = v.w;
        r2[0] = v.x; r2[XSTR] = v.y; r2[2 * XSTR] = v.z; r2[3 * XSTR] = v.w;
    }
    __syncthreads();

    int tc = lt & 15;                // c2 group (4 cols)
    int tp = lt >> 4;                // t-pair group (4 pairs = 8 t)
    int t0 = tp * 8;
    int c2b = tc * 4;

    float4 tb4 = *(const float4*)(tb + c2b);
    ull acc[4][4];
    #pragma unroll
    for (int j = 0; j < 4; j++) {
        acc[j][0] = pk2(tb4.x); acc[j][1] = pk2(tb4.y);
        acc[j][2] = pk2(tb4.z); acc[j][3] = pk2(tb4.w);
    }

    const float4* ws4 = (const float4*)ws;
    #pragma unroll 1
    for (int c = 0; c < 64; c++) {
        const ull* p1 = (const ull*)(xs1 + c * XSTR + t0);
        const ull* p2 = (const ull*)(xs2 + c * XSTR + t0);
        ull A0 = p1[0], A1 = p1[1], A2 = p1[2], A3 = p1[3], A4 = p1[4];
        ull O0 = p2[1], O1 = p2[2], O2 = p2[3], O3 = p2[4];
        float4 w0 = ws4[(c * 3 + 0) * 16 + tc];
        float4 w1 = ws4[(c * 3 + 1) * 16 + tc];
        float4 w2 = ws4[(c * 3 + 2) * 16 + tc];

        ull W00 = pk2(w0.x), W01 = pk2(w0.y), W02 = pk2(w0.z), W03 = pk2(w0.w);
        ull W10 = pk2(w1.x), W11 = pk2(w1.y), W12 = pk2(w1.z), W13 = pk2(w1.w);
        ull W20 = pk2(w2.x), W21 = pk2(w2.y), W22 = pk2(w2.z), W23 = pk2(w2.w);

        acc[0][0] = fma2_(W00, A0, fma2_(W10, O0, fma2_(W20, A1, acc[0][0])));
        acc[0][1] = fma2_(W01, A0, fma2_(W11, O0, fma2_(W21, A1, acc[0][1])));
        acc[0][2] = fma2_(W02, A0, fma2_(W12, O0, fma2_(W22, A1, acc[0][2])));
        acc[0][3] = fma2_(W03, A0, fma2_(W13, O0, fma2_(W23, A1, acc[0][3])));

        acc[1][0] = fma2_(W00, A1, fma2_(W10, O1, fma2_(W20, A2, acc[1][0])));
        acc[1][1] = fma2_(W01, A1, fma2_(W11, O1, fma2_(W21, A2, acc[1][1])));
        acc[1][2] = fma2_(W02, A1, fma2_(W12, O1, fma2_(W22, A2, acc[1][2])));
        acc[1][3] = fma2_(W03, A1, fma2_(W13, O1, fma2_(W23, A2, acc[1][3])));

        acc[2][0] = fma2_(W00, A2, fma2_(W10, O2, fma2_(W20, A3, acc[2][0])));
        acc[2][1] = fma2_(W01, A2, fma2_(W11, O2, fma2_(W21, A3, acc[2][1])));
        acc[2][2] = fma2_(W02, A2, fma2_(W12, O2, fma2_(W22, A3, acc[2][2])));
        acc[2][3] = fma2_(W03, A2, fma2_(W13, O2, fma2_(W23, A3, acc[2][3])));

        acc[3][0] = fma2_(W00, A3, fma2_(W10, O3, fma2_(W20, A4, acc[3][0])));
        acc[3][1] = fma2_(W01, A3, fma2_(W11, O3, fma2_(W21, A4, acc[3][1])));
        acc[3][2] = fma2_(W02, A3, fma2_(W12, O3, fma2_(W22, A4, acc[3][2])));
        acc[3][3] = fma2_(W03, A3, fma2_(W13, O3, fma2_(W23, A4, acc[3][3])));
    }

    // epilogue: store + per-thread BN partial sums (4 c2 columns)
    float s_sum[4] = {0.f, 0.f, 0.f, 0.f};
    float s_sq[4] = {0.f, 0.f, 0.f, 0.f};
    #pragma unroll
    for (int j = 0; j < 4; j++) {
        float2 q0 = upk(acc[j][0]), q1 = upk(acc[j][1]);
        float2 q2 = upk(acc[j][2]), q3 = upk(acc[j][3]);
        float4 ya = make_float4(q0.x, q1.x, q2.x, q3.x);   // t = t0+2j
        float4 yb = make_float4(q0.y, q1.y, q2.y, q3.y);   // t = t0+2j+1
        int ra = ((b * 128 + t0 + 2 * j) * 8 + n) * 64 + c2b;
        *(float4*)(out + ra) = ya;
        *(float4*)(out + ra + 512) = yb;
        s_sum[0] += ya.x + yb.x; s_sq[0] += ya.x * ya.x + yb.x * yb.x;
        s_sum[1] += ya.y + yb.y; s_sq[1] += ya.y * ya.y + yb.y * yb.y;
        s_sum[2] += ya.z + yb.z; s_sq[2] += ya.z * ya.z + yb.z * yb.z;
        s_sum[3] += ya.w + yb.w; s_sq[3] += ya.w * ya.w + yb.w * yb.w;
    }

    float* st = sm + ST_OFF;        // [32 slots][64 c2] sum, then sq
    int slot = half * 16 + tp;
    __syncthreads();
    #pragma unroll
    for (int l = 0; l < 4; l++) {
        st[slot * 64 + c2b + l] = s_sum[l];
        st[2048 + slot * 64 + c2b + l] = s_sq[l];
    }
    __syncthreads();
    if (tid < 64) {
        float s = 0.f;
        #pragma unroll
        for (int k = 0; k < 32; k++) s += st[k * 64 + tid];
        atomicAdd(&g_stats[statOff + tid], s);
    } else if (tid < 128) {
        int c = tid - 64;
        float s = 0.f;
        #pragma unroll
        for (int k = 0; k < 32; k++) s += st[2048 + k * 64 + c];
        atomicAdd(&g_stats[statOff + 64 + c], s);
    }
}

// ---------------- fused bn->relu->1x1->tanh, scrambled store ----------------
__global__ void fused_out_kernel(const float* __restrict__ tmp, const float* __restrict__ ow,
                                 const float* __restrict__ ob, const float* __restrict__ gam,
                                 const float* __restrict__ beta, float* __restrict__ z,
                                 int statOff) {
    __shared__ float ys[64][65];
    __shared__ float ws[64][68];
    __shared__ float sc[64], sh[64], obs[64];
    int tid = threadIdx.x;         // 256
    int row0 = blockIdx.x * 64;

    if (tid < 64) {
        const float inv_cnt = 1.0f / 131072.0f;
        float mu = g_stats[statOff + tid] * inv_cnt;
        float var = g_stats[statOff + 64 + tid] * inv_cnt - mu * mu;
        float scv = gam[tid] * rsqrtf(var + 1e-5f);
        sc[tid] = scv;
        sh[tid] = beta[tid] - mu * scv;
        obs[tid] = ob[tid];
    }
    for (int i = tid; i < 4096; i += 256) {
        int c2 = i >> 6, c = i & 63;
        ws[c][c2] = ow[i];
    }
    __syncthreads();
    for (int i = tid; i < 4096; i += 256) {
        int r = i >> 6, c = i & 63;
        float v = tmp[(row0 + r) * 64 + c];
        ys[r][c] = fmaxf(0.f, fmaf(v, sc[c], sh[c]));
    }
    __syncthreads();

    int tr = (tid >> 4) << 2, tc = (tid & 15) << 2;
    ull acc[4][2];
    #pragma unroll
    for (int i = 0; i < 4; i++) { acc[i][0] = 0ULL; acc[i][1] = 0ULL; }

    #pragma unroll 4
    for (int k = 0; k < 64; k++) {
        ulonglong2 bv = *(const ulonglong2*)&ws[k][tc];
        ull a0 = pk2(ys[tr + 0][k]);
        ull a1 = pk2(ys[tr + 1][k]);
        ull a2 = pk2(ys[tr + 2][k]);
        ull a3 = pk2(ys[tr + 3][k]);
        acc[0][0] = fma2_(a0, bv.x, acc[0][0]); acc[0][1] = fma2_(a0, bv.y, acc[0][1]);
        acc[1][0] = fma2_(a1, bv.x, acc[1][0]); acc[1][1] = fma2_(a1, bv.y, acc[1][1]);
        acc[2][0] = fma2_(a2, bv.x, acc[2][0]); acc[2][1] = fma2_(a2, bv.y, acc[2][1]);
        acc[3][0] = fma2_(a3, bv.x, acc[3][0]); acc[3][1] = fma2_(a3, bv.y, acc[3][1]);
    }

    float4 oq = *(const float4*)&obs[tc];
    #pragma unroll
    for (int i = 0; i < 4; i++) {
        int r = row0 + tr + i;
        int b = r >> 10, t = (r >> 3) & 127, n = r & 7;
        float2 p0 = upk(acc[i][0]), p1 = upk(acc[i][1]);
        int base = ((b * 64 + tc) * 8 + n) * 128 + t;
        z[base]          = tanh_ap(p0.x + oq.x);
        z[base + 1024]   = tanh_ap(p0.y + oq.y);
        z[base + 2048]   = tanh_ap(p1.x + oq.z);
        z[base + 3072]   = tanh_ap(p1.y + oq.w);
    }
}

// ---------------- final regression + mean ----------------
__global__ void final_kernel(const float* __restrict__ z, float* __restrict__ out) {
    int bn = blockIdx.x;            // 1024
    int b = bn >> 3, n = bn & 7;
    int t = threadIdx.x;            // 128
    __shared__ float wb[64];
    if (t < 64) wb[t] = g_wbar[t];
    __syncthreads();

    const float4* row = (const float4*)(z + ((b * 128 + t) * 8 + n) * 64);
    const float4* w4 = (const float4*)wb;
    float s = 0.f;
    #pragma unroll
    for (int i = 0; i < 16; i++) {
        float4 v = row[i], w = w4[i];
        s += v.x * w.x + v.y * w.y + v.z * w.z + v.w * w.w;
    }
    #pragma unroll
    for (int o = 16; o > 0; o >>= 1) s += __shfl_down_sync(0xffffffffu, s, o);
    __shared__ float part[4];
    if ((t & 31) == 0) part[t >> 5] = s;
    __syncthreads();
    if (t == 0) {
        float tot = part[0] + part[1] + part[2] + part[3];
        out[bn] = tot * (1.0f / 128.0f) + g_wbar[64];
    }
}

// ---------------- host launcher ----------------
extern "C" void kernel_launch(void* const* d_in, const int* in_sizes, int n_in,
                              void* d_out, int out_size) {
    const float* x      = (const float*)d_in[0];
    const int*   ei     = (const int*)d_in[1];
    const float* gcn1_w = (const float*)d_in[2];
    const float* gcn1_b = (const float*)d_in[3];
    const float* t1_w   = (const float*)d_in[4];
    const float* t1_b   = (const float*)d_in[5];
    const float* bn1_g  = (const float*)d_in[6];
    const float* bn1_b  = (const float*)d_in[7];
    const float* o1_w   = (const float*)d_in[8];
    const float* o1_b   = (const float*)d_in[9];
    const float* gcn2_w = (const float*)d_in[10];
    const float* gcn2_b = (const float*)d_in[11];
    const float* t2_w   = (const float*)d_in[12];
    const float* t2_b   = (const float*)d_in[13];
    const float* bn2_g  = (const float*)d_in[14];
    const float* bn2_b  = (const float*)d_in[15];
    const float* o2_w   = (const float*)d_in[16];
    const float* o2_b   = (const float*)d_in[17];
    const float* reg_w  = (const float*)d_in[18];
    const float* reg_b  = (const float*)d_in[19];
    float* out = (float*)d_out;

    const int* src = ei;
    const int* dst = ei + EDGES;

    cudaFuncSetAttribute(tconv_kernel, cudaFuncAttributeMaxDynamicSharedMemorySize, TCONV_SMEM);

    float* bufA; cudaGetSymbolAddress((void**)&bufA, g_bufA);
    float* bufB; cudaGetSymbolAddress((void**)&bufB, g_bufB);
    float* bufC; cudaGetSymbolAddress((void**)&bufC, g_bufC);
    float* tw1;  cudaGetSymbolAddress((void**)&tw1, g_tw1);
    float* tw2;  cudaGetSymbolAddress((void**)&tw2, g_tw2);

    // prologue + edge sort (shared by both layers)
    prologue_kernel<<<512, 256>>>(reg_w, reg_b, t1_w, t2_w);
    hist_kernel<<<EDGES / 256, 256>>>(dst);
    scan1_kernel<<<128, 256>>>();
    scan2_kernel<<<1, 128>>>();
    scan3_kernel<<<NROWS / 256, 256>>>();
    scatter_kernel<<<EDGES / 256, 256>>>(src, dst);

    // -------- layer 1 --------
    gemm_hs_kernel<32><<<NROWS / 128, 256>>>(x, gcn1_w, bufA);
    gather_agg_kernel<<<NROWS / 16, 256>>>(bufA, gcn1_b, bufB);
    tconv_kernel<<<512, 512, TCONV_SMEM>>>(bufB, tw1, t1_b, bufC, 0);
    fused_out_kernel<<<NROWS / 64, 256>>>(bufC, o1_w, o1_b, bn1_g, bn1_b, bufA, 0);

    // -------- layer 2 --------
    gemm_hs_kernel<64><<<NROWS / 128, 256>>>(bufA, gcn2_w, bufB);
    gather_agg_kernel<<<NROWS / 16, 256>>>(bufB, gcn2_b, bufC);
    tconv_kernel<<<512, 512, TCONV_SMEM>>>(bufC, tw2, t2_b, bufA, 128);
    fused_out_kernel<<<NROWS / 64, 256>>>(bufA, o2_w, o2_b, bn2_g, bn2_b, bufB, 128);

    // -------- regression + mean --------
    final_kernel<<<1024, 128>>>(bufB, out);
}

// round 6
// speedup vs baseline: 1.5786x; 1.1572x over previous
#include <cuda_runtime.h>
#include <cuda_bf16.h>
#include <math.h>

#define NROWS 131072
#define EDGES 1048576

// ---------------- scratch (device globals) ----------------
__device__ float g_bufA[NROWS * 64];
__device__ float g_bufB[NROWS * 64];
__device__ float g_bufC[NROWS * 64];
__device__ float g_deg[NROWS];      // dinv
__device__ int   g_hist[NROWS];
__device__ int   g_off[NROWS];
__device__ int   g_cursor[NROWS];
__device__ int   g_bsum[128];
__device__ int   g_srcs[EDGES];
__device__ float g_stats[256];
__device__ float g_wbar[65];
__device__ float g_tw1[12288];      // [(c*3+k)*64 + c2]
__device__ float g_tw2[12288];

// ---------------- f32x2 helpers ----------------
typedef unsigned long long ull;
__device__ __forceinline__ ull pk2(float x) {
    ull u; asm("mov.b64 %0,{%1,%2};" : "=l"(u) : "f"(x), "f"(x)); return u;
}
__device__ __forceinline__ float2 upk(ull u) {
    float2 r; asm("mov.b64 {%0,%1},%2;" : "=f"(r.x), "=f"(r.y) : "l"(u)); return r;
}
__device__ __forceinline__ ull fma2_(ull a, ull b, ull c) {
    ull d; asm("fma.rn.f32x2 %0,%1,%2,%3;" : "=l"(d) : "l"(a), "l"(b), "l"(c)); return d;
}
__device__ __forceinline__ float tanh_ap(float x) {
    float y; asm("tanh.approx.f32 %0,%1;" : "=f"(y) : "f"(x)); return y;
}

// ---------------- prologue: zero + wbar + weight transpose ----------------
__global__ void prologue_kernel(const float* __restrict__ rw, const float* __restrict__ rb,
                                const float* __restrict__ t1w, const float* __restrict__ t2w) {
    int i = blockIdx.x * blockDim.x + threadIdx.x;
    if (i < NROWS) g_hist[i] = 0;
    if (i < 256) g_stats[i] = 0.0f;
    if (i < 12288) {
        int c2 = i & 63, rest = i >> 6;
        int c = rest / 3, k = rest - 3 * c;
        int s = (c2 * 64 + c) * 3 + k;
        g_tw1[i] = t1w[s];
        g_tw2[i] = t2w[s];
    }
    if (i < 64) {
        float s = 0.f;
        #pragma unroll
        for (int j = 0; j < 8; j++) s += rw[i * 8 + j];
        g_wbar[i] = s * 0.125f;
    }
    if (i == 64) {
        float s = 0.f;
        #pragma unroll
        for (int j = 0; j < 8; j++) s += rb[j];
        g_wbar[64] = s * 0.125f;
    }
}

__global__ void hist_kernel(const int* __restrict__ dst) {
    int e = blockIdx.x * blockDim.x + threadIdx.x;
    if (e < EDGES) atomicAdd(&g_hist[dst[e]], 1);
}

// exclusive scan over 131072 ints: 128 segments of 1024
__global__ void scan1_kernel() {
    __shared__ int sh[256];
    int tid = threadIdx.x;
    int base = blockIdx.x * 1024 + tid * 4;
    int4 v = *(const int4*)&g_hist[base];
    int s0 = v.x, s1 = s0 + v.y, s2 = s1 + v.z, s3 = s2 + v.w;
    sh[tid] = s3;
    __syncthreads();
    #pragma unroll
    for (int o = 1; o < 256; o <<= 1) {
        int t = (tid >= o) ? sh[tid - o] : 0;
        __syncthreads();
        sh[tid] += t;
        __syncthreads();
    }
    int excl = tid ? sh[tid - 1] : 0;
    int4 w = make_int4(excl, excl + s0, excl + s1, excl + s2);
    *(int4*)&g_off[base] = w;
    if (tid == 255) g_bsum[blockIdx.x] = sh[255];
}

__global__ void scan2_kernel() {
    __shared__ int sh[128];
    int tid = threadIdx.x;   // 128
    sh[tid] = g_bsum[tid];
    __syncthreads();
    #pragma unroll
    for (int o = 1; o < 128; o <<= 1) {
        int t = (tid >= o) ? sh[tid - o] : 0;
        __syncthreads();
        sh[tid] += t;
        __syncthreads();
    }
    g_bsum[tid] = tid ? sh[tid - 1] : 0;
}

__global__ void scan3_kernel(const float* __restrict__ rb, float* __restrict__ out) {
    int i = blockIdx.x * blockDim.x + threadIdx.x;
    if (i < NROWS) {
        int o = g_off[i] + g_bsum[i >> 10];
        g_off[i] = o;
        g_cursor[i] = o;
        g_deg[i] = rsqrtf((float)g_hist[i] + 1.0f);
    }
    if (i < 1024) {
        float s = 0.f;
        #pragma unroll
        for (int j = 0; j < 8; j++) s += rb[j];
        out[i] = s * 0.125f;          // bbar init; fused_out<1> accumulates onto this
    }
}

__global__ void scatter_kernel(const int* __restrict__ src, const int* __restrict__ dst) {
    int e = blockIdx.x * blockDim.x + threadIdx.x;
    if (e < EDGES) {
        int d = dst[e];
        int pos = atomicAdd(&g_cursor[d], 1);
        g_srcs[pos] = src[e];
    }
}

// ---------------- dense GEMM -> hs = (A@W)*dinv  (8x4 tile, k4-vectorized A) --------
template <int K>
__global__ void gemm_hs_kernel(const float* __restrict__ A, const float* __restrict__ W,
                               float* __restrict__ hs) {
    __shared__ float As[128][K + 4];
    __shared__ float Ws[K][68];
    int tid = threadIdx.x;           // 256
    int row0 = blockIdx.x * 128;

    for (int i = tid; i < K * 16; i += 256) {
        int r = i / 16, cq = i & 15;
        *(float4*)&Ws[r][cq * 4] = ((const float4*)W)[i];
    }
    constexpr int KQ = K / 4;
    for (int i = tid; i < 128 * KQ; i += 256) {
        int r = i / KQ, cq = i - r * KQ;
        *(float4*)&As[r][cq * 4] = ((const float4*)(A + (long)(row0 + r) * K))[cq];
    }
    __syncthreads();

    int tr = (tid >> 4) << 3;        // 0..120
    int tc = (tid & 15) << 2;        // 0..60
    ull acc[8][2];
    #pragma unroll
    for (int i = 0; i < 8; i++) { acc[i][0] = 0ULL; acc[i][1] = 0ULL; }

    #pragma unroll 2
    for (int k4 = 0; k4 < K; k4 += 4) {
        float4 a[8];
        #pragma unroll
        for (int i = 0; i < 8; i++) a[i] = *(const float4*)&As[tr + i][k4];
        #pragma unroll
        for (int kk = 0; kk < 4; kk++) {
            ulonglong2 bv = *(const ulonglong2*)&Ws[k4 + kk][tc];
            #pragma unroll
            for (int i = 0; i < 8; i++) {
                float av = (kk == 0) ? a[i].x : (kk == 1) ? a[i].y : (kk == 2) ? a[i].z : a[i].w;
                ull ap = pk2(av);
                acc[i][0] = fma2_(ap, bv.x, acc[i][0]);
                acc[i][1] = fma2_(ap, bv.y, acc[i][1]);
            }
        }
    }

    #pragma unroll
    for (int i = 0; i < 8; i++) {
        int r = row0 + tr + i;
        float dv = g_deg[r];
        float2 p0 = upk(acc[i][0]), p1 = upk(acc[i][1]);
        float4 h4 = make_float4(p0.x * dv, p0.y * dv, p1.x * dv, p1.y * dv);
        *(float4*)(hs + (long)r * 64 + tc) = h4;
    }
}

// ---------------- sorted gather aggregation (atomic-free) ----------------
__global__ void gather_agg_kernel(const float* __restrict__ hs, const float* __restrict__ bias,
                                  float* __restrict__ agg) {
    int tid = threadIdx.x;              // 256
    int r = blockIdx.x * 16 + (tid >> 4);
    int q = tid & 15;
    int off = __ldg(&g_off[r]);
    int cnt = __ldg(&g_hist[r]);
    float dv = g_deg[r];
    const float4* h4 = (const float4*)hs;

    float4 acc = __ldg(&h4[(long)r * 16 + q]);   // self loop
    int i = 0;
    for (; i + 2 <= cnt; i += 2) {
        int s0 = __ldg(&g_srcs[off + i]);
        int s1 = __ldg(&g_srcs[off + i + 1]);
        float4 v0 = __ldg(&h4[(long)s0 * 16 + q]);
        float4 v1 = __ldg(&h4[(long)s1 * 16 + q]);
        acc.x += v0.x + v1.x; acc.y += v0.y + v1.y;
        acc.z += v0.z + v1.z; acc.w += v0.w + v1.w;
    }
    if (i < cnt) {
        int s0 = __ldg(&g_srcs[off + i]);
        float4 v0 = __ldg(&h4[(long)s0 * 16 + q]);
        acc.x += v0.x; acc.y += v0.y; acc.z += v0.z; acc.w += v0.w;
    }
    float4 b = __ldg(&((const float4*)bias)[q]);
    float4 o = make_float4(fmaf(acc.x, dv, b.x), fmaf(acc.y, dv, b.y),
                           fmaf(acc.z, dv, b.z), fmaf(acc.w, dv, b.w));
    ((float4*)agg)[(long)r * 16 + q] = o;
}

// ---------------- temporal (1,3) conv: 4x4 register tile + f32x2 + fused BN stats ----
#define XSTR 134
#define CPSZ (64 * XSTR)
#define HALFSZ (2 * CPSZ)
#define WS_OFF (2 * HALFSZ)               // 34304
#define ST_OFF (WS_OFF + 12288)           // 46592
#define TCONV_SMEM ((ST_OFF + 4096) * 4)  // 202752 bytes

__global__ void __launch_bounds__(512, 1)
tconv_kernel(const float* __restrict__ in, const float* __restrict__ wsg,
             const float* __restrict__ tb, float* __restrict__ out, int statOff) {
    extern __shared__ float sm[];
    float* ws = sm + WS_OFF;
    int tid = threadIdx.x;           // 512
    int half = tid >> 8;
    int lt = tid & 255;
    int p = blockIdx.x;              // 512 blocks
    int b = p >> 2;
    int n = ((p & 3) << 1) | half;
    float* xs1 = sm + half * HALFSZ;
    float* xs2 = xs1 + CPSZ;

    for (int i = tid; i < 3072; i += 512)
        ((float4*)ws)[i] = ((const float4*)wsg)[i];

    if (lt < 128) {
        int c = lt >> 1, s = (lt & 1) ? 129 : 0;
        xs1[c * XSTR + s] = 0.f;
    }
    const float4* in4 = (const float4*)in;
    for (int i = lt; i < 2048; i += 256) {
        int t = i >> 4, q = i & 15;
        float4 v = in4[((b * 128 + t) * 8 + n) * 16 + q];
        float* r1 = xs1 + (q * 4) * XSTR + (t + 1);
        float* r2 = xs2 + (q * 4) * XSTR + (t + 2);
        r1[0] = v.x; r1[XSTR] = v.y; r1[2 * XSTR] = v.z; r1[3 * XSTR] = v.w;
        r2[0] = v.x; r2[XSTR] = v.y; r2[2 * XSTR] = v.z; r2[3 * XSTR] = v.w;
    }
    __syncthreads();

    int tc = lt & 15;                // c2 group (4 cols)
    int tp = lt >> 4;                // t-pair group (4 pairs = 8 t)
    int t0 = tp * 8;
    int c2b = tc * 4;

    float4 tb4 = *(const float4*)(tb + c2b);
    ull acc[4][4];
    #pragma unroll
    for (int j = 0; j < 4; j++) {
        acc[j][0] = pk2(tb4.x); acc[j][1] = pk2(tb4.y);
        acc[j][2] = pk2(tb4.z); acc[j][3] = pk2(tb4.w);
    }

    const float4* ws4 = (const float4*)ws;
    #pragma unroll 1
    for (int c = 0; c < 64; c++) {
        const ull* p1 = (const ull*)(xs1 + c * XSTR + t0);
        const ull* p2 = (const ull*)(xs2 + c * XSTR + t0);
        ull A0 = p1[0], A1 = p1[1], A2 = p1[2], A3 = p1[3], A4 = p1[4];
        ull O0 = p2[1], O1 = p2[2], O2 = p2[3], O3 = p2[4];
        float4 w0 = ws4[(c * 3 + 0) * 16 + tc];
        float4 w1 = ws4[(c * 3 + 1) * 16 + tc];
        float4 w2 = ws4[(c * 3 + 2) * 16 + tc];

        ull W00 = pk2(w0.x), W01 = pk2(w0.y), W02 = pk2(w0.z), W03 = pk2(w0.w);
        ull W10 = pk2(w1.x), W11 = pk2(w1.y), W12 = pk2(w1.z), W13 = pk2(w1.w);
        ull W20 = pk2(w2.x), W21 = pk2(w2.y), W22 = pk2(w2.z), W23 = pk2(w2.w);

        acc[0][0] = fma2_(W00, A0, fma2_(W10, O0, fma2_(W20, A1, acc[0][0])));
        acc[0][1] = fma2_(W01, A0, fma2_(W11, O0, fma2_(W21, A1, acc[0][1])));
        acc[0][2] = fma2_(W02, A0, fma2_(W12, O0, fma2_(W22, A1, acc[0][2])));
        acc[0][3] = fma2_(W03, A0, fma2_(W13, O0, fma2_(W23, A1, acc[0][3])));

        acc[1][0] = fma2_(W00, A1, fma2_(W10, O1, fma2_(W20, A2, acc[1][0])));
        acc[1][1] = fma2_(W01, A1, fma2_(W11, O1, fma2_(W21, A2, acc[1][1])));
        acc[1][2] = fma2_(W02, A1, fma2_(W12, O1, fma2_(W22, A2, acc[1][2])));
        acc[1][3] = fma2_(W03, A1, fma2_(W13, O1, fma2_(W23, A2, acc[1][3])));

        acc[2][0] = fma2_(W00, A2, fma2_(W10, O2, fma2_(W20, A3, acc[2][0])));
        acc[2][1] = fma2_(W01, A2, fma2_(W11, O2, fma2_(W21, A3, acc[2][1])));
        acc[2][2] = fma2_(W02, A2, fma2_(W12, O2, fma2_(W22, A3, acc[2][2])));
        acc[2][3] = fma2_(W03, A2, fma2_(W13, O2, fma2_(W23, A3, acc[2][3])));

        acc[3][0] = fma2_(W00, A3, fma2_(W10, O3, fma2_(W20, A4, acc[3][0])));
        acc[3][1] = fma2_(W01, A3, fma2_(W11, O3, fma2_(W21, A4, acc[3][1])));
        acc[3][2] = fma2_(W02, A3, fma2_(W12, O3, fma2_(W22, A4, acc[3][2])));
        acc[3][3] = fma2_(W03, A3, fma2_(W13, O3, fma2_(W23, A4, acc[3][3])));
    }

    // epilogue: store + per-thread BN partial sums (4 c2 columns)
    float s_sum[4] = {0.f, 0.f, 0.f, 0.f};
    float s_sq[4] = {0.f, 0.f, 0.f, 0.f};
    #pragma unroll
    for (int j = 0; j < 4; j++) {
        float2 q0 = upk(acc[j][0]), q1 = upk(acc[j][1]);
        float2 q2 = upk(acc[j][2]), q3 = upk(acc[j][3]);
        float4 ya = make_float4(q0.x, q1.x, q2.x, q3.x);   // t = t0+2j
        float4 yb = make_float4(q0.y, q1.y, q2.y, q3.y);   // t = t0+2j+1
        int ra = ((b * 128 + t0 + 2 * j) * 8 + n) * 64 + c2b;
        *(float4*)(out + ra) = ya;
        *(float4*)(out + ra + 512) = yb;
        s_sum[0] += ya.x + yb.x; s_sq[0] += ya.x * ya.x + yb.x * yb.x;
        s_sum[1] += ya.y + yb.y; s_sq[1] += ya.y * ya.y + yb.y * yb.y;
        s_sum[2] += ya.z + yb.z; s_sq[2] += ya.z * ya.z + yb.z * yb.z;
        s_sum[3] += ya.w + yb.w; s_sq[3] += ya.w * ya.w + yb.w * yb.w;
    }

    float* st = sm + ST_OFF;        // [32 slots][64 c2] sum, then sq
    int slot = half * 16 + tp;
    __syncthreads();
    #pragma unroll
    for (int l = 0; l < 4; l++) {
        st[slot * 64 + c2b + l] = s_sum[l];
        st[2048 + slot * 64 + c2b + l] = s_sq[l];
    }
    __syncthreads();
    if (tid < 64) {
        float s = 0.f;
        #pragma unroll
        for (int k = 0; k < 32; k++) s += st[k * 64 + tid];
        atomicAdd(&g_stats[statOff + tid], s);
    } else if (tid < 128) {
        int c = tid - 64;
        float s = 0.f;
        #pragma unroll
        for (int k = 0; k < 32; k++) s += st[2048 + k * 64 + c];
        atomicAdd(&g_stats[statOff + 64 + c], s);
    }
}

// ---------------- fused bn->relu->1x1->tanh ----------------
// FINAL==0: scrambled store of z.  FINAL==1: reduce directly into out[1024] (skips z).
template <int FINAL>
__global__ void fused_out_kernel(const float* __restrict__ tmp, const float* __restrict__ ow,
                                 const float* __restrict__ ob, const float* __restrict__ gam,
                                 const float* __restrict__ beta, float* __restrict__ z,
                                 int statOff) {
    __shared__ float ys[64][68];
    __shared__ float ws[64][68];
    __shared__ float sc[64], sh[64], obs[64];
    int tid = threadIdx.x;         // 256
    int row0 = blockIdx.x * 64;

    if (tid < 64) {
        const float inv_cnt = 1.0f / 131072.0f;
        float mu = g_stats[statOff + tid] * inv_cnt;
        float var = g_stats[statOff + 64 + tid] * inv_cnt - mu * mu;
        float scv = gam[tid] * rsqrtf(var + 1e-5f);
        sc[tid] = scv;
        sh[tid] = beta[tid] - mu * scv;
        obs[tid] = ob[tid];
    }
    for (int i = tid; i < 4096; i += 256) {
        int c2 = i >> 6, c = i & 63;
        ws[c][c2] = ow[i];
    }
    __syncthreads();
    for (int i = tid; i < 4096; i += 256) {
        int r = i >> 6, c = i & 63;
        float v = tmp[(row0 + r) * 64 + c];
        ys[r][c] = fmaxf(0.f, fmaf(v, sc[c], sh[c]));
    }
    __syncthreads();

    int tr = (tid >> 4) << 2, tc = (tid & 15) << 2;
    ull acc[4][2];
    #pragma unroll
    for (int i = 0; i < 4; i++) { acc[i][0] = 0ULL; acc[i][1] = 0ULL; }

    #pragma unroll 4
    for (int k4 = 0; k4 < 64; k4 += 4) {
        float4 a[4];
        #pragma unroll
        for (int i = 0; i < 4; i++) a[i] = *(const float4*)&ys[tr + i][k4];
        #pragma unroll
        for (int kk = 0; kk < 4; kk++) {
            ulonglong2 bv = *(const ulonglong2*)&ws[k4 + kk][tc];
            #pragma unroll
            for (int i = 0; i < 4; i++) {
                float av = (kk == 0) ? a[i].x : (kk == 1) ? a[i].y : (kk == 2) ? a[i].z : a[i].w;
                ull ap = pk2(av);
                acc[i][0] = fma2_(ap, bv.x, acc[i][0]);
                acc[i][1] = fma2_(ap, bv.y, acc[i][1]);
            }
        }
    }

    float4 oq = *(const float4*)&obs[tc];

    if (FINAL == 0) {
        #pragma unroll
        for (int i = 0; i < 4; i++) {
            int r = row0 + tr + i;
            int b = r >> 10, t = (r >> 3) & 127, n = r & 7;
            float2 p0 = upk(acc[i][0]), p1 = upk(acc[i][1]);
            int base = ((b * 64 + tc) * 8 + n) * 128 + t;
            z[base]          = tanh_ap(p0.x + oq.x);
            z[base + 1024]   = tanh_ap(p0.y + oq.y);
            z[base + 2048]   = tanh_ap(p1.x + oq.z);
            z[base + 3072]   = tanh_ap(p1.y + oq.w);
        }
    } else {
        // out[b*8 + ((2n + (t>>6)) & 7)] += (1/128) * wbar[t&63] * sum_j tanh(v_j + ob_j)
        int rbase = row0 + tr;
        int t = (rbase >> 3) & 127;               // constant over i (tr aligned 4)
        float w = g_wbar[t & 63] * (1.0f / 128.0f);
        int th = t >> 6;
        int b = rbase >> 10;
        float* sred = &ys[0][0];                  // reuse (1024 floats used)
        __syncthreads();                          // ys no longer needed by anyone
        int slot = ((tr >> 3) << 4) | (tid & 15); // 0..127
        #pragma unroll
        for (int i = 0; i < 4; i++) {
            int n = (rbase + i) & 7;
            float2 p0 = upk(acc[i][0]), p1 = upk(acc[i][1]);
            float s = tanh_ap(p0.x + oq.x) + tanh_ap(p0.y + oq.y)
                    + tanh_ap(p1.x + oq.z) + tanh_ap(p1.y + oq.w);
            sred[n * 128 + slot] = w * s;
        }
        __syncthreads();
        int n = tid >> 5, lane = tid & 31;
        float s = sred[n * 128 + lane] + sred[n * 128 + lane + 32]
                + sred[n * 128 + lane + 64] + sred[n * 128 + lane + 96];
        #pragma unroll
        for (int o = 16; o > 0; o >>= 1) s += __shfl_down_sync(0xffffffffu, s, o);
        if (lane == 0) atomicAdd(&z[b * 8 + ((2 * n + th) & 7)], s);
    }
}

// ---------------- host launcher ----------------
extern "C" void kernel_launch(void* const* d_in, const int* in_sizes, int n_in,
                              void* d_out, int out_size) {
    const float* x      = (const float*)d_in[0];
    const int*   ei     = (const int*)d_in[1];
    const float* gcn1_w = (const float*)d_in[2];
    const float* gcn1_b = (const float*)d_in[3];
    const float* t1_w   = (const float*)d_in[4];
    const float* t1_b   = (const float*)d_in[5];
    const float* bn1_g  = (const float*)d_in[6];
    const float* bn1_b  = (const float*)d_in[7];
    const float* o1_w   = (const float*)d_in[8];
    const float* o1_b   = (const float*)d_in[9];
    const float* gcn2_w = (const float*)d_in[10];
    const float* gcn2_b = (const float*)d_in[11];
    const float* t2_w   = (const float*)d_in[12];
    const float* t2_b   = (const float*)d_in[13];
    const float* bn2_g  = (const float*)d_in[14];
    const float* bn2_b  = (const float*)d_in[15];
    const float* o2_w   = (const float*)d_in[16];
    const float* o2_b   = (const float*)d_in[17];
    const float* reg_w  = (const float*)d_in[18];
    const float* reg_b  = (const float*)d_in[19];
    float* out = (float*)d_out;

    const int* src = ei;
    const int* dst = ei + EDGES;

    cudaFuncSetAttribute(tconv_kernel, cudaFuncAttributeMaxDynamicSharedMemorySize, TCONV_SMEM);

    float* bufA; cudaGetSymbolAddress((void**)&bufA, g_bufA);
    float* bufB; cudaGetSymbolAddress((void**)&bufB, g_bufB);
    float* bufC; cudaGetSymbolAddress((void**)&bufC, g_bufC);
    float* tw1;  cudaGetSymbolAddress((void**)&tw1, g_tw1);
    float* tw2;  cudaGetSymbolAddress((void**)&tw2, g_tw2);

    // prologue + edge sort (shared by both layers)
    prologue_kernel<<<512, 256>>>(reg_w, reg_b, t1_w, t2_w);
    hist_kernel<<<EDGES / 256, 256>>>(dst);
    scan1_kernel<<<128, 256>>>();
    scan2_kernel<<<1, 128>>>();
    scan3_kernel<<<NROWS / 256, 256>>>(reg_b, out);
    scatter_kernel<<<EDGES / 256, 256>>>(src, dst);

    // -------- layer 1 --------
    gemm_hs_kernel<32><<<NROWS / 128, 256>>>(x, gcn1_w, bufA);
    gather_agg_kernel<<<NROWS / 16, 256>>>(bufA, gcn1_b, bufB);
    tconv_kernel<<<512, 512, TCONV_SMEM>>>(bufB, tw1, t1_b, bufC, 0);
    fused_out_kernel<0><<<NROWS / 64, 256>>>(bufC, o1_w, o1_b, bn1_g, bn1_b, bufA, 0);

    // -------- layer 2 --------
    gemm_hs_kernel<64><<<NROWS / 128, 256>>>(bufA, gcn2_w, bufB);
    gather_agg_kernel<<<NROWS / 16, 256>>>(bufB, gcn2_b, bufC);
    tconv_kernel<<<512, 512, TCONV_SMEM>>>(bufC, tw2, t2_b, bufB, 128);
    fused_out_kernel<1><<<NROWS / 64, 256>>>(bufB, o2_w, o2_b, bn2_g, bn2_b, out, 128);
}

// round 9
// speedup vs baseline: 1.8038x; 1.1426x over previous
#include <cuda_runtime.h>
#include <cuda_bf16.h>
#include <cstdint>
#include <stdint.h>
#include <math.h>

#define NROWS 131072
#define EDGES 1048576

// ---------------- scratch (device globals) ----------------
__device__ float g_bufA[NROWS * 64];
__device__ float g_bufB[NROWS * 64];
__device__ float g_bufC[NROWS * 64];
__device__ float g_deg[NROWS];      // dinv
__device__ int   g_hist[NROWS];
__device__ int   g_off[NROWS];
__device__ int   g_cursor[NROWS];
__device__ int   g_bsum[128];
__device__ int   g_srcs[EDGES];
__device__ float g_stats[256];
__device__ float g_wbar[65];
// bf16 weight tiles [tap*2+split][64k x 64n], XOR-swizzled rows of 128B
__device__ __align__(16) __nv_bfloat16 g_wt1[24576];
__device__ __align__(16) __nv_bfloat16 g_wt2[24576];

// ---------------- f32x2 helpers ----------------
typedef unsigned long long ull;
__device__ __forceinline__ ull pk2(float x) {
    ull u; asm("mov.b64 %0,{%1,%2};" : "=l"(u) : "f"(x), "f"(x)); return u;
}
__device__ __forceinline__ float2 upk(ull u) {
    float2 r; asm("mov.b64 {%0,%1},%2;" : "=f"(r.x), "=f"(r.y) : "l"(u)); return r;
}
__device__ __forceinline__ ull fma2_(ull a, ull b, ull c) {
    ull d; asm("fma.rn.f32x2 %0,%1,%2,%3;" : "=l"(d) : "l"(a), "l"(b), "l"(c)); return d;
}
__device__ __forceinline__ float tanh_ap(float x) {
    float y; asm("tanh.approx.f32 %0,%1;" : "=f"(y) : "f"(x)); return y;
}

// ---------------- mma.sync helpers ----------------
__device__ __forceinline__ unsigned smem_u32(const void* p) {
    unsigned a;
    asm("{ .reg .u64 t; cvta.to.shared.u64 t, %1; cvt.u32.u64 %0, t; }" : "=r"(a) : "l"(p));
    return a;
}
__device__ __forceinline__ void ldsm4(unsigned& r0, unsigned& r1, unsigned& r2, unsigned& r3,
                                      unsigned addr) {
    asm volatile("ldmatrix.sync.aligned.m8n8.x4.shared.b16 {%0,%1,%2,%3}, [%4];"
                 : "=r"(r0), "=r"(r1), "=r"(r2), "=r"(r3) : "r"(addr));
}
__device__ __forceinline__ void ldsm4t(unsigned& r0, unsigned& r1, unsigned& r2, unsigned& r3,
                                       unsigned addr) {
    asm volatile("ldmatrix.sync.aligned.m8n8.x4.trans.shared.b16 {%0,%1,%2,%3}, [%4];"
                 : "=r"(r0), "=r"(r1), "=r"(r2), "=r"(r3) : "r"(addr));
}
__device__ __forceinline__ void mma_bf16(float* c, unsigned a0, unsigned a1, unsigned a2,
                                         unsigned a3, unsigned b0, unsigned b1) {
    asm volatile(
        "mma.sync.aligned.m16n8k16.row.col.f32.bf16.bf16.f32 "
        "{%0,%1,%2,%3}, {%4,%5,%6,%7}, {%8,%9}, {%0,%1,%2,%3};"
        : "+f"(c[0]), "+f"(c[1]), "+f"(c[2]), "+f"(c[3])
        : "r"(a0), "r"(a1), "r"(a2), "r"(a3), "r"(b0), "r"(b1));
}

// ---------------- prologue: zero + wbar + bf16-split [k][n] swizzled weights -------
__global__ void prologue_kernel(const float* __restrict__ rw, const float* __restrict__ rb,
                                const float* __restrict__ t1w, const float* __restrict__ t2w) {
    int i = blockIdx.x * blockDim.x + threadIdx.x;
    if (i < NROWS) g_hist[i] = 0;
    if (i < 256) g_stats[i] = 0.0f;
    if (i < 12288) {
        int k = i >> 12;              // tap 0..2
        int r = i & 4095;
        int c2 = r >> 6, c = r & 63;  // c2 = out(n), c = in(k-dim)
        int off = c * 128 + c2 * 2;   // [k][n] rows of 128B
        int sw = off ^ ((off >> 3) & 0x70);
        int idx = sw >> 1;
        float w1 = t1w[(c2 * 64 + c) * 3 + k];
        float w2 = t2w[(c2 * 64 + c) * 3 + k];
        __nv_bfloat16 h1 = __float2bfloat16_rn(w1);
        __nv_bfloat16 h2 = __float2bfloat16_rn(w2);
        __nv_bfloat16 l1 = __float2bfloat16_rn(w1 - __bfloat162float(h1));
        __nv_bfloat16 l2 = __float2bfloat16_rn(w2 - __bfloat162float(h2));
        g_wt1[(k * 2 + 0) * 4096 + idx] = h1;
        g_wt1[(k * 2 + 1) * 4096 + idx] = l1;
        g_wt2[(k * 2 + 0) * 4096 + idx] = h2;
        g_wt2[(k * 2 + 1) * 4096 + idx] = l2;
    }
    if (i < 64) {
        float s = 0.f;
        #pragma unroll
        for (int j = 0; j < 8; j++) s += rw[i * 8 + j];
        g_wbar[i] = s * 0.125f;
    }
    if (i == 64) {
        float s = 0.f;
        #pragma unroll
        for (int j = 0; j < 8; j++) s += rb[j];
        g_wbar[64] = s * 0.125f;
    }
}

__global__ void hist_kernel(const int* __restrict__ dst) {
    int e = blockIdx.x * blockDim.x + threadIdx.x;
    if (e < EDGES) atomicAdd(&g_hist[dst[e]], 1);
}

__global__ void scan1_kernel() {
    __shared__ int sh[256];
    int tid = threadIdx.x;
    int base = blockIdx.x * 1024 + tid * 4;
    int4 v = *(const int4*)&g_hist[base];
    int s0 = v.x, s1 = s0 + v.y, s2 = s1 + v.z, s3 = s2 + v.w;
    sh[tid] = s3;
    __syncthreads();
    #pragma unroll
    for (int o = 1; o < 256; o <<= 1) {
        int t = (tid >= o) ? sh[tid - o] : 0;
        __syncthreads();
        sh[tid] += t;
        __syncthreads();
    }
    int excl = tid ? sh[tid - 1] : 0;
    int4 w = make_int4(excl, excl + s0, excl + s1, excl + s2);
    *(int4*)&g_off[base] = w;
    if (tid == 255) g_bsum[blockIdx.x] = sh[255];
}

__global__ void scan2_kernel() {
    __shared__ int sh[128];
    int tid = threadIdx.x;
    sh[tid] = g_bsum[tid];
    __syncthreads();
    #pragma unroll
    for (int o = 1; o < 128; o <<= 1) {
        int t = (tid >= o) ? sh[tid - o] : 0;
        __syncthreads();
        sh[tid] += t;
        __syncthreads();
    }
    g_bsum[tid] = tid ? sh[tid - 1] : 0;
}

__global__ void scan3_kernel(const float* __restrict__ rb, float* __restrict__ out) {
    int i = blockIdx.x * blockDim.x + threadIdx.x;
    if (i < NROWS) {
        int o = g_off[i] + g_bsum[i >> 10];
        g_off[i] = o;
        g_cursor[i] = o;
        g_deg[i] = rsqrtf((float)g_hist[i] + 1.0f);
    }
    if (i < 1024) {
        float s = 0.f;
        #pragma unroll
        for (int j = 0; j < 8; j++) s += rb[j];
        out[i] = s * 0.125f;
    }
}

__global__ void scatter_kernel(const int* __restrict__ src, const int* __restrict__ dst) {
    int e = blockIdx.x * blockDim.x + threadIdx.x;
    if (e < EDGES) {
        int d = dst[e];
        int pos = atomicAdd(&g_cursor[d], 1);
        g_srcs[pos] = src[e];
    }
}

// ---------------- dense GEMM -> hs = (A@W)*dinv ----------------
template <int K>
__global__ void gemm_hs_kernel(const float* __restrict__ A, const float* __restrict__ W,
                               float* __restrict__ hs) {
    __shared__ float As[128][K + 4];
    __shared__ float Ws[K][68];
    int tid = threadIdx.x;           // 256
    int row0 = blockIdx.x * 128;

    for (int i = tid; i < K * 16; i += 256) {
        int r = i / 16, cq = i & 15;
        *(float4*)&Ws[r][cq * 4] = ((const float4*)W)[i];
    }
    constexpr int KQ = K / 4;
    for (int i = tid; i < 128 * KQ; i += 256) {
        int r = i / KQ, cq = i - r * KQ;
        *(float4*)&As[r][cq * 4] = ((const float4*)(A + (long)(row0 + r) * K))[cq];
    }
    __syncthreads();

    int tr = (tid >> 4) << 3;
    int tc = (tid & 15) << 2;
    ull acc[8][2];
    #pragma unroll
    for (int i = 0; i < 8; i++) { acc[i][0] = 0ULL; acc[i][1] = 0ULL; }

    #pragma unroll 2
    for (int k4 = 0; k4 < K; k4 += 4) {
        float4 a[8];
        #pragma unroll
        for (int i = 0; i < 8; i++) a[i] = *(const float4*)&As[tr + i][k4];
        #pragma unroll
        for (int kk = 0; kk < 4; kk++) {
            ulonglong2 bv = *(const ulonglong2*)&Ws[k4 + kk][tc];
            #pragma unroll
            for (int i = 0; i < 8; i++) {
                float av = (kk == 0) ? a[i].x : (kk == 1) ? a[i].y : (kk == 2) ? a[i].z : a[i].w;
                ull ap = pk2(av);
                acc[i][0] = fma2_(ap, bv.x, acc[i][0]);
                acc[i][1] = fma2_(ap, bv.y, acc[i][1]);
            }
        }
    }

    #pragma unroll
    for (int i = 0; i < 8; i++) {
        int r = row0 + tr + i;
        float dv = g_deg[r];
        float2 p0 = upk(acc[i][0]), p1 = upk(acc[i][1]);
        float4 h4 = make_float4(p0.x * dv, p0.y * dv, p1.x * dv, p1.y * dv);
        *(float4*)(hs + (long)r * 64 + tc) = h4;
    }
}

// ---------------- sorted gather aggregation (atomic-free) ----------------
__global__ void gather_agg_kernel(const float* __restrict__ hs, const float* __restrict__ bias,
                                  float* __restrict__ agg) {
    int tid = threadIdx.x;              // 256
    int r = blockIdx.x * 16 + (tid >> 4);
    int q = tid & 15;
    int off = __ldg(&g_off[r]);
    int cnt = __ldg(&g_hist[r]);
    float dv = g_deg[r];
    const float4* h4 = (const float4*)hs;

    float4 acc = __ldg(&h4[(long)r * 16 + q]);
    int i = 0;
    for (; i + 2 <= cnt; i += 2) {
        int s0 = __ldg(&g_srcs[off + i]);
        int s1 = __ldg(&g_srcs[off + i + 1]);
        float4 v0 = __ldg(&h4[(long)s0 * 16 + q]);
        float4 v1 = __ldg(&h4[(long)s1 * 16 + q]);
        acc.x += v0.x + v1.x; acc.y += v0.y + v1.y;
        acc.z += v0.z + v1.z; acc.w += v0.w + v1.w;
    }
    if (i < cnt) {
        int s0 = __ldg(&g_srcs[off + i]);
        float4 v0 = __ldg(&h4[(long)s0 * 16 + q]);
        acc.x += v0.x; acc.y += v0.y; acc.z += v0.z; acc.w += v0.w;
    }
    float4 b = __ldg(&((const float4*)bias)[q]);
    float4 o = make_float4(fmaf(acc.x, dv, b.x), fmaf(acc.y, dv, b.y),
                           fmaf(acc.z, dv, b.z), fmaf(acc.w, dv, b.w));
    ((float4*)agg)[(long)r * 16 + q] = o;
}

// ---------------- temporal (1,3) conv via mma.sync bf16 3-term split ----------------
// Block = (b, mt): 128 output rows. A image: 144 rows x 64 bf16 (shift -8), hi/lo,
// XOR-swizzled 128B rows. Tap k = image row offset 8k. 3 passes: AhBh, AhBl, AlBh.
#define TM_A_HI 0
#define TM_A_LO 18432
#define TM_B    36864
#define TM_BIAS 86016
#define TM_PART 86272
#define TM_SMEM 88320

__global__ void __launch_bounds__(256, 2)
tconv_mma_kernel(const float* __restrict__ in, const __nv_bfloat16* __restrict__ wt,
                 const float* __restrict__ tb, float* __restrict__ out, int statOff) {
    extern __shared__ char smc[];
    unsigned sb = smem_u32(smc);
    int tid = threadIdx.x;           // 256
    int wid = tid >> 5;
    int lane = tid & 31;
    int p = blockIdx.x;              // 1024
    int b = p >> 3;
    int mt = p & 7;

    // weights: 6 tiles x 8KB
    for (int i = tid; i < 3072; i += 256)
        ((float4*)(smc + TM_B))[i] = ((const float4*)wt)[i];
    if (tid < 64) ((float*)(smc + TM_BIAS))[tid] = tb[tid];

    // A image: 144 rows, fp32 -> bf16 hi/lo, swizzled
    const float4* in4 = (const float4*)in;
    for (int i = tid; i < 2304; i += 256) {
        int y = i >> 4, q = i & 15;
        int rr = mt * 128 + y - 8;
        float4 v = make_float4(0.f, 0.f, 0.f, 0.f);
        if (rr >= 0 && rr < 1024) v = in4[(long)(b * 1024 + rr) * 16 + q];
        __nv_bfloat162 h01 = __floats2bfloat162_rn(v.x, v.y);
        __nv_bfloat162 h23 = __floats2bfloat162_rn(v.z, v.w);
        float lx = v.x - __bfloat162float(h01.x);
        float ly = v.y - __bfloat162float(h01.y);
        float lz = v.z - __bfloat162float(h23.x);
        float lw = v.w - __bfloat162float(h23.y);
        __nv_bfloat162 l01 = __floats2bfloat162_rn(lx, ly);
        __nv_bfloat162 l23 = __floats2bfloat162_rn(lz, lw);
        int off = y * 128 + q * 8;
        int sw = off ^ ((off >> 3) & 0x70);
        uint2 hp, lp;
        hp.x = *(unsigned*)&h01; hp.y = *(unsigned*)&h23;
        lp.x = *(unsigned*)&l01; lp.y = *(unsigned*)&l23;
        *(uint2*)(smc + TM_A_HI + sw) = hp;
        *(uint2*)(smc + TM_A_LO + sw) = lp;
    }
    __syncthreads();

    int g = lane >> 2, tig = lane & 3;
    int m0 = wid * 16;
    int arow = lane & 15;            // row within 16-row tile
    int lext = (lane >> 4) << 4;     // +16B for upper-half lanes

    float acc[8][4];
    #pragma unroll
    for (int s = 0; s < 8; s++)
        #pragma unroll
        for (int j = 0; j < 4; j++) acc[s][j] = 0.f;

    #pragma unroll 1
    for (int tap = 0; tap < 3; tap++) {
        #pragma unroll 1
        for (int pass = 0; pass < 3; pass++) {
            unsigned abase = sb + ((pass == 2) ? TM_A_LO : TM_A_HI);
            unsigned btile = sb + TM_B + (unsigned)(tap * 2 + (pass == 1)) * 8192u;
            int ay = tap * 8 + m0 + arow;
            unsigned arowbase = abase + (unsigned)(ay * 128);
            unsigned asw = (unsigned)((ay & 7) << 4);
            #pragma unroll
            for (int k16 = 0; k16 < 4; k16++) {
                unsigned a0, a1, a2, a3;
                unsigned kb = (unsigned)(k16 * 32) + lext;
                ldsm4(a0, a1, a2, a3, arowbase + (kb ^ asw));
                int krow = k16 * 16 + arow;
                unsigned brow = btile + (unsigned)(krow * 128);
                unsigned bsw = (unsigned)((krow & 7) << 4);
                #pragma unroll
                for (int nn = 0; nn < 4; nn++) {
                    unsigned b0, b1, b2, b3;
                    unsigned nb = (unsigned)(nn * 32) + lext;
                    ldsm4t(b0, b1, b2, b3, brow + (nb ^ bsw));
                    mma_bf16(acc[2 * nn], a0, a1, a2, a3, b0, b1);
                    mma_bf16(acc[2 * nn + 1], a0, a1, a2, a3, b2, b3);
                }
            }
        }
    }
    __syncthreads();   // all reads of A region done; reuse as staging

    // stage y = acc + bias into smem (stride 68 floats)
    float* stg = (float*)smc;
    const float* biasS = (const float*)(smc + TM_BIAS);
    #pragma unroll
    for (int s = 0; s < 8; s++) {
        int col = s * 8 + tig * 2;
        float b0v = biasS[col], b1v = biasS[col + 1];
        int r0 = m0 + g, r1 = m0 + g + 8;
        stg[r0 * 68 + col]     = acc[s][0] + b0v;
        stg[r0 * 68 + col + 1] = acc[s][1] + b1v;
        stg[r1 * 68 + col]     = acc[s][2] + b0v;
        stg[r1 * 68 + col + 1] = acc[s][3] + b1v;
    }
    __syncthreads();

    // BN column sums (4 groups of 32 rows)
    {
        int g2 = tid >> 6, c2 = tid & 63;
        float s = 0.f, qq = 0.f;
        #pragma unroll 8
        for (int i2 = 0; i2 < 32; i2++) {
            float v = stg[(g2 * 32 + i2) * 68 + c2];
            s += v; qq = fmaf(v, v, qq);
        }
        float* ps = (float*)(smc + TM_PART);
        ps[g2 * 64 + c2] = s;
        ps[256 + g2 * 64 + c2] = qq;
    }
    __syncthreads();
    {
        const float* ps = (const float*)(smc + TM_PART);
        if (tid < 64)
            atomicAdd(&g_stats[statOff + tid], ps[tid] + ps[64 + tid] + ps[128 + tid] + ps[192 + tid]);
        else if (tid < 128) {
            int c = tid - 64;
            atomicAdd(&g_stats[statOff + 64 + c],
                      ps[256 + c] + ps[320 + c] + ps[384 + c] + ps[448 + c]);
        }
    }

    // coalesced store
    float4* out4 = (float4*)out;
    long rb16 = (long)(b * 1024 + mt * 128) * 16;
    #pragma unroll
    for (int jj = 0; jj < 8; jj++) {
        int idx = jj * 256 + tid;
        int mm = idx >> 4, q = idx & 15;
        out4[rb16 + mm * 16 + q] = *(const float4*)&stg[mm * 68 + q * 4];
    }
}

// ---------------- fused bn->relu->1x1->tanh ----------------
template <int FINAL>
__global__ void fused_out_kernel(const float* __restrict__ tmp, const float* __restrict__ ow,
                                 const float* __restrict__ ob, const float* __restrict__ gam,
                                 const float* __restrict__ beta, float* __restrict__ z,
                                 int statOff) {
    __shared__ float ys[64][68];
    __shared__ float ws[64][68];
    __shared__ float sc[64], sh[64], obs[64];
    int tid = threadIdx.x;         // 256
    int row0 = blockIdx.x * 64;

    if (tid < 64) {
        const float inv_cnt = 1.0f / 131072.0f;
        float mu = g_stats[statOff + tid] * inv_cnt;
        float var = g_stats[statOff + 64 + tid] * inv_cnt - mu * mu;
        float scv = gam[tid] * rsqrtf(var + 1e-5f);
        sc[tid] = scv;
        sh[tid] = beta[tid] - mu * scv;
        obs[tid] = ob[tid];
    }
    for (int i = tid; i < 4096; i += 256) {
        int c2 = i >> 6, c = i & 63;
        ws[c][c2] = ow[i];
    }
    __syncthreads();
    for (int i = tid; i < 4096; i += 256) {
        int r = i >> 6, c = i & 63;
        float v = tmp[(row0 + r) * 64 + c];
        ys[r][c] = fmaxf(0.f, fmaf(v, sc[c], sh[c]));
    }
    __syncthreads();

    int tr = (tid >> 4) << 2, tc = (tid & 15) << 2;
    ull acc[4][2];
    #pragma unroll
    for (int i = 0; i < 4; i++) { acc[i][0] = 0ULL; acc[i][1] = 0ULL; }

    #pragma unroll 4
    for (int k4 = 0; k4 < 64; k4 += 4) {
        float4 a[4];
        #pragma unroll
        for (int i = 0; i < 4; i++) a[i] = *(const float4*)&ys[tr + i][k4];
        #pragma unroll
        for (int kk = 0; kk < 4; kk++) {
            ulonglong2 bv = *(const ulonglong2*)&ws[k4 + kk][tc];
            #pragma unroll
            for (int i = 0; i < 4; i++) {
                float av = (kk == 0) ? a[i].x : (kk == 1) ? a[i].y : (kk == 2) ? a[i].z : a[i].w;
                ull ap = pk2(av);
                acc[i][0] = fma2_(ap, bv.x, acc[i][0]);
                acc[i][1] = fma2_(ap, bv.y, acc[i][1]);
            }
        }
    }

    float4 oq = *(const float4*)&obs[tc];

    if (FINAL == 0) {
        #pragma unroll
        for (int i = 0; i < 4; i++) {
            int r = row0 + tr + i;
            int b = r >> 10, t = (r >> 3) & 127, n = r & 7;
            float2 p0 = upk(acc[i][0]), p1 = upk(acc[i][1]);
            int base = ((b * 64 + tc) * 8 + n) * 128 + t;
            z[base]          = tanh_ap(p0.x + oq.x);
            z[base + 1024]   = tanh_ap(p0.y + oq.y);
            z[base + 2048]   = tanh_ap(p1.x + oq.z);
            z[base + 3072]   = tanh_ap(p1.y + oq.w);
        }
    } else {
        int rbase = row0 + tr;
        int t = (rbase >> 3) & 127;
        float w = g_wbar[t & 63] * (1.0f / 128.0f);
        int th = t >> 6;
        int b = rbase >> 10;
        float* sred = &ys[0][0];
        __syncthreads();
        int slot = ((tr >> 3) << 4) | (tid & 15);
        #pragma unroll
        for (int i = 0; i < 4; i++) {
            int n = (rbase + i) & 7;
            float2 p0 = upk(acc[i][0]), p1 = upk(acc[i][1]);
            float s = tanh_ap(p0.x + oq.x) + tanh_ap(p0.y + oq.y)
                    + tanh_ap(p1.x + oq.z) + tanh_ap(p1.y + oq.w);
            sred[n * 128 + slot] = w * s;
        }
        __syncthreads();
        int n = tid >> 5, lane = tid & 31;
        float s = sred[n * 128 + lane] + sred[n * 128 + lane + 32]
                + sred[n * 128 + lane + 64] + sred[n * 128 + lane + 96];
        #pragma unroll
        for (int o = 16; o > 0; o >>= 1) s += __shfl_down_sync(0xffffffffu, s, o);
        if (lane == 0) atomicAdd(&z[b * 8 + ((2 * n + th) & 7)], s);
    }
}

// ---------------- host launcher ----------------
extern "C" void kernel_launch(void* const* d_in, const int* in_sizes, int n_in,
                              void* d_out, int out_size) {
    const float* x      = (const float*)d_in[0];
    const int*   ei     = (const int*)d_in[1];
    const float* gcn1_w = (const float*)d_in[2];
    const float* gcn1_b = (const float*)d_in[3];
    const float* t1_w   = (const float*)d_in[4];
    const float* t1_b   = (const float*)d_in[5];
    const float* bn1_g  = (const float*)d_in[6];
    const float* bn1_b  = (const float*)d_in[7];
    const float* o1_w   = (const float*)d_in[8];
    const float* o1_b   = (const float*)d_in[9];
    const float* gcn2_w = (const float*)d_in[10];
    const float* gcn2_b = (const float*)d_in[11];
    const float* t2_w   = (const float*)d_in[12];
    const float* t2_b   = (const float*)d_in[13];
    const float* bn2_g  = (const float*)d_in[14];
    const float* bn2_b  = (const float*)d_in[15];
    const float* o2_w   = (const float*)d_in[16];
    const float* o2_b   = (const float*)d_in[17];
    const float* reg_w  = (const float*)d_in[18];
    const float* reg_b  = (const float*)d_in[19];
    float* out = (float*)d_out;

    const int* src = ei;
    const int* dst = ei + EDGES;

    cudaFuncSetAttribute(tconv_mma_kernel, cudaFuncAttributeMaxDynamicSharedMemorySize, TM_SMEM);

    float* bufA; cudaGetSymbolAddress((void**)&bufA, g_bufA);
    float* bufB; cudaGetSymbolAddress((void**)&bufB, g_bufB);
    float* bufC; cudaGetSymbolAddress((void**)&bufC, g_bufC);
    __nv_bfloat16* wt1; cudaGetSymbolAddress((void**)&wt1, g_wt1);
    __nv_bfloat16* wt2; cudaGetSymbolAddress((void**)&wt2, g_wt2);

    prologue_kernel<<<512, 256>>>(reg_w, reg_b, t1_w, t2_w);
    hist_kernel<<<EDGES / 256, 256>>>(dst);
    scan1_kernel<<<128, 256>>>();
    scan2_kernel<<<1, 128>>>();
    scan3_kernel<<<NROWS / 256, 256>>>(reg_b, out);
    scatter_kernel<<<EDGES / 256, 256>>>(src, dst);

    // -------- layer 1 --------
    gemm_hs_kernel<32><<<NROWS / 128, 256>>>(x, gcn1_w, bufA);
    gather_agg_kernel<<<NROWS / 16, 256>>>(bufA, gcn1_b, bufB);
    tconv_mma_kernel<<<1024, 256, TM_SMEM>>>(bufB, wt1, t1_b, bufC, 0);
    fused_out_kernel<0><<<NROWS / 64, 256>>>(bufC, o1_w, o1_b, bn1_g, bn1_b, bufA, 0);

    // -------- layer 2 --------
    gemm_hs_kernel<64><<<NROWS / 128, 256>>>(bufA, gcn2_w, bufB);
    gather_agg_kernel<<<NROWS / 16, 256>>>(bufB, gcn2_b, bufC);
    tconv_mma_kernel<<<1024, 256, TM_SMEM>>>(bufC, wt2, t2_b, bufB, 128);
    fused_out_kernel<1><<<NROWS / 64, 256>>>(bufB, o2_w, o2_b, bn2_g, bn2_b, out, 128);
}

// round 10
// speedup vs baseline: 2.2969x; 1.2734x over previous
#include <cuda_runtime.h>
#include <cuda_bf16.h>
#include <cstdint>
#include <stdint.h>
#include <math.h>

#define NROWS 131072
#define EDGES 1048576

// ---------------- scratch (device globals) ----------------
__device__ float g_bufA[NROWS * 64];
__device__ float g_bufB[NROWS * 64];
__device__ float g_bufC[NROWS * 64];
__device__ float g_deg[NROWS];      // dinv
__device__ int   g_hist[NROWS];
__device__ int   g_off[NROWS];
__device__ int   g_cursor[NROWS];
__device__ int   g_bsum[128];
__device__ int   g_srcs[EDGES];
__device__ float g_stats[256];
__device__ float g_wbar[65];
// bf16 weight tiles, XOR-swizzled 128B rows, hi tile then lo tile
__device__ __align__(16) __nv_bfloat16 g_wt1[24576];  // tconv l1: [tap*2+split][64x64]
__device__ __align__(16) __nv_bfloat16 g_wt2[24576];  // tconv l2
__device__ __align__(16) __nv_bfloat16 g_gw1[8192];   // gcn1_w [32k x 64n] (rows<32)
__device__ __align__(16) __nv_bfloat16 g_gw2[8192];   // gcn2_w [64k x 64n]
__device__ __align__(16) __nv_bfloat16 g_ow1[8192];   // o1_w^T [64c x 64c2]
__device__ __align__(16) __nv_bfloat16 g_ow2[8192];   // o2_w^T

typedef unsigned long long ull;
__device__ __forceinline__ float tanh_ap(float x) {
    float y; asm("tanh.approx.f32 %0,%1;" : "=f"(y) : "f"(x)); return y;
}

// ---------------- mma.sync helpers ----------------
__device__ __forceinline__ unsigned smem_u32(const void* p) {
    unsigned a;
    asm("{ .reg .u64 t; cvta.to.shared.u64 t, %1; cvt.u32.u64 %0, t; }" : "=r"(a) : "l"(p));
    return a;
}
__device__ __forceinline__ void ldsm4(unsigned& r0, unsigned& r1, unsigned& r2, unsigned& r3,
                                      unsigned addr) {
    asm volatile("ldmatrix.sync.aligned.m8n8.x4.shared.b16 {%0,%1,%2,%3}, [%4];"
                 : "=r"(r0), "=r"(r1), "=r"(r2), "=r"(r3) : "r"(addr));
}
__device__ __forceinline__ void ldsm4t(unsigned& r0, unsigned& r1, unsigned& r2, unsigned& r3,
                                       unsigned addr) {
    asm volatile("ldmatrix.sync.aligned.m8n8.x4.trans.shared.b16 {%0,%1,%2,%3}, [%4];"
                 : "=r"(r0), "=r"(r1), "=r"(r2), "=r"(r3) : "r"(addr));
}
__device__ __forceinline__ void mma_bf16(float* c, unsigned a0, unsigned a1, unsigned a2,
                                         unsigned a3, unsigned b0, unsigned b1) {
    asm volatile(
        "mma.sync.aligned.m16n8k16.row.col.f32.bf16.bf16.f32 "
        "{%0,%1,%2,%3}, {%4,%5,%6,%7}, {%8,%9}, {%0,%1,%2,%3};"
        : "+f"(c[0]), "+f"(c[1]), "+f"(c[2]), "+f"(c[3])
        : "r"(a0), "r"(a1), "r"(a2), "r"(a3), "r"(b0), "r"(b1));
}
__device__ __forceinline__ void split_store(char* hi, char* lo, int sw, float4 v) {
    __nv_bfloat162 h01 = __floats2bfloat162_rn(v.x, v.y);
    __nv_bfloat162 h23 = __floats2bfloat162_rn(v.z, v.w);
    float lx = v.x - __bfloat162float(h01.x);
    float ly = v.y - __bfloat162float(h01.y);
    float lz = v.z - __bfloat162float(h23.x);
    float lw = v.w - __bfloat162float(h23.y);
    __nv_bfloat162 l01 = __floats2bfloat162_rn(lx, ly);
    __nv_bfloat162 l23 = __floats2bfloat162_rn(lz, lw);
    uint2 hp, lp;
    hp.x = *(unsigned*)&h01; hp.y = *(unsigned*)&h23;
    lp.x = *(unsigned*)&l01; lp.y = *(unsigned*)&l23;
    *(uint2*)(hi + sw) = hp;
    *(uint2*)(lo + sw) = lp;
}

// ---------------- prologue ----------------
__global__ void prologue_kernel(const float* __restrict__ rw, const float* __restrict__ rb,
                                const float* __restrict__ t1w, const float* __restrict__ t2w,
                                const float* __restrict__ g1w, const float* __restrict__ g2w,
                                const float* __restrict__ o1w, const float* __restrict__ o2w) {
    int i = blockIdx.x * blockDim.x + threadIdx.x;
    if (i < NROWS) g_hist[i] = 0;
    if (i < 256) g_stats[i] = 0.0f;
    if (i < 12288) {
        int k = i >> 12;              // tap 0..2
        int r = i & 4095;
        int c2 = r >> 6, c = r & 63;
        int off = c * 128 + c2 * 2;   // [k-dim row][n]
        int sw = off ^ ((off >> 3) & 0x70);
        int idx = sw >> 1;
        float w1 = t1w[(c2 * 64 + c) * 3 + k];
        float w2 = t2w[(c2 * 64 + c) * 3 + k];
        __nv_bfloat16 h1 = __float2bfloat16_rn(w1);
        __nv_bfloat16 h2 = __float2bfloat16_rn(w2);
        g_wt1[(k * 2 + 0) * 4096 + idx] = h1;
        g_wt1[(k * 2 + 1) * 4096 + idx] = __float2bfloat16_rn(w1 - __bfloat162float(h1));
        g_wt2[(k * 2 + 0) * 4096 + idx] = h2;
        g_wt2[(k * 2 + 1) * 4096 + idx] = __float2bfloat16_rn(w2 - __bfloat162float(h2));
    } else if (i < 16384) {           // gcn2_w [64,64] k-major
        int j = i - 12288;
        int k = j >> 6, n = j & 63;
        int off = k * 128 + n * 2;
        int sw = off ^ ((off >> 3) & 0x70);
        int idx = sw >> 1;
        float w = g2w[k * 64 + n];
        __nv_bfloat16 h = __float2bfloat16_rn(w);
        g_gw2[idx] = h;
        g_gw2[4096 + idx] = __float2bfloat16_rn(w - __bfloat162float(h));
    } else if (i < 20480) {           // o1_w^T: Wt[c][c2] = o1w[c2*64+c]
        int j = i - 16384;
        int c = j >> 6, c2 = j & 63;
        int off = c * 128 + c2 * 2;
        int sw = off ^ ((off >> 3) & 0x70);
        int idx = sw >> 1;
        float w = o1w[c2 * 64 + c];
        __nv_bfloat16 h = __float2bfloat16_rn(w);
        g_ow1[idx] = h;
        g_ow1[4096 + idx] = __float2bfloat16_rn(w - __bfloat162float(h));
    } else if (i < 24576) {           // o2_w^T
        int j = i - 20480;
        int c = j >> 6, c2 = j & 63;
        int off = c * 128 + c2 * 2;
        int sw = off ^ ((off >> 3) & 0x70);
        int idx = sw >> 1;
        float w = o2w[c2 * 64 + c];
        __nv_bfloat16 h = __float2bfloat16_rn(w);
        g_ow2[idx] = h;
        g_ow2[4096 + idx] = __float2bfloat16_rn(w - __bfloat162float(h));
    } else if (i < 26624) {           // gcn1_w [32,64] k-major
        int j = i - 24576;
        int k = j >> 6, n = j & 63;
        int off = k * 128 + n * 2;
        int sw = off ^ ((off >> 3) & 0x70);
        int idx = sw >> 1;
        float w = g1w[k * 64 + n];
        __nv_bfloat16 h = __float2bfloat16_rn(w);
        g_gw1[idx] = h;
        g_gw1[4096 + idx] = __float2bfloat16_rn(w - __bfloat162float(h));
    }
    if (i < 64) {
        float s = 0.f;
        #pragma unroll
        for (int j = 0; j < 8; j++) s += rw[i * 8 + j];
        g_wbar[i] = s * 0.125f;
    }
    if (i == 64) {
        float s = 0.f;
        #pragma unroll
        for (int j = 0; j < 8; j++) s += rb[j];
        g_wbar[64] = s * 0.125f;
    }
}

__global__ void hist_kernel(const int* __restrict__ dst) {
    int e = blockIdx.x * blockDim.x + threadIdx.x;
    if (e < EDGES) atomicAdd(&g_hist[dst[e]], 1);
}

__global__ void scan1_kernel() {
    __shared__ int sh[256];
    int tid = threadIdx.x;
    int base = blockIdx.x * 1024 + tid * 4;
    int4 v = *(const int4*)&g_hist[base];
    int s0 = v.x, s1 = s0 + v.y, s2 = s1 + v.z, s3 = s2 + v.w;
    sh[tid] = s3;
    __syncthreads();
    #pragma unroll
    for (int o = 1; o < 256; o <<= 1) {
        int t = (tid >= o) ? sh[tid - o] : 0;
        __syncthreads();
        sh[tid] += t;
        __syncthreads();
    }
    int excl = tid ? sh[tid - 1] : 0;
    int4 w = make_int4(excl, excl + s0, excl + s1, excl + s2);
    *(int4*)&g_off[base] = w;
    if (tid == 255) g_bsum[blockIdx.x] = sh[255];
}

__global__ void scan2_kernel() {
    __shared__ int sh[128];
    int tid = threadIdx.x;
    sh[tid] = g_bsum[tid];
    __syncthreads();
    #pragma unroll
    for (int o = 1; o < 128; o <<= 1) {
        int t = (tid >= o) ? sh[tid - o] : 0;
        __syncthreads();
        sh[tid] += t;
        __syncthreads();
    }
    g_bsum[tid] = tid ? sh[tid - 1] : 0;
}

__global__ void scan3_kernel(const float* __restrict__ rb, float* __restrict__ out) {
    int i = blockIdx.x * blockDim.x + threadIdx.x;
    if (i < NROWS) {
        int o = g_off[i] + g_bsum[i >> 10];
        g_off[i] = o;
        g_cursor[i] = o;
        g_deg[i] = rsqrtf((float)g_hist[i] + 1.0f);
    }
    if (i < 1024) {
        float s = 0.f;
        #pragma unroll
        for (int j = 0; j < 8; j++) s += rb[j];
        out[i] = s * 0.125f;
    }
}

__global__ void scatter_kernel(const int* __restrict__ src, const int* __restrict__ dst) {
    int e = blockIdx.x * blockDim.x + threadIdx.x;
    if (e < EDGES) {
        int d = dst[e];
        int pos = atomicAdd(&g_cursor[d], 1);
        g_srcs[pos] = src[e];
    }
}

// ---------------- GEMM hs = (A@W)*dinv via mma.sync bf16 3-split ----------------
#define GM_AH 0
#define GM_AL 16384
#define GM_W  32768
#define GM_SMEM 49152

template <int K>
__global__ void __launch_bounds__(256, 2)
gemm_mma_kernel(const float* __restrict__ A, const __nv_bfloat16* __restrict__ wt,
                float* __restrict__ hs) {
    extern __shared__ char smc[];
    unsigned sb = smem_u32(smc);
    int tid = threadIdx.x;
    int wid = tid >> 5, lane = tid & 31;
    int row0 = blockIdx.x * 128;

    for (int i = tid; i < 1024; i += 256)
        ((float4*)(smc + GM_W))[i] = ((const float4*)wt)[i];

    constexpr int QR = K / 4;
    const float4* a4 = (const float4*)A;
    for (int i = tid; i < 128 * QR; i += 256) {
        int y = i / QR, q = i - y * QR;
        float4 v = a4[(long)(row0 + y) * QR + q];
        int off = y * 128 + q * 8;
        int sw = off ^ ((off >> 3) & 0x70);
        split_store(smc + GM_AH, smc + GM_AL, sw, v);
    }
    __syncthreads();

    int g = lane >> 2, tig = lane & 3;
    int m0 = wid * 16;
    int arow = lane & 15;
    int lext = (lane >> 4) << 4;

    float acc[8][4];
    #pragma unroll
    for (int s = 0; s < 8; s++)
        #pragma unroll
        for (int j = 0; j < 4; j++) acc[s][j] = 0.f;

    #pragma unroll 1
    for (int pass = 0; pass < 3; pass++) {
        unsigned abase = sb + ((pass == 2) ? GM_AL : GM_AH);
        unsigned btile = sb + GM_W + ((pass == 1) ? 8192u : 0u);
        int ay = m0 + arow;
        unsigned arb = abase + (unsigned)(ay * 128);
        unsigned asw = (unsigned)((ay & 7) << 4);
        #pragma unroll
        for (int k16 = 0; k16 < K / 16; k16++) {
            unsigned a0, a1, a2, a3;
            ldsm4(a0, a1, a2, a3, arb + (((unsigned)(k16 * 32) + lext) ^ asw));
            int krow = k16 * 16 + arow;
            unsigned brow = btile + (unsigned)(krow * 128);
            unsigned bsw = (unsigned)((krow & 7) << 4);
            #pragma unroll
            for (int nn = 0; nn < 4; nn++) {
                unsigned b0, b1, b2, b3;
                ldsm4t(b0, b1, b2, b3, brow + (((unsigned)(nn * 32) + lext) ^ bsw));
                mma_bf16(acc[2 * nn], a0, a1, a2, a3, b0, b1);
                mma_bf16(acc[2 * nn + 1], a0, a1, a2, a3, b2, b3);
            }
        }
    }
    __syncthreads();

    // stage with dinv, then coalesced store
    float* stg = (float*)smc;       // [128][68]
    int r0 = row0 + m0 + g, r1 = r0 + 8;
    float dv0 = g_deg[r0], dv1 = g_deg[r1];
    #pragma unroll
    for (int s = 0; s < 8; s++) {
        int col = s * 8 + tig * 2;
        float2 p0 = make_float2(acc[s][0] * dv0, acc[s][1] * dv0);
        float2 p1 = make_float2(acc[s][2] * dv1, acc[s][3] * dv1);
        *(float2*)&stg[(m0 + g) * 68 + col] = p0;
        *(float2*)&stg[(m0 + g + 8) * 68 + col] = p1;
    }
    __syncthreads();
    float4* o4 = (float4*)hs;
    #pragma unroll
    for (int jj = 0; jj < 8; jj++) {
        int idx = jj * 256 + tid;
        int mm = idx >> 4, q = idx & 15;
        o4[(long)(row0 + mm) * 16 + q] = *(const float4*)&stg[mm * 68 + q * 4];
    }
}

// ---------------- sorted gather aggregation (atomic-free) ----------------
__global__ void gather_agg_kernel(const float* __restrict__ hs, const float* __restrict__ bias,
                                  float* __restrict__ agg) {
    int tid = threadIdx.x;              // 256
    int r = blockIdx.x * 16 + (tid >> 4);
    int q = tid & 15;
    int off = __ldg(&g_off[r]);
    int cnt = __ldg(&g_hist[r]);
    float dv = g_deg[r];
    const float4* h4 = (const float4*)hs;

    float4 acc = __ldg(&h4[(long)r * 16 + q]);
    int i = 0;
    for (; i + 2 <= cnt; i += 2) {
        int s0 = __ldg(&g_srcs[off + i]);
        int s1 = __ldg(&g_srcs[off + i + 1]);
        float4 v0 = __ldg(&h4[(long)s0 * 16 + q]);
        float4 v1 = __ldg(&h4[(long)s1 * 16 + q]);
        acc.x += v0.x + v1.x; acc.y += v0.y + v1.y;
        acc.z += v0.z + v1.z; acc.w += v0.w + v1.w;
    }
    if (i < cnt) {
        int s0 = __ldg(&g_srcs[off + i]);
        float4 v0 = __ldg(&h4[(long)s0 * 16 + q]);
        acc.x += v0.x; acc.y += v0.y; acc.z += v0.z; acc.w += v0.w;
    }
    float4 b = __ldg(&((const float4*)bias)[q]);
    float4 o = make_float4(fmaf(acc.x, dv, b.x), fmaf(acc.y, dv, b.y),
                           fmaf(acc.z, dv, b.z), fmaf(acc.w, dv, b.w));
    ((float4*)agg)[(long)r * 16 + q] = o;
}

// ---------------- temporal (1,3) conv via mma.sync bf16 3-split (R9, proven) --------
#define TM_A_HI 0
#define TM_A_LO 18432
#define TM_B    36864
#define TM_BIAS 86016
#define TM_PART 86272
#define TM_SMEM 88320

__global__ void __launch_bounds__(256, 2)
tconv_mma_kernel(const float* __restrict__ in, const __nv_bfloat16* __restrict__ wt,
                 const float* __restrict__ tb, float* __restrict__ out, int statOff) {
    extern __shared__ char smc[];
    unsigned sb = smem_u32(smc);
    int tid = threadIdx.x;           // 256
    int wid = tid >> 5;
    int lane = tid & 31;
    int p = blockIdx.x;              // 1024
    int b = p >> 3;
    int mt = p & 7;

    for (int i = tid; i < 3072; i += 256)
        ((float4*)(smc + TM_B))[i] = ((const float4*)wt)[i];
    if (tid < 64) ((float*)(smc + TM_BIAS))[tid] = tb[tid];

    const float4* in4 = (const float4*)in;
    for (int i = tid; i < 2304; i += 256) {
        int y = i >> 4, q = i & 15;
        int rr = mt * 128 + y - 8;
        float4 v = make_float4(0.f, 0.f, 0.f, 0.f);
        if (rr >= 0 && rr < 1024) v = in4[(long)(b * 1024 + rr) * 16 + q];
        int off = y * 128 + q * 8;
        int sw = off ^ ((off >> 3) & 0x70);
        split_store(smc + TM_A_HI, smc + TM_A_LO, sw, v);
    }
    __syncthreads();

    int g = lane >> 2, tig = lane & 3;
    int m0 = wid * 16;
    int arow = lane & 15;
    int lext = (lane >> 4) << 4;

    float acc[8][4];
    #pragma unroll
    for (int s = 0; s < 8; s++)
        #pragma unroll
        for (int j = 0; j < 4; j++) acc[s][j] = 0.f;

    #pragma unroll 1
    for (int tap = 0; tap < 3; tap++) {
        #pragma unroll 1
        for (int pass = 0; pass < 3; pass++) {
            unsigned abase = sb + ((pass == 2) ? TM_A_LO : TM_A_HI);
            unsigned btile = sb + TM_B + (unsigned)(tap * 2 + (pass == 1)) * 8192u;
            int ay = tap * 8 + m0 + arow;
            unsigned arowbase = abase + (unsigned)(ay * 128);
            unsigned asw = (unsigned)((ay & 7) << 4);
            #pragma unroll
            for (int k16 = 0; k16 < 4; k16++) {
                unsigned a0, a1, a2, a3;
                ldsm4(a0, a1, a2, a3, arowbase + (((unsigned)(k16 * 32) + lext) ^ asw));
                int krow = k16 * 16 + arow;
                unsigned brow = btile + (unsigned)(krow * 128);
                unsigned bsw = (unsigned)((krow & 7) << 4);
                #pragma unroll
                for (int nn = 0; nn < 4; nn++) {
                    unsigned b0, b1, b2, b3;
                    ldsm4t(b0, b1, b2, b3, brow + (((unsigned)(nn * 32) + lext) ^ bsw));
                    mma_bf16(acc[2 * nn], a0, a1, a2, a3, b0, b1);
                    mma_bf16(acc[2 * nn + 1], a0, a1, a2, a3, b2, b3);
                }
            }
        }
    }
    __syncthreads();

    float* stg = (float*)smc;
    const float* biasS = (const float*)(smc + TM_BIAS);
    #pragma unroll
    for (int s = 0; s < 8; s++) {
        int col = s * 8 + tig * 2;
        float b0v = biasS[col], b1v = biasS[col + 1];
        int r0 = m0 + g, r1 = m0 + g + 8;
        stg[r0 * 68 + col]     = acc[s][0] + b0v;
        stg[r0 * 68 + col + 1] = acc[s][1] + b1v;
        stg[r1 * 68 + col]     = acc[s][2] + b0v;
        stg[r1 * 68 + col + 1] = acc[s][3] + b1v;
    }
    __syncthreads();

    {
        int g2 = tid >> 6, c2 = tid & 63;
        float s = 0.f, qq = 0.f;
        #pragma unroll 8
        for (int i2 = 0; i2 < 32; i2++) {
            float v = stg[(g2 * 32 + i2) * 68 + c2];
            s += v; qq = fmaf(v, v, qq);
        }
        float* ps = (float*)(smc + TM_PART);
        ps[g2 * 64 + c2] = s;
        ps[256 + g2 * 64 + c2] = qq;
    }
    __syncthreads();
    {
        const float* ps = (const float*)(smc + TM_PART);
        if (tid < 64)
            atomicAdd(&g_stats[statOff + tid], ps[tid] + ps[64 + tid] + ps[128 + tid] + ps[192 + tid]);
        else if (tid < 128) {
            int c = tid - 64;
            atomicAdd(&g_stats[statOff + 64 + c],
                      ps[256 + c] + ps[320 + c] + ps[384 + c] + ps[448 + c]);
        }
    }

    float4* out4 = (float4*)out;
    long rb16 = (long)(b * 1024 + mt * 128) * 16;
    #pragma unroll
    for (int jj = 0; jj < 8; jj++) {
        int idx = jj * 256 + tid;
        int mm = idx >> 4, q = idx & 15;
        out4[rb16 + mm * 16 + q] = *(const float4*)&stg[mm * 68 + q * 4];
    }
}

// ---------------- fused bn->relu->1x1->tanh via mma.sync ----------------
#define FM_AH 0
#define FM_AL 16384
#define FM_W  32768
#define FM_MISC 49152
#define FM_SRED (FM_MISC + 768)
#define FM_SMEM 50176

template <int FINAL>
__global__ void __launch_bounds__(256, 2)
fused_mma_kernel(const float* __restrict__ tmp, const __nv_bfloat16* __restrict__ wt,
                 const float* __restrict__ ob, const float* __restrict__ gam,
                 const float* __restrict__ beta, float* __restrict__ z, int statOff) {
    extern __shared__ char smc[];
    unsigned sb = smem_u32(smc);
    int tid = threadIdx.x;
    int wid = tid >> 5, lane = tid & 31;
    int row0 = blockIdx.x * 128;

    float* scS = (float*)(smc + FM_MISC);
    float* shS = scS + 64;
    float* obsS = scS + 128;
    float* sred = (float*)(smc + FM_SRED);

    if (tid < 64) {
        const float inv_cnt = 1.0f / 131072.0f;
        float mu = g_stats[statOff + tid] * inv_cnt;
        float var = g_stats[statOff + 64 + tid] * inv_cnt - mu * mu;
        float scv = gam[tid] * rsqrtf(var + 1e-5f);
        scS[tid] = scv;
        shS[tid] = beta[tid] - mu * scv;
        obsS[tid] = ob[tid];
        sred[tid] = 0.f;
    }
    for (int i = tid; i < 1024; i += 256)
        ((float4*)(smc + FM_W))[i] = ((const float4*)wt)[i];
    __syncthreads();

    // BN + relu + bf16-split conversion
    const float4* t4 = (const float4*)tmp;
    for (int i = tid; i < 2048; i += 256) {
        int y = i >> 4, q = i & 15;
        float4 v = t4[(long)(row0 + y) * 16 + q];
        float4 sc4 = *(const float4*)&scS[q * 4];
        float4 sh4 = *(const float4*)&shS[q * 4];
        float4 r;
        r.x = fmaxf(0.f, fmaf(v.x, sc4.x, sh4.x));
        r.y = fmaxf(0.f, fmaf(v.y, sc4.y, sh4.y));
        r.z = fmaxf(0.f, fmaf(v.z, sc4.z, sh4.z));
        r.w = fmaxf(0.f, fmaf(v.w, sc4.w, sh4.w));
        int off = y * 128 + q * 8;
        int sw = off ^ ((off >> 3) & 0x70);
        split_store(smc + FM_AH, smc + FM_AL, sw, r);
    }
    __syncthreads();

    int g = lane >> 2, tig = lane & 3;
    int m0 = wid * 16;
    int arow = lane & 15;
    int lext = (lane >> 4) << 4;

    float acc[8][4];
    #pragma unroll
    for (int s = 0; s < 8; s++)
        #pragma unroll
        for (int j = 0; j < 4; j++) acc[s][j] = 0.f;

    #pragma unroll 1
    for (int pass = 0; pass < 3; pass++) {
        unsigned abase = sb + ((pass == 2) ? FM_AL : FM_AH);
        unsigned btile = sb + FM_W + ((pass == 1) ? 8192u : 0u);
        int ay = m0 + arow;
        unsigned arb = abase + (unsigned)(ay * 128);
        unsigned asw = (unsigned)((ay & 7) << 4);
        #pragma unroll
        for (int k16 = 0; k16 < 4; k16++) {
            unsigned a0, a1, a2, a3;
            ldsm4(a0, a1, a2, a3, arb + (((unsigned)(k16 * 32) + lext) ^ asw));
            int krow = k16 * 16 + arow;
            unsigned brow = btile + (unsigned)(krow * 128);
            unsigned bsw = (unsigned)((krow & 7) << 4);
            #pragma unroll
            for (int nn = 0; nn < 4; nn++) {
                unsigned b0, b1, b2, b3;
                ldsm4t(b0, b1, b2, b3, brow + (((unsigned)(nn * 32) + lext) ^ bsw));
                mma_bf16(acc[2 * nn], a0, a1, a2, a3, b0, b1);
                mma_bf16(acc[2 * nn + 1], a0, a1, a2, a3, b2, b3);
            }
        }
    }

    // geometry: rows r0 = row0+m0+g (n=g, t0), r1 = r0+8 (same n, t0+1)
    int bq = row0 >> 10;
    int t0 = ((row0 + m0) >> 3) & 127;       // uniform per warp, even

    if (FINAL == 0) {
        __syncthreads();                      // A/W regions now reusable
        // stage z tile [c2][n][t'] with stride 132 per c2
        float* stg2 = (float*)smc;
        #pragma unroll
        for (int s = 0; s < 8; s++) {
            int c2 = s * 8 + tig * 2;
            float o0 = obsS[c2], o1 = obsS[c2 + 1];
            int tp = 2 * wid;                 // t' for row g; row g+8 -> tp+1
            float2 va = make_float2(tanh_ap(acc[s][0] + o0), tanh_ap(acc[s][2] + o0));
            float2 vb = make_float2(tanh_ap(acc[s][1] + o1), tanh_ap(acc[s][3] + o1));
            *(float2*)&stg2[c2 * 132 + g * 16 + tp] = va;
            *(float2*)&stg2[(c2 + 1) * 132 + g * 16 + tp] = vb;
        }
        __syncthreads();
        int t0b = (row0 >> 3) & 127;
        float4* z4 = (float4*)z;
        int gb4 = bq * 16384 + (t0b >> 2);
        for (int i = tid; i < 2048; i += 256) {
            int c2 = i >> 5, rem = i & 31;
            int n = rem >> 2, q = rem & 3;
            float4 v = *(const float4*)&stg2[c2 * 132 + n * 16 + q * 4];
            z4[gb4 + c2 * 256 + n * 32 + q] = v;
        }
    } else {
        // reduce directly into out[bq*8 + (2n+th)&7]
        float w0 = g_wbar[t0 & 63] * 0.0078125f;
        float w1 = g_wbar[(t0 + 1) & 63] * 0.0078125f;
        float s0 = 0.f, s1 = 0.f;
        #pragma unroll
        for (int s = 0; s < 8; s++) {
            int c2 = s * 8 + tig * 2;
            float o0 = obsS[c2], o1 = obsS[c2 + 1];
            s0 += tanh_ap(acc[s][0] + o0) + tanh_ap(acc[s][1] + o1);
            s1 += tanh_ap(acc[s][2] + o0) + tanh_ap(acc[s][3] + o1);
        }
        float part = w0 * s0 + w1 * s1;
        part += __shfl_xor_sync(0xffffffffu, part, 1);
        part += __shfl_xor_sync(0xffffffffu, part, 2);
        part += __shfl_xor_sync(0xffffffffu, part, 16);   // merge n=g with n=g+4 (same idx)
        int th = (t0 >> 6) & 1;
        if (tig == 0 && g < 4) {
            int idx = (2 * g + th) & 7;
            sred[idx * 8 + wid] = part;
        }
        __syncthreads();
        if (tid < 8) {
            float ssum = 0.f;
            #pragma unroll
            for (int w = 0; w < 8; w++) ssum += sred[tid * 8 + w];
            atomicAdd(&z[bq * 8 + tid], ssum);
        }
    }
}

// ---------------- host launcher ----------------
extern "C" void kernel_launch(void* const* d_in, const int* in_sizes, int n_in,
                              void* d_out, int out_size) {
    const float* x      = (const float*)d_in[0];
    const int*   ei     = (const int*)d_in[1];
    const float* gcn1_w = (const float*)d_in[2];
    const float* gcn1_b = (const float*)d_in[3];
    const float* t1_w   = (const float*)d_in[4];
    const float* t1_b   = (const float*)d_in[5];
    const float* bn1_g  = (const float*)d_in[6];
    const float* bn1_b  = (const float*)d_in[7];
    const float* o1_w   = (const float*)d_in[8];
    const float* o1_b   = (const float*)d_in[9];
    const float* gcn2_w = (const float*)d_in[10];
    const float* gcn2_b = (const float*)d_in[11];
    const float* t2_w   = (const float*)d_in[12];
    const float* t2_b   = (const float*)d_in[13];
    const float* bn2_g  = (const float*)d_in[14];
    const float* bn2_b  = (const float*)d_in[15];
    const float* o2_w   = (const float*)d_in[16];
    const float* o2_b   = (const float*)d_in[17];
    const float* reg_w  = (const float*)d_in[18];
    const float* reg_b  = (const float*)d_in[19];
    float* out = (float*)d_out;

    const int* src = ei;
    const int* dst = ei + EDGES;

    cudaFuncSetAttribute(tconv_mma_kernel, cudaFuncAttributeMaxDynamicSharedMemorySize, TM_SMEM);
    cudaFuncSetAttribute(gemm_mma_kernel<32>, cudaFuncAttributeMaxDynamicSharedMemorySize, GM_SMEM);
    cudaFuncSetAttribute(gemm_mma_kernel<64>, cudaFuncAttributeMaxDynamicSharedMemorySize, GM_SMEM);
    cudaFuncSetAttribute(fused_mma_kernel<0>, cudaFuncAttributeMaxDynamicSharedMemorySize, FM_SMEM);
    cudaFuncSetAttribute(fused_mma_kernel<1>, cudaFuncAttributeMaxDynamicSharedMemorySize, FM_SMEM);

    float* bufA; cudaGetSymbolAddress((void**)&bufA, g_bufA);
    float* bufB; cudaGetSymbolAddress((void**)&bufB, g_bufB);
    float* bufC; cudaGetSymbolAddress((void**)&bufC, g_bufC);
    __nv_bfloat16* wt1; cudaGetSymbolAddress((void**)&wt1, g_wt1);
    __nv_bfloat16* wt2; cudaGetSymbolAddress((void**)&wt2, g_wt2);
    __nv_bfloat16* gw1; cudaGetSymbolAddress((void**)&gw1, g_gw1);
    __nv_bfloat16* gw2; cudaGetSymbolAddress((void**)&gw2, g_gw2);
    __nv_bfloat16* ow1; cudaGetSymbolAddress((void**)&ow1, g_ow1);
    __nv_bfloat16* ow2; cudaGetSymbolAddress((void**)&ow2, g_ow2);

    prologue_kernel<<<512, 256>>>(reg_w, reg_b, t1_w, t2_w, gcn1_w, gcn2_w, o1_w, o2_w);
    hist_kernel<<<EDGES / 256, 256>>>(dst);
    scan1_kernel<<<128, 256>>>();
    scan2_kernel<<<1, 128>>>();
    scan3_kernel<<<NROWS / 256, 256>>>(reg_b, out);
    scatter_kernel<<<EDGES / 256, 256>>>(src, dst);

    // -------- layer 1 --------
    gemm_mma_kernel<32><<<NROWS / 128, 256, GM_SMEM>>>(x, gw1, bufA);
    gather_agg_kernel<<<NROWS / 16, 256>>>(bufA, gcn1_b, bufB);
    tconv_mma_kernel<<<1024, 256, TM_SMEM>>>(bufB, wt1, t1_b, bufC, 0);
    fused_mma_kernel<0><<<NROWS / 128, 256, FM_SMEM>>>(bufC, ow1, o1_b, bn1_g, bn1_b, bufA, 0);

    // -------- layer 2 --------
    gemm_mma_kernel<64><<<NROWS / 128, 256, GM_SMEM>>>(bufA, gw2, bufB);
    gather_agg_kernel<<<NROWS / 16, 256>>>(bufB, gcn2_b, bufC);
    tconv_mma_kernel<<<1024, 256, TM_SMEM>>>(bufC, wt2, t2_b, bufB, 128);
    fused_mma_kernel<1><<<NROWS / 128, 256, FM_SMEM>>>(bufB, ow2, o2_b, bn2_g, bn2_b, out, 128);
}

// round 11
// speedup vs baseline: 2.4199x; 1.0536x over previous
#include <cuda_runtime.h>
#include <cuda_bf16.h>
#include <cstdint>
#include <stdint.h>
#include <math.h>

#define NROWS 131072
#define EDGES 1048576

// ---------------- scratch (device globals) ----------------
__device__ float g_bufA[NROWS * 64];
__device__ float g_bufB[NROWS * 64];
__device__ float g_bufC[NROWS * 64];
__device__ float g_deg[NROWS];      // dinv
__device__ int   g_hist[NROWS];
__device__ int   g_off[NROWS];
__device__ int   g_cursor[NROWS];
__device__ int   g_bsum[128];
__device__ int   g_srcs[EDGES];
__device__ float g_stats[256];
__device__ float g_wbar[65];
// bf16 weight tiles, XOR-swizzled 128B rows, hi tile then lo tile
__device__ __align__(16) __nv_bfloat16 g_wt1[24576];  // tconv l1: [tap*2+split][64x64]
__device__ __align__(16) __nv_bfloat16 g_wt2[24576];  // tconv l2
__device__ __align__(16) __nv_bfloat16 g_gw1[8192];   // gcn1_w [32k x 64n]
__device__ __align__(16) __nv_bfloat16 g_gw2[8192];   // gcn2_w [64k x 64n]
__device__ __align__(16) __nv_bfloat16 g_ow1[8192];   // o1_w^T [64c x 64c2]
__device__ __align__(16) __nv_bfloat16 g_ow2[8192];   // o2_w^T

typedef unsigned long long ull;
__device__ __forceinline__ float tanh_ap(float x) {
    float y; asm("tanh.approx.f32 %0,%1;" : "=f"(y) : "f"(x)); return y;
}

// ---------------- mma.sync helpers ----------------
__device__ __forceinline__ unsigned smem_u32(const void* p) {
    unsigned a;
    asm("{ .reg .u64 t; cvta.to.shared.u64 t, %1; cvt.u32.u64 %0, t; }" : "=r"(a) : "l"(p));
    return a;
}
__device__ __forceinline__ void ldsm4(unsigned& r0, unsigned& r1, unsigned& r2, unsigned& r3,
                                      unsigned addr) {
    asm volatile("ldmatrix.sync.aligned.m8n8.x4.shared.b16 {%0,%1,%2,%3}, [%4];"
                 : "=r"(r0), "=r"(r1), "=r"(r2), "=r"(r3) : "r"(addr));
}
__device__ __forceinline__ void ldsm4t(unsigned& r0, unsigned& r1, unsigned& r2, unsigned& r3,
                                       unsigned addr) {
    asm volatile("ldmatrix.sync.aligned.m8n8.x4.trans.shared.b16 {%0,%1,%2,%3}, [%4];"
                 : "=r"(r0), "=r"(r1), "=r"(r2), "=r"(r3) : "r"(addr));
}
__device__ __forceinline__ void mma_bf16(float* c, unsigned a0, unsigned a1, unsigned a2,
                                         unsigned a3, unsigned b0, unsigned b1) {
    asm volatile(
        "mma.sync.aligned.m16n8k16.row.col.f32.bf16.bf16.f32 "
        "{%0,%1,%2,%3}, {%4,%5,%6,%7}, {%8,%9}, {%0,%1,%2,%3};"
        : "+f"(c[0]), "+f"(c[1]), "+f"(c[2]), "+f"(c[3])
        : "r"(a0), "r"(a1), "r"(a2), "r"(a3), "r"(b0), "r"(b1));
}
__device__ __forceinline__ void split_store(char* hi, char* lo, int sw, float4 v) {
    __nv_bfloat162 h01 = __floats2bfloat162_rn(v.x, v.y);
    __nv_bfloat162 h23 = __floats2bfloat162_rn(v.z, v.w);
    float lx = v.x - __bfloat162float(h01.x);
    float ly = v.y - __bfloat162float(h01.y);
    float lz = v.z - __bfloat162float(h23.x);
    float lw = v.w - __bfloat162float(h23.y);
    __nv_bfloat162 l01 = __floats2bfloat162_rn(lx, ly);
    __nv_bfloat162 l23 = __floats2bfloat162_rn(lz, lw);
    uint2 hp, lp;
    hp.x = *(unsigned*)&h01; hp.y = *(unsigned*)&h23;
    lp.x = *(unsigned*)&l01; lp.y = *(unsigned*)&l23;
    *(uint2*)(hi + sw) = hp;
    *(uint2*)(lo + sw) = lp;
}

// shared 3-pass bf16-split GEMM micro-kernel: A image (hi/lo) x B tiles (hi at btile, lo +8192B)
// acc layout: acc[s][j], rows m0+g (j=0,1) & m0+g+8 (j=2,3), cols c2 = s*8+tig*2+(j&1)
__device__ __forceinline__ void mma_3split_64(float acc[8][4], unsigned sb, unsigned ahOff,
                                              unsigned alOff, unsigned wOff, int m0, int lane) {
    int arow = lane & 15;
    int lext = (lane >> 4) << 4;
    #pragma unroll 1
    for (int pass = 0; pass < 3; pass++) {
        unsigned abase = sb + ((pass == 2) ? alOff : ahOff);
        unsigned btile = sb + wOff + ((pass == 1) ? 8192u : 0u);
        int ay = m0 + arow;
        unsigned arb = abase + (unsigned)(ay * 128);
        unsigned asw = (unsigned)((ay & 7) << 4);
        #pragma unroll
        for (int k16 = 0; k16 < 4; k16++) {
            unsigned a0, a1, a2, a3;
            ldsm4(a0, a1, a2, a3, arb + (((unsigned)(k16 * 32) + lext) ^ asw));
            int krow = k16 * 16 + arow;
            unsigned brow = btile + (unsigned)(krow * 128);
            unsigned bsw = (unsigned)((krow & 7) << 4);
            #pragma unroll
            for (int nn = 0; nn < 4; nn++) {
                unsigned b0, b1, b2, b3;
                ldsm4t(b0, b1, b2, b3, brow + (((unsigned)(nn * 32) + lext) ^ bsw));
                mma_bf16(acc[2 * nn], a0, a1, a2, a3, b0, b1);
                mma_bf16(acc[2 * nn + 1], a0, a1, a2, a3, b2, b3);
            }
        }
    }
}

// ---------------- prologue ----------------
__global__ void prologue_kernel(const float* __restrict__ rw, const float* __restrict__ rb,
                                const float* __restrict__ t1w, const float* __restrict__ t2w,
                                const float* __restrict__ g1w, const float* __restrict__ g2w,
                                const float* __restrict__ o1w, const float* __restrict__ o2w) {
    int i = blockIdx.x * blockDim.x + threadIdx.x;
    if (i < NROWS) g_hist[i] = 0;
    if (i < 256) g_stats[i] = 0.0f;
    if (i < 12288) {
        int k = i >> 12;
        int r = i & 4095;
        int c2 = r >> 6, c = r & 63;
        int off = c * 128 + c2 * 2;
        int sw = off ^ ((off >> 3) & 0x70);
        int idx = sw >> 1;
        float w1 = t1w[(c2 * 64 + c) * 3 + k];
        float w2 = t2w[(c2 * 64 + c) * 3 + k];
        __nv_bfloat16 h1 = __float2bfloat16_rn(w1);
        __nv_bfloat16 h2 = __float2bfloat16_rn(w2);
        g_wt1[(k * 2 + 0) * 4096 + idx] = h1;
        g_wt1[(k * 2 + 1) * 4096 + idx] = __float2bfloat16_rn(w1 - __bfloat162float(h1));
        g_wt2[(k * 2 + 0) * 4096 + idx] = h2;
        g_wt2[(k * 2 + 1) * 4096 + idx] = __float2bfloat16_rn(w2 - __bfloat162float(h2));
    } else if (i < 16384) {
        int j = i - 12288;
        int k = j >> 6, n = j & 63;
        int off = k * 128 + n * 2;
        int sw = off ^ ((off >> 3) & 0x70);
        int idx = sw >> 1;
        float w = g2w[k * 64 + n];
        __nv_bfloat16 h = __float2bfloat16_rn(w);
        g_gw2[idx] = h;
        g_gw2[4096 + idx] = __float2bfloat16_rn(w - __bfloat162float(h));
    } else if (i < 20480) {
        int j = i - 16384;
        int c = j >> 6, c2 = j & 63;
        int off = c * 128 + c2 * 2;
        int sw = off ^ ((off >> 3) & 0x70);
        int idx = sw >> 1;
        float w = o1w[c2 * 64 + c];
        __nv_bfloat16 h = __float2bfloat16_rn(w);
        g_ow1[idx] = h;
        g_ow1[4096 + idx] = __float2bfloat16_rn(w - __bfloat162float(h));
    } else if (i < 24576) {
        int j = i - 20480;
        int c = j >> 6, c2 = j & 63;
        int off = c * 128 + c2 * 2;
        int sw = off ^ ((off >> 3) & 0x70);
        int idx = sw >> 1;
        float w = o2w[c2 * 64 + c];
        __nv_bfloat16 h = __float2bfloat16_rn(w);
        g_ow2[idx] = h;
        g_ow2[4096 + idx] = __float2bfloat16_rn(w - __bfloat162float(h));
    } else if (i < 26624) {
        int j = i - 24576;
        int k = j >> 6, n = j & 63;
        int off = k * 128 + n * 2;
        int sw = off ^ ((off >> 3) & 0x70);
        int idx = sw >> 1;
        float w = g1w[k * 64 + n];
        __nv_bfloat16 h = __float2bfloat16_rn(w);
        g_gw1[idx] = h;
        g_gw1[4096 + idx] = __float2bfloat16_rn(w - __bfloat162float(h));
    }
    if (i < 64) {
        float s = 0.f;
        #pragma unroll
        for (int j = 0; j < 8; j++) s += rw[i * 8 + j];
        g_wbar[i] = s * 0.125f;
    }
    if (i == 64) {
        float s = 0.f;
        #pragma unroll
        for (int j = 0; j < 8; j++) s += rb[j];
        g_wbar[64] = s * 0.125f;
    }
}

__global__ void hist_kernel(const int* __restrict__ dst) {
    int e = blockIdx.x * blockDim.x + threadIdx.x;
    if (e < EDGES) atomicAdd(&g_hist[dst[e]], 1);
}

__global__ void scan1_kernel() {
    __shared__ int sh[256];
    int tid = threadIdx.x;
    int base = blockIdx.x * 1024 + tid * 4;
    int4 v = *(const int4*)&g_hist[base];
    int s0 = v.x, s1 = s0 + v.y, s2 = s1 + v.z, s3 = s2 + v.w;
    sh[tid] = s3;
    __syncthreads();
    #pragma unroll
    for (int o = 1; o < 256; o <<= 1) {
        int t = (tid >= o) ? sh[tid - o] : 0;
        __syncthreads();
        sh[tid] += t;
        __syncthreads();
    }
    int excl = tid ? sh[tid - 1] : 0;
    int4 w = make_int4(excl, excl + s0, excl + s1, excl + s2);
    *(int4*)&g_off[base] = w;
    if (tid == 255) g_bsum[blockIdx.x] = sh[255];
}

// scan3: local re-scan of the 128 segment sums (replaces scan2) + dinv/cursor/out-init
__global__ void scan3_kernel(const float* __restrict__ rb, float* __restrict__ out) {
    __shared__ int bs[128];
    int tid = threadIdx.x;
    if (tid < 128) bs[tid] = g_bsum[tid];
    __syncthreads();
    #pragma unroll
    for (int o = 1; o < 128; o <<= 1) {
        int t = (tid < 128 && tid >= o) ? bs[tid - o] : 0;
        __syncthreads();
        if (tid < 128) bs[tid] += t;
        __syncthreads();
    }
    int i = blockIdx.x * blockDim.x + tid;
    if (i < NROWS) {
        int seg = i >> 10;
        int o = g_off[i] + (seg ? bs[seg - 1] : 0);
        g_off[i] = o;
        g_cursor[i] = o;
        g_deg[i] = rsqrtf((float)g_hist[i] + 1.0f);
    }
    if (i < 1024) {
        float s = 0.f;
        #pragma unroll
        for (int j = 0; j < 8; j++) s += rb[j];
        out[i] = s * 0.125f;
    }
}

__global__ void scatter_kernel(const int* __restrict__ src, const int* __restrict__ dst) {
    int e = blockIdx.x * blockDim.x + threadIdx.x;
    if (e < EDGES) {
        int d = dst[e];
        int pos = atomicAdd(&g_cursor[d], 1);
        g_srcs[pos] = src[e];
    }
}

// ---------------- GEMM hs = (A@W)*dinv via mma.sync (layer 1 input) ----------------
#define GM_AH 0
#define GM_AL 16384
#define GM_W  32768
#define GM_SMEM 49152

template <int K>
__global__ void __launch_bounds__(256, 2)
gemm_mma_kernel(const float* __restrict__ A, const __nv_bfloat16* __restrict__ wt,
                float* __restrict__ hs) {
    extern __shared__ char smc[];
    unsigned sb = smem_u32(smc);
    int tid = threadIdx.x;
    int wid = tid >> 5, lane = tid & 31;
    int row0 = blockIdx.x * 128;

    for (int i = tid; i < 1024; i += 256)
        ((float4*)(smc + GM_W))[i] = ((const float4*)wt)[i];

    constexpr int QR = K / 4;
    const float4* a4 = (const float4*)A;
    for (int i = tid; i < 128 * QR; i += 256) {
        int y = i / QR, q = i - y * QR;
        float4 v = a4[(long)(row0 + y) * QR + q];
        int off = y * 128 + q * 8;
        int sw = off ^ ((off >> 3) & 0x70);
        split_store(smc + GM_AH, smc + GM_AL, sw, v);
    }
    __syncthreads();

    int g = lane >> 2, tig = lane & 3;
    int m0 = wid * 16;
    int arow = lane & 15;
    int lext = (lane >> 4) << 4;

    float acc[8][4];
    #pragma unroll
    for (int s = 0; s < 8; s++)
        #pragma unroll
        for (int j = 0; j < 4; j++) acc[s][j] = 0.f;

    #pragma unroll 1
    for (int pass = 0; pass < 3; pass++) {
        unsigned abase = sb + ((pass == 2) ? GM_AL : GM_AH);
        unsigned btile = sb + GM_W + ((pass == 1) ? 8192u : 0u);
        int ay = m0 + arow;
        unsigned arb = abase + (unsigned)(ay * 128);
        unsigned asw = (unsigned)((ay & 7) << 4);
        #pragma unroll
        for (int k16 = 0; k16 < K / 16; k16++) {
            unsigned a0, a1, a2, a3;
            ldsm4(a0, a1, a2, a3, arb + (((unsigned)(k16 * 32) + lext) ^ asw));
            int krow = k16 * 16 + arow;
            unsigned brow = btile + (unsigned)(krow * 128);
            unsigned bsw = (unsigned)((krow & 7) << 4);
            #pragma unroll
            for (int nn = 0; nn < 4; nn++) {
                unsigned b0, b1, b2, b3;
                ldsm4t(b0, b1, b2, b3, brow + (((unsigned)(nn * 32) + lext) ^ bsw));
                mma_bf16(acc[2 * nn], a0, a1, a2, a3, b0, b1);
                mma_bf16(acc[2 * nn + 1], a0, a1, a2, a3, b2, b3);
            }
        }
    }
    __syncthreads();

    float* stg = (float*)smc;       // [128][68]
    int r0 = row0 + m0 + g, r1 = r0 + 8;
    float dv0 = g_deg[r0], dv1 = g_deg[r1];
    #pragma unroll
    for (int s = 0; s < 8; s++) {
        int col = s * 8 + tig * 2;
        float2 p0 = make_float2(acc[s][0] * dv0, acc[s][1] * dv0);
        float2 p1 = make_float2(acc[s][2] * dv1, acc[s][3] * dv1);
        *(float2*)&stg[(m0 + g) * 68 + col] = p0;
        *(float2*)&stg[(m0 + g + 8) * 68 + col] = p1;
    }
    __syncthreads();
    float4* o4 = (float4*)hs;
    #pragma unroll
    for (int jj = 0; jj < 8; jj++) {
        int idx = jj * 256 + tid;
        int mm = idx >> 4, q = idx & 15;
        o4[(long)(row0 + mm) * 16 + q] = *(const float4*)&stg[mm * 68 + q * 4];
    }
}

// ---------------- sorted gather aggregation (atomic-free) ----------------
__global__ void gather_agg_kernel(const float* __restrict__ hs, const float* __restrict__ bias,
                                  float* __restrict__ agg) {
    int tid = threadIdx.x;              // 256
    int r = blockIdx.x * 16 + (tid >> 4);
    int q = tid & 15;
    int off = __ldg(&g_off[r]);
    int cnt = __ldg(&g_hist[r]);
    float dv = g_deg[r];
    const float4* h4 = (const float4*)hs;

    float4 acc = __ldg(&h4[(long)r * 16 + q]);
    int i = 0;
    for (; i + 2 <= cnt; i += 2) {
        int s0 = __ldg(&g_srcs[off + i]);
        int s1 = __ldg(&g_srcs[off + i + 1]);
        float4 v0 = __ldg(&h4[(long)s0 * 16 + q]);
        float4 v1 = __ldg(&h4[(long)s1 * 16 + q]);
        acc.x += v0.x + v1.x; acc.y += v0.y + v1.y;
        acc.z += v0.z + v1.z; acc.w += v0.w + v1.w;
    }
    if (i < cnt) {
        int s0 = __ldg(&g_srcs[off + i]);
        float4 v0 = __ldg(&h4[(long)s0 * 16 + q]);
        acc.x += v0.x; acc.y += v0.y; acc.z += v0.z; acc.w += v0.w;
    }
    float4 b = __ldg(&((const float4*)bias)[q]);
    float4 o = make_float4(fmaf(acc.x, dv, b.x), fmaf(acc.y, dv, b.y),
                           fmaf(acc.z, dv, b.z), fmaf(acc.w, dv, b.w));
    ((float4*)agg)[(long)r * 16 + q] = o;
}

// ---------------- temporal (1,3) conv via mma.sync (proven) ----------------
#define TM_A_HI 0
#define TM_A_LO 18432
#define TM_B    36864
#define TM_BIAS 86016
#define TM_PART 86272
#define TM_SMEM 88320

__global__ void __launch_bounds__(256, 2)
tconv_mma_kernel(const float* __restrict__ in, const __nv_bfloat16* __restrict__ wt,
                 const float* __restrict__ tb, float* __restrict__ out, int statOff) {
    extern __shared__ char smc[];
    unsigned sb = smem_u32(smc);
    int tid = threadIdx.x;
    int wid = tid >> 5;
    int lane = tid & 31;
    int p = blockIdx.x;
    int b = p >> 3;
    int mt = p & 7;

    for (int i = tid; i < 3072; i += 256)
        ((float4*)(smc + TM_B))[i] = ((const float4*)wt)[i];
    if (tid < 64) ((float*)(smc + TM_BIAS))[tid] = tb[tid];

    const float4* in4 = (const float4*)in;
    for (int i = tid; i < 2304; i += 256) {
        int y = i >> 4, q = i & 15;
        int rr = mt * 128 + y - 8;
        float4 v = make_float4(0.f, 0.f, 0.f, 0.f);
        if (rr >= 0 && rr < 1024) v = in4[(long)(b * 1024 + rr) * 16 + q];
        int off = y * 128 + q * 8;
        int sw = off ^ ((off >> 3) & 0x70);
        split_store(smc + TM_A_HI, smc + TM_A_LO, sw, v);
    }
    __syncthreads();

    int g = lane >> 2, tig = lane & 3;
    int m0 = wid * 16;
    int arow = lane & 15;
    int lext = (lane >> 4) << 4;

    float acc[8][4];
    #pragma unroll
    for (int s = 0; s < 8; s++)
        #pragma unroll
        for (int j = 0; j < 4; j++) acc[s][j] = 0.f;

    #pragma unroll 1
    for (int tap = 0; tap < 3; tap++) {
        #pragma unroll 1
        for (int pass = 0; pass < 3; pass++) {
            unsigned abase = sb + ((pass == 2) ? TM_A_LO : TM_A_HI);
            unsigned btile = sb + TM_B + (unsigned)(tap * 2 + (pass == 1)) * 8192u;
            int ay = tap * 8 + m0 + arow;
            unsigned arowbase = abase + (unsigned)(ay * 128);
            unsigned asw = (unsigned)((ay & 7) << 4);
            #pragma unroll
            for (int k16 = 0; k16 < 4; k16++) {
                unsigned a0, a1, a2, a3;
                ldsm4(a0, a1, a2, a3, arowbase + (((unsigned)(k16 * 32) + lext) ^ asw));
                int krow = k16 * 16 + arow;
                unsigned brow = btile + (unsigned)(krow * 128);
                unsigned bsw = (unsigned)((krow & 7) << 4);
                #pragma unroll
                for (int nn = 0; nn < 4; nn++) {
                    unsigned b0, b1, b2, b3;
                    ldsm4t(b0, b1, b2, b3, brow + (((unsigned)(nn * 32) + lext) ^ bsw));
                    mma_bf16(acc[2 * nn], a0, a1, a2, a3, b0, b1);
                    mma_bf16(acc[2 * nn + 1], a0, a1, a2, a3, b2, b3);
                }
            }
        }
    }
    __syncthreads();

    float* stg = (float*)smc;
    const float* biasS = (const float*)(smc + TM_BIAS);
    #pragma unroll
    for (int s = 0; s < 8; s++) {
        int col = s * 8 + tig * 2;
        float b0v = biasS[col], b1v = biasS[col + 1];
        int r0 = m0 + g, r1 = m0 + g + 8;
        stg[r0 * 68 + col]     = acc[s][0] + b0v;
        stg[r0 * 68 + col + 1] = acc[s][1] + b1v;
        stg[r1 * 68 + col]     = acc[s][2] + b0v;
        stg[r1 * 68 + col + 1] = acc[s][3] + b1v;
    }
    __syncthreads();

    {
        int g2 = tid >> 6, c2 = tid & 63;
        float s = 0.f, qq = 0.f;
        #pragma unroll 8
        for (int i2 = 0; i2 < 32; i2++) {
            float v = stg[(g2 * 32 + i2) * 68 + c2];
            s += v; qq = fmaf(v, v, qq);
        }
        float* ps = (float*)(smc + TM_PART);
        ps[g2 * 64 + c2] = s;
        ps[256 + g2 * 64 + c2] = qq;
    }
    __syncthreads();
    {
        const float* ps = (const float*)(smc + TM_PART);
        if (tid < 64)
            atomicAdd(&g_stats[statOff + tid], ps[tid] + ps[64 + tid] + ps[128 + tid] + ps[192 + tid]);
        else if (tid < 128) {
            int c = tid - 64;
            atomicAdd(&g_stats[statOff + 64 + c],
                      ps[256 + c] + ps[320 + c] + ps[384 + c] + ps[448 + c]);
        }
    }

    float4* out4 = (float4*)out;
    long rb16 = (long)(b * 1024 + mt * 128) * 16;
    #pragma unroll
    for (int jj = 0; jj < 8; jj++) {
        int idx = jj * 256 + tid;
        int mm = idx >> 4, q = idx & 15;
        out4[rb16 + mm * 16 + q] = *(const float4*)&stg[mm * 68 + q * 4];
    }
}

// ---------------- layer-1 epilogue fused with layer-2 GEMM ----------------
// Block = (b, n). Reads tconv-l1 output rows (b*128+t)*8+n; produces hs2 rows
// r2 = b*1024 + c2*16 + n*2 + th directly (with dinv applied).
#define F2_AH   0
#define F2_AL   16384
#define F2_OW   32768
#define F2_GW   49152
#define F2_STG  65536                      // [128][68] fp32 = 34816
#define F2_MISC (65536 + 34816)            // sc64, sh64, obs64, dv128 floats
#define F2_SMEM (F2_MISC + 1280)           // 101632

__global__ void __launch_bounds__(256, 2)
fused_gemm2_kernel(const float* __restrict__ tmp, const __nv_bfloat16* __restrict__ owt,
                   const __nv_bfloat16* __restrict__ gwt, const float* __restrict__ ob,
                   const float* __restrict__ gam, const float* __restrict__ beta,
                   float* __restrict__ hs2) {
    extern __shared__ char smc[];
    unsigned sb = smem_u32(smc);
    int tid = threadIdx.x;
    int wid = tid >> 5, lane = tid & 31;
    int p = blockIdx.x;                 // 1024
    int b = p >> 3, n = p & 7;

    float* scS = (float*)(smc + F2_MISC);
    float* shS = scS + 64;
    float* obsS = scS + 128;
    float* dvS = scS + 192;             // [128]
    float* stgF = (float*)(smc + F2_STG);

    if (tid < 64) {
        const float inv_cnt = 1.0f / 131072.0f;
        float mu = g_stats[tid] * inv_cnt;
        float var = g_stats[64 + tid] * inv_cnt - mu * mu;
        float scv = gam[tid] * rsqrtf(var + 1e-5f);
        scS[tid] = scv;
        shS[tid] = beta[tid] - mu * scv;
        obsS[tid] = ob[tid];
    }
    if (tid < 128)
        dvS[tid] = g_deg[b * 1024 + (tid >> 1) * 16 + n * 2 + (tid & 1)];
    for (int i = tid; i < 1024; i += 256) {
        ((float4*)(smc + F2_OW))[i] = ((const float4*)owt)[i];
        ((float4*)(smc + F2_GW))[i] = ((const float4*)gwt)[i];
    }
    __syncthreads();

    // A image: rows t (0..127), cols c; BN+relu applied, bf16 hi/lo split
    const float4* t4 = (const float4*)tmp;
    for (int i = tid; i < 2048; i += 256) {
        int y = i >> 4, q = i & 15;
        float4 v = t4[((long)(b * 128 + y) * 8 + n) * 16 + q];
        float4 sc4 = *(const float4*)&scS[q * 4];
        float4 sh4 = *(const float4*)&shS[q * 4];
        float4 r;
        r.x = fmaxf(0.f, fmaf(v.x, sc4.x, sh4.x));
        r.y = fmaxf(0.f, fmaf(v.y, sc4.y, sh4.y));
        r.z = fmaxf(0.f, fmaf(v.z, sc4.z, sh4.z));
        r.w = fmaxf(0.f, fmaf(v.w, sc4.w, sh4.w));
        int off = y * 128 + q * 8;
        int sw = off ^ ((off >> 3) & 0x70);
        split_store(smc + F2_AH, smc + F2_AL, sw, r);
    }
    __syncthreads();

    int g = lane >> 2, tig = lane & 3;
    int m0 = wid * 16;

    // GEMM1: y @ o1w^T -> acc over (t rows, c2 cols)
    float acc[8][4];
    #pragma unroll
    for (int s = 0; s < 8; s++)
        #pragma unroll
        for (int j = 0; j < 4; j++) acc[s][j] = 0.f;
    mma_3split_64(acc, sb, F2_AH, F2_AL, F2_OW, m0, lane);

    // epilogue1: v = tanh(acc + ob); stage to stgF[zr=2*c2+th][t'] (stride 68)
    int th = (m0 >= 64) ? 1 : 0;
    int tp0 = (m0 + g) & 63;            // t' for row m0+g; row m0+g+8 -> tp0+8
    #pragma unroll
    for (int s = 0; s < 8; s++) {
        int c2 = s * 8 + tig * 2;
        float o0 = obsS[c2], o1 = obsS[c2 + 1];
        stgF[(2 * c2 + th) * 68 + tp0]           = tanh_ap(acc[s][0] + o0);
        stgF[(2 * (c2 + 1) + th) * 68 + tp0]     = tanh_ap(acc[s][1] + o1);
        stgF[(2 * c2 + th) * 68 + tp0 + 8]       = tanh_ap(acc[s][2] + o0);
        stgF[(2 * (c2 + 1) + th) * 68 + tp0 + 8] = tanh_ap(acc[s][3] + o1);
    }
    __syncthreads();   // GEMM1 reads of A image done + stgF complete

    // rebuild A image = z tile [zr][t'] bf16 hi/lo (64 cols -> rows use first 128B half)
    for (int i = tid; i < 2048; i += 256) {
        int zr = i >> 4, q = i & 15;
        float4 v = *(const float4*)&stgF[zr * 68 + q * 4];
        int off = zr * 128 + q * 8;
        int sw = off ^ ((off >> 3) & 0x70);
        split_store(smc + F2_AH, smc + F2_AL, sw, v);
    }
    __syncthreads();

    // GEMM2: z @ gcn2_w
    float acc2[8][4];
    #pragma unroll
    for (int s = 0; s < 8; s++)
        #pragma unroll
        for (int j = 0; j < 4; j++) acc2[s][j] = 0.f;
    mma_3split_64(acc2, sb, F2_AH, F2_AL, F2_GW, m0, lane);
    __syncthreads();   // before reusing stgF

    // epilogue2: hs2 = acc2 * dinv, stage then coalesced store
    {
        int zr0 = m0 + g, zr1 = m0 + g + 8;
        float dv0 = dvS[zr0], dv1 = dvS[zr1];
        #pragma unroll
        for (int s = 0; s < 8; s++) {
            int col = s * 8 + tig * 2;
            *(float2*)&stgF[zr0 * 68 + col] = make_float2(acc2[s][0] * dv0, acc2[s][1] * dv0);
            *(float2*)&stgF[zr1 * 68 + col] = make_float2(acc2[s][2] * dv1, acc2[s][3] * dv1);
        }
    }
    __syncthreads();
    float4* o4 = (float4*)hs2;
    long base = (long)b * 1024 + n * 2;
    #pragma unroll
    for (int jj = 0; jj < 8; jj++) {
        int idx = jj * 256 + tid;
        int zr = idx >> 4, q = idx & 15;
        long r2 = base + (zr >> 1) * 16 + (zr & 1);
        o4[r2 * 16 + q] = *(const float4*)&stgF[zr * 68 + q * 4];
    }
}

// ---------------- layer-2 final: bn->relu->1x1->tanh->regression reduce ------------
#define FM_AH 0
#define FM_AL 16384
#define FM_W  32768
#define FM_MISC 49152
#define FM_SRED (FM_MISC + 768)
#define FM_SMEM 50176

__global__ void __launch_bounds__(256, 2)
fused_final_kernel(const float* __restrict__ tmp, const __nv_bfloat16* __restrict__ wt,
                   const float* __restrict__ ob, const float* __restrict__ gam,
                   const float* __restrict__ beta, float* __restrict__ z, int statOff) {
    extern __shared__ char smc[];
    unsigned sb = smem_u32(smc);
    int tid = threadIdx.x;
    int wid = tid >> 5, lane = tid & 31;
    int row0 = blockIdx.x * 128;

    float* scS = (float*)(smc + FM_MISC);
    float* shS = scS + 64;
    float* obsS = scS + 128;
    float* sred = (float*)(smc + FM_SRED);

    if (tid < 64) {
        const float inv_cnt = 1.0f / 131072.0f;
        float mu = g_stats[statOff + tid] * inv_cnt;
        float var = g_stats[statOff + 64 + tid] * inv_cnt - mu * mu;
        float scv = gam[tid] * rsqrtf(var + 1e-5f);
        scS[tid] = scv;
        shS[tid] = beta[tid] - mu * scv;
        obsS[tid] = ob[tid];
        sred[tid] = 0.f;
    }
    for (int i = tid; i < 1024; i += 256)
        ((float4*)(smc + FM_W))[i] = ((const float4*)wt)[i];
    __syncthreads();

    const float4* t4 = (const float4*)tmp;
    for (int i = tid; i < 2048; i += 256) {
        int y = i >> 4, q = i & 15;
        float4 v = t4[(long)(row0 + y) * 16 + q];
        float4 sc4 = *(const float4*)&scS[q * 4];
        float4 sh4 = *(const float4*)&shS[q * 4];
        float4 r;
        r.x = fmaxf(0.f, fmaf(v.x, sc4.x, sh4.x));
        r.y = fmaxf(0.f, fmaf(v.y, sc4.y, sh4.y));
        r.z = fmaxf(0.f, fmaf(v.z, sc4.z, sh4.z));
        r.w = fmaxf(0.f, fmaf(v.w, sc4.w, sh4.w));
        int off = y * 128 + q * 8;
        int sw = off ^ ((off >> 3) & 0x70);
        split_store(smc + FM_AH, smc + FM_AL, sw, r);
    }
    __syncthreads();

    int g = lane >> 2, tig = lane & 3;
    int m0 = wid * 16;

    float acc[8][4];
    #pragma unroll
    for (int s = 0; s < 8; s++)
        #pragma unroll
        for (int j = 0; j < 4; j++) acc[s][j] = 0.f;
    mma_3split_64(acc, sb, FM_AH, FM_AL, FM_W, m0, lane);

    int bq = row0 >> 10;
    int t0 = ((row0 + m0) >> 3) & 127;

    float w0 = g_wbar[t0 & 63] * 0.0078125f;
    float w1 = g_wbar[(t0 + 1) & 63] * 0.0078125f;
    float s0 = 0.f, s1 = 0.f;
    #pragma unroll
    for (int s = 0; s < 8; s++) {
        int c2 = s * 8 + tig * 2;
        float o0 = obsS[c2], o1 = obsS[c2 + 1];
        s0 += tanh_ap(acc[s][0] + o0) + tanh_ap(acc[s][1] + o1);
        s1 += tanh_ap(acc[s][2] + o0) + tanh_ap(acc[s][3] + o1);
    }
    float part = w0 * s0 + w1 * s1;
    part += __shfl_xor_sync(0xffffffffu, part, 1);
    part += __shfl_xor_sync(0xffffffffu, part, 2);
    part += __shfl_xor_sync(0xffffffffu, part, 16);
    int th = (t0 >> 6) & 1;
    if (tig == 0 && g < 4) {
        int idx = (2 * g + th) & 7;
        sred[idx * 8 + wid] = part;
    }
    __syncthreads();
    if (tid < 8) {
        float ssum = 0.f;
        #pragma unroll
        for (int w = 0; w < 8; w++) ssum += sred[tid * 8 + w];
        atomicAdd(&z[bq * 8 + tid], ssum);
    }
}

// ---------------- host launcher ----------------
extern "C" void kernel_launch(void* const* d_in, const int* in_sizes, int n_in,
                              void* d_out, int out_size) {
    const float* x      = (const float*)d_in[0];
    const int*   ei     = (const int*)d_in[1];
    const float* gcn1_w = (const float*)d_in[2];
    const float* gcn1_b = (const float*)d_in[3];
    const float* t1_w   = (const float*)d_in[4];
    const float* t1_b   = (const float*)d_in[5];
    const float* bn1_g  = (const float*)d_in[6];
    const float* bn1_b  = (const float*)d_in[7];
    const float* o1_w   = (const float*)d_in[8];
    const float* o1_b   = (const float*)d_in[9];
    const float* gcn2_w = (const float*)d_in[10];
    const float* gcn2_b = (const float*)d_in[11];
    const float* t2_w   = (const float*)d_in[12];
    const float* t2_b   = (const float*)d_in[13];
    const float* bn2_g  = (const float*)d_in[14];
    const float* bn2_b  = (const float*)d_in[15];
    const float* o2_w   = (const float*)d_in[16];
    const float* o2_b   = (const float*)d_in[17];
    const float* reg_w  = (const float*)d_in[18];
    const float* reg_b  = (const float*)d_in[19];
    float* out = (float*)d_out;

    const int* src = ei;
    const int* dst = ei + EDGES;

    cudaFuncSetAttribute(tconv_mma_kernel, cudaFuncAttributeMaxDynamicSharedMemorySize, TM_SMEM);
    cudaFuncSetAttribute(gemm_mma_kernel<32>, cudaFuncAttributeMaxDynamicSharedMemorySize, GM_SMEM);
    cudaFuncSetAttribute(fused_gemm2_kernel, cudaFuncAttributeMaxDynamicSharedMemorySize, F2_SMEM);
    cudaFuncSetAttribute(fused_final_kernel, cudaFuncAttributeMaxDynamicSharedMemorySize, FM_SMEM);

    float* bufA; cudaGetSymbolAddress((void**)&bufA, g_bufA);
    float* bufB; cudaGetSymbolAddress((void**)&bufB, g_bufB);
    float* bufC; cudaGetSymbolAddress((void**)&bufC, g_bufC);
    __nv_bfloat16* wt1; cudaGetSymbolAddress((void**)&wt1, g_wt1);
    __nv_bfloat16* wt2; cudaGetSymbolAddress((void**)&wt2, g_wt2);
    __nv_bfloat16* gw1; cudaGetSymbolAddress((void**)&gw1, g_gw1);
    __nv_bfloat16* gw2; cudaGetSymbolAddress((void**)&gw2, g_gw2);
    __nv_bfloat16* ow1; cudaGetSymbolAddress((void**)&ow1, g_ow1);
    __nv_bfloat16* ow2; cudaGetSymbolAddress((void**)&ow2, g_ow2);

    prologue_kernel<<<512, 256>>>(reg_w, reg_b, t1_w, t2_w, gcn1_w, gcn2_w, o1_w, o2_w);
    hist_kernel<<<EDGES / 256, 256>>>(dst);
    scan1_kernel<<<128, 256>>>();
    scan3_kernel<<<NROWS / 256, 256>>>(reg_b, out);
    scatter_kernel<<<EDGES / 256, 256>>>(src, dst);

    // -------- layer 1 --------
    gemm_mma_kernel<32><<<NROWS / 128, 256, GM_SMEM>>>(x, gw1, bufA);
    gather_agg_kernel<<<NROWS / 16, 256>>>(bufA, gcn1_b, bufB);
    tconv_mma_kernel<<<1024, 256, TM_SMEM>>>(bufB, wt1, t1_b, bufC, 0);
    // fused: bn1 -> relu -> 1x1(o1) -> tanh -> layer2 GEMM (gcn2_w) -> *dinv -> bufA
    fused_gemm2_kernel<<<1024, 256, F2_SMEM>>>(bufC, ow1, gw2, o1_b, bn1_g, bn1_b, bufA);

    // -------- layer 2 --------
    gather_agg_kernel<<<NROWS / 16, 256>>>(bufA, gcn2_b, bufB);
    tconv_mma_kernel<<<1024, 256, TM_SMEM>>>(bufB, wt2, t2_b, bufC, 128);
    fused_final_kernel<<<NROWS / 128, 256, FM_SMEM>>>(bufC, ow2, o2_b, bn2_g, bn2_b, out, 128);
}

// round 14
// speedup vs baseline: 2.6037x; 1.0759x over previous
#include <cuda_runtime.h>
#include <cuda_bf16.h>
#include <cstdint>
#include <stdint.h>
#include <math.h>

#define NROWS 131072
#define EDGES 1048576

// ---------------- scratch (device globals) ----------------
__device__ float g_bufA[NROWS * 64];
__device__ float g_bufB[NROWS * 64];
__device__ float g_bufC[NROWS * 64];
__device__ float g_deg[NROWS];      // dinv
__device__ int   g_hist[NROWS];
__device__ int   g_off[NROWS];
__device__ int   g_cursor[NROWS];
__device__ int   g_bsum[128];
__device__ int   g_srcs[EDGES];
__device__ float g_stats[256];
__device__ float g_wbar[65];
// bf16 weight tiles, XOR-swizzled 128B rows, hi tile then lo tile
__device__ __align__(16) __nv_bfloat16 g_wt1[24576];  // tconv l1: [tap*2+split][64x64]
__device__ __align__(16) __nv_bfloat16 g_wt2[24576];  // tconv l2
__device__ __align__(16) __nv_bfloat16 g_gw1[8192];   // gcn1_w [32k x 64n]
__device__ __align__(16) __nv_bfloat16 g_gw2[8192];   // gcn2_w [64k x 64n]
__device__ __align__(16) __nv_bfloat16 g_ow1[8192];   // o1_w^T [64c x 64c2]
__device__ __align__(16) __nv_bfloat16 g_ow2[8192];   // o2_w^T

typedef unsigned long long ull;
__device__ __forceinline__ float tanh_ap(float x) {
    float y; asm("tanh.approx.f32 %0,%1;" : "=f"(y) : "f"(x)); return y;
}

// ---------------- mma.sync helpers ----------------
__device__ __forceinline__ unsigned smem_u32(const void* p) {
    unsigned a;
    asm("{ .reg .u64 t; cvta.to.shared.u64 t, %1; cvt.u32.u64 %0, t; }" : "=r"(a) : "l"(p));
    return a;
}
__device__ __forceinline__ void ldsm4(unsigned& r0, unsigned& r1, unsigned& r2, unsigned& r3,
                                      unsigned addr) {
    asm volatile("ldmatrix.sync.aligned.m8n8.x4.shared.b16 {%0,%1,%2,%3}, [%4];"
                 : "=r"(r0), "=r"(r1), "=r"(r2), "=r"(r3) : "r"(addr));
}
__device__ __forceinline__ void ldsm4t(unsigned& r0, unsigned& r1, unsigned& r2, unsigned& r3,
                                       unsigned addr) {
    asm volatile("ldmatrix.sync.aligned.m8n8.x4.trans.shared.b16 {%0,%1,%2,%3}, [%4];"
                 : "=r"(r0), "=r"(r1), "=r"(r2), "=r"(r3) : "r"(addr));
}
__device__ __forceinline__ void mma_bf16(float* c, unsigned a0, unsigned a1, unsigned a2,
                                         unsigned a3, unsigned b0, unsigned b1) {
    asm volatile(
        "mma.sync.aligned.m16n8k16.row.col.f32.bf16.bf16.f32 "
        "{%0,%1,%2,%3}, {%4,%5,%6,%7}, {%8,%9}, {%0,%1,%2,%3};"
        : "+f"(c[0]), "+f"(c[1]), "+f"(c[2]), "+f"(c[3])
        : "r"(a0), "r"(a1), "r"(a2), "r"(a3), "r"(b0), "r"(b1));
}
__device__ __forceinline__ void split_store(char* hi, char* lo, int sw, float4 v) {
    __nv_bfloat162 h01 = __floats2bfloat162_rn(v.x, v.y);
    __nv_bfloat162 h23 = __floats2bfloat162_rn(v.z, v.w);
    float lx = v.x - __bfloat162float(h01.x);
    float ly = v.y - __bfloat162float(h01.y);
    float lz = v.z - __bfloat162float(h23.x);
    float lw = v.w - __bfloat162float(h23.y);
    __nv_bfloat162 l01 = __floats2bfloat162_rn(lx, ly);
    __nv_bfloat162 l23 = __floats2bfloat162_rn(lz, lw);
    uint2 hp, lp;
    hp.x = *(unsigned*)&h01; hp.y = *(unsigned*)&h23;
    lp.x = *(unsigned*)&l01; lp.y = *(unsigned*)&l23;
    *(uint2*)(hi + sw) = hp;
    *(uint2*)(lo + sw) = lp;
}
__device__ __forceinline__ void split_store1(char* hi, char* lo, int sw, float v) {
    __nv_bfloat16 h = __float2bfloat16_rn(v);
    __nv_bfloat16 l = __float2bfloat16_rn(v - __bfloat162float(h));
    *(__nv_bfloat16*)(hi + sw) = h;
    *(__nv_bfloat16*)(lo + sw) = l;
}

// one k16 step of the 3-term bf16 split GEMM: Ah*Bh + Ah*Bl + Al*Bh
// loads A(hi,lo) once and B(hi,lo) once, issues 6 MMAs per nn.
__device__ __forceinline__ void mma_3split_k16(float acc[8][4], unsigned ahRow, unsigned alRow,
                                               unsigned asw, unsigned bhTile, unsigned blTile,
                                               int k16, int arow, int lext) {
    unsigned a0, a1, a2, a3, c0, c1, c2, c3;
    unsigned kb = (((unsigned)(k16 * 32)) + lext) ^ asw;
    ldsm4(a0, a1, a2, a3, ahRow + kb);
    ldsm4(c0, c1, c2, c3, alRow + kb);
    int krow = k16 * 16 + arow;
    unsigned bro = (unsigned)(krow * 128);
    unsigned bsw = (unsigned)((krow & 7) << 4);
    #pragma unroll
    for (int nn = 0; nn < 4; nn++) {
        unsigned b0, b1, b2, b3, d0, d1, d2, d3;
        unsigned nb = (((unsigned)(nn * 32)) + lext) ^ bsw;
        ldsm4t(b0, b1, b2, b3, bhTile + bro + nb);
        ldsm4t(d0, d1, d2, d3, blTile + bro + nb);
        mma_bf16(acc[2 * nn],     a0, a1, a2, a3, b0, b1);
        mma_bf16(acc[2 * nn + 1], a0, a1, a2, a3, b2, b3);
        mma_bf16(acc[2 * nn],     a0, a1, a2, a3, d0, d1);
        mma_bf16(acc[2 * nn + 1], a0, a1, a2, a3, d2, d3);
        mma_bf16(acc[2 * nn],     c0, c1, c2, c3, b0, b1);
        mma_bf16(acc[2 * nn + 1], c0, c1, c2, c3, b2, b3);
    }
}

// full K=64 sweep
__device__ __forceinline__ void mma_3split_64(float acc[8][4], unsigned sb, unsigned ahOff,
                                              unsigned alOff, unsigned wOff, int m0, int lane) {
    int arow = lane & 15;
    int lext = (lane >> 4) << 4;
    int ay = m0 + arow;
    unsigned ahRow = sb + ahOff + (unsigned)(ay * 128);
    unsigned alRow = sb + alOff + (unsigned)(ay * 128);
    unsigned asw = (unsigned)((ay & 7) << 4);
    #pragma unroll
    for (int k16 = 0; k16 < 4; k16++)
        mma_3split_k16(acc, ahRow, alRow, asw, sb + wOff, sb + wOff + 8192u, k16, arow, lext);
}

// ---------------- prologue ----------------
__global__ void prologue_kernel(const float* __restrict__ rw, const float* __restrict__ rb,
                                const float* __restrict__ t1w, const float* __restrict__ t2w,
                                const float* __restrict__ g1w, const float* __restrict__ g2w,
                                const float* __restrict__ o1w, const float* __restrict__ o2w) {
    int i = blockIdx.x * blockDim.x + threadIdx.x;
    if (i < NROWS) g_hist[i] = 0;
    if (i < 256) g_stats[i] = 0.0f;
    if (i < 12288) {
        int k = i >> 12;
        int r = i & 4095;
        int c2 = r >> 6, c = r & 63;
        int off = c * 128 + c2 * 2;
        int sw = off ^ ((off >> 3) & 0x70);
        int idx = sw >> 1;
        float w1 = t1w[(c2 * 64 + c) * 3 + k];
        float w2 = t2w[(c2 * 64 + c) * 3 + k];
        __nv_bfloat16 h1 = __float2bfloat16_rn(w1);
        __nv_bfloat16 h2 = __float2bfloat16_rn(w2);
        g_wt1[(k * 2 + 0) * 4096 + idx] = h1;
        g_wt1[(k * 2 + 1) * 4096 + idx] = __float2bfloat16_rn(w1 - __bfloat162float(h1));
        g_wt2[(k * 2 + 0) * 4096 + idx] = h2;
        g_wt2[(k * 2 + 1) * 4096 + idx] = __float2bfloat16_rn(w2 - __bfloat162float(h2));
    } else if (i < 16384) {
        int j = i - 12288;
        int k = j >> 6, n = j & 63;
        int off = k * 128 + n * 2;
        int sw = off ^ ((off >> 3) & 0x70);
        int idx = sw >> 1;
        float w = g2w[k * 64 + n];
        __nv_bfloat16 h = __float2bfloat16_rn(w);
        g_gw2[idx] = h;
        g_gw2[4096 + idx] = __float2bfloat16_rn(w - __bfloat162float(h));
    } else if (i < 20480) {
        int j = i - 16384;
        int c = j >> 6, c2 = j & 63;
        int off = c * 128 + c2 * 2;
        int sw = off ^ ((off >> 3) & 0x70);
        int idx = sw >> 1;
        float w = o1w[c2 * 64 + c];
        __nv_bfloat16 h = __float2bfloat16_rn(w);
        g_ow1[idx] = h;
        g_ow1[4096 + idx] = __float2bfloat16_rn(w - __bfloat162float(h));
    } else if (i < 24576) {
        int j = i - 20480;
        int c = j >> 6, c2 = j & 63;
        int off = c * 128 + c2 * 2;
        int sw = off ^ ((off >> 3) & 0x70);
        int idx = sw >> 1;
        float w = o2w[c2 * 64 + c];
        __nv_bfloat16 h = __float2bfloat16_rn(w);
        g_ow2[idx] = h;
        g_ow2[4096 + idx] = __float2bfloat16_rn(w - __bfloat162float(h));
    } else if (i < 26624) {
        int j = i - 24576;
        int k = j >> 6, n = j & 63;
        int off = k * 128 + n * 2;
        int sw = off ^ ((off >> 3) & 0x70);
        int idx = sw >> 1;
        float w = g1w[k * 64 + n];
        __nv_bfloat16 h = __float2bfloat16_rn(w);
        g_gw1[idx] = h;
        g_gw1[4096 + idx] = __float2bfloat16_rn(w - __bfloat162float(h));
    }
    if (i < 64) {
        float s = 0.f;
        #pragma unroll
        for (int j = 0; j < 8; j++) s += rw[i * 8 + j];
        g_wbar[i] = s * 0.125f;
    }
    if (i == 64) {
        float s = 0.f;
        #pragma unroll
        for (int j = 0; j < 8; j++) s += rb[j];
        g_wbar[64] = s * 0.125f;
    }
}

__global__ void hist_kernel(const int* __restrict__ dst) {
    int e = blockIdx.x * blockDim.x + threadIdx.x;
    if (e < EDGES) atomicAdd(&g_hist[dst[e]], 1);
}

__global__ void scan1_kernel() {
    __shared__ int sh[256];
    int tid = threadIdx.x;
    int base = blockIdx.x * 1024 + tid * 4;
    int4 v = *(const int4*)&g_hist[base];
    int s0 = v.x, s1 = s0 + v.y, s2 = s1 + v.z, s3 = s2 + v.w;
    sh[tid] = s3;
    __syncthreads();
    #pragma unroll
    for (int o = 1; o < 256; o <<= 1) {
        int t = (tid >= o) ? sh[tid - o] : 0;
        __syncthreads();
        sh[tid] += t;
        __syncthreads();
    }
    int excl = tid ? sh[tid - 1] : 0;
    int4 w = make_int4(excl, excl + s0, excl + s1, excl + s2);
    *(int4*)&g_off[base] = w;
    if (tid == 255) g_bsum[blockIdx.x] = sh[255];
}

// scan3: local re-scan of the 128 segment sums + dinv/cursor/out-init
__global__ void scan3_kernel(const float* __restrict__ rb, float* __restrict__ out) {
    __shared__ int bs[128];
    int tid = threadIdx.x;
    if (tid < 128) bs[tid] = g_bsum[tid];
    __syncthreads();
    #pragma unroll
    for (int o = 1; o < 128; o <<= 1) {
        int t = (tid < 128 && tid >= o) ? bs[tid - o] : 0;
        __syncthreads();
        if (tid < 128) bs[tid] += t;
        __syncthreads();
    }
    int i = blockIdx.x * blockDim.x + tid;
    if (i < NROWS) {
        int seg = i >> 10;
        int o = g_off[i] + (seg ? bs[seg - 1] : 0);
        g_off[i] = o;
        g_cursor[i] = o;
        g_deg[i] = rsqrtf((float)g_hist[i] + 1.0f);
    }
    if (i < 1024) {
        float s = 0.f;
        #pragma unroll
        for (int j = 0; j < 8; j++) s += rb[j];
        out[i] = s * 0.125f;
    }
}

__global__ void scatter_kernel(const int* __restrict__ src, const int* __restrict__ dst) {
    int e = blockIdx.x * blockDim.x + threadIdx.x;
    if (e < EDGES) {
        int d = dst[e];
        int pos = atomicAdd(&g_cursor[d], 1);
        g_srcs[pos] = src[e];
    }
}

// ---------------- GEMM hs = (A@W)*dinv via mma.sync (layer 1 input) ----------------
#define GM_AH 0
#define GM_AL 16384
#define GM_W  32768
#define GM_SMEM 49152

template <int K>
__global__ void __launch_bounds__(256, 2)
gemm_mma_kernel(const float* __restrict__ A, const __nv_bfloat16* __restrict__ wt,
                float* __restrict__ hs) {
    extern __shared__ char smc[];
    unsigned sb = smem_u32(smc);
    int tid = threadIdx.x;
    int wid = tid >> 5, lane = tid & 31;
    int row0 = blockIdx.x * 128;

    for (int i = tid; i < 1024; i += 256)
        ((float4*)(smc + GM_W))[i] = ((const float4*)wt)[i];

    constexpr int QR = K / 4;
    const float4* a4 = (const float4*)A;
    for (int i = tid; i < 128 * QR; i += 256) {
        int y = i / QR, q = i - y * QR;
        float4 v = a4[(long)(row0 + y) * QR + q];
        int off = y * 128 + q * 8;
        int sw = off ^ ((off >> 3) & 0x70);
        split_store(smc + GM_AH, smc + GM_AL, sw, v);
    }
    __syncthreads();

    int g = lane >> 2, tig = lane & 3;
    int m0 = wid * 16;
    int arow = lane & 15;
    int lext = (lane >> 4) << 4;

    float acc[8][4];
    #pragma unroll
    for (int s = 0; s < 8; s++)
        #pragma unroll
        for (int j = 0; j < 4; j++) acc[s][j] = 0.f;

    {
        int ay = m0 + arow;
        unsigned ahRow = sb + GM_AH + (unsigned)(ay * 128);
        unsigned alRow = sb + GM_AL + (unsigned)(ay * 128);
        unsigned asw = (unsigned)((ay & 7) << 4);
        #pragma unroll
        for (int k16 = 0; k16 < K / 16; k16++)
            mma_3split_k16(acc, ahRow, alRow, asw, sb + GM_W, sb + GM_W + 8192u,
                           k16, arow, lext);
    }
    __syncthreads();

    float* stg = (float*)smc;       // [128][68]
    int r0 = row0 + m0 + g, r1 = r0 + 8;
    float dv0 = g_deg[r0], dv1 = g_deg[r1];
    #pragma unroll
    for (int s = 0; s < 8; s++) {
        int col = s * 8 + tig * 2;
        float2 p0 = make_float2(acc[s][0] * dv0, acc[s][1] * dv0);
        float2 p1 = make_float2(acc[s][2] * dv1, acc[s][3] * dv1);
        *(float2*)&stg[(m0 + g) * 68 + col] = p0;
        *(float2*)&stg[(m0 + g + 8) * 68 + col] = p1;
    }
    __syncthreads();
    float4* o4 = (float4*)hs;
    #pragma unroll
    for (int jj = 0; jj < 8; jj++) {
        int idx = jj * 256 + tid;
        int mm = idx >> 4, q = idx & 15;
        o4[(long)(row0 + mm) * 16 + q] = *(const float4*)&stg[mm * 68 + q * 4];
    }
}

// ---------------- sorted gather aggregation (atomic-free) ----------------
__global__ void gather_agg_kernel(const float* __restrict__ hs, const float* __restrict__ bias,
                                  float* __restrict__ agg) {
    int tid = threadIdx.x;              // 256
    int r = blockIdx.x * 16 + (tid >> 4);
    int q = tid & 15;
    int off = __ldg(&g_off[r]);
    int cnt = __ldg(&g_hist[r]);
    float dv = g_deg[r];
    const float4* h4 = (const float4*)hs;

    float4 acc = __ldg(&h4[(long)r * 16 + q]);
    int i = 0;
    for (; i + 2 <= cnt; i += 2) {
        int s0 = __ldg(&g_srcs[off + i]);
        int s1 = __ldg(&g_srcs[off + i + 1]);
        float4 v0 = __ldg(&h4[(long)s0 * 16 + q]);
        float4 v1 = __ldg(&h4[(long)s1 * 16 + q]);
        acc.x += v0.x + v1.x; acc.y += v0.y + v1.y;
        acc.z += v0.z + v1.z; acc.w += v0.w + v1.w;
    }
    if (i < cnt) {
        int s0 = __ldg(&g_srcs[off + i]);
        float4 v0 = __ldg(&h4[(long)s0 * 16 + q]);
        acc.x += v0.x; acc.y += v0.y; acc.z += v0.z; acc.w += v0.w;
    }
    float4 b = __ldg(&((const float4*)bias)[q]);
    float4 o = make_float4(fmaf(acc.x, dv, b.x), fmaf(acc.y, dv, b.y),
                           fmaf(acc.z, dv, b.z), fmaf(acc.w, dv, b.w));
    ((float4*)agg)[(long)r * 16 + q] = o;
}

// ---------------- temporal (1,3) conv via mma.sync ----------------
#define TM_A_HI 0
#define TM_A_LO 18432
#define TM_B    36864
#define TM_BIAS 86016
#define TM_PART 86272
#define TM_SMEM 88320

__global__ void __launch_bounds__(256, 2)
tconv_mma_kernel(const float* __restrict__ in, const __nv_bfloat16* __restrict__ wt,
                 const float* __restrict__ tb, float* __restrict__ out, int statOff) {
    extern __shared__ char smc[];
    unsigned sb = smem_u32(smc);
    int tid = threadIdx.x;
    int wid = tid >> 5;
    int lane = tid & 31;
    int p = blockIdx.x;
    int b = p >> 3;
    int mt = p & 7;

    for (int i = tid; i < 3072; i += 256)
        ((float4*)(smc + TM_B))[i] = ((const float4*)wt)[i];
    if (tid < 64) ((float*)(smc + TM_BIAS))[tid] = tb[tid];

    const float4* in4 = (const float4*)in;
    for (int i = tid; i < 2304; i += 256) {
        int y = i >> 4, q = i & 15;
        int rr = mt * 128 + y - 8;
        float4 v = make_float4(0.f, 0.f, 0.f, 0.f);
        if (rr >= 0 && rr < 1024) v = in4[(long)(b * 1024 + rr) * 16 + q];
        int off = y * 128 + q * 8;
        int sw = off ^ ((off >> 3) & 0x70);
        split_store(smc + TM_A_HI, smc + TM_A_LO, sw, v);
    }
    __syncthreads();

    int g = lane >> 2, tig = lane & 3;
    int m0 = wid * 16;
    int arow = lane & 15;
    int lext = (lane >> 4) << 4;

    float acc[8][4];
    #pragma unroll
    for (int s = 0; s < 8; s++)
        #pragma unroll
        for (int j = 0; j < 4; j++) acc[s][j] = 0.f;

    #pragma unroll 1
    for (int tap = 0; tap < 3; tap++) {
        int ay = tap * 8 + m0 + arow;
        unsigned ahRow = sb + TM_A_HI + (unsigned)(ay * 128);
        unsigned alRow = sb + TM_A_LO + (unsigned)(ay * 128);
        unsigned asw = (unsigned)((ay & 7) << 4);
        unsigned bh = sb + TM_B + (unsigned)(tap * 2) * 8192u;
        #pragma unroll
        for (int k16 = 0; k16 < 4; k16++)
            mma_3split_k16(acc, ahRow, alRow, asw, bh, bh + 8192u, k16, arow, lext);
    }
    __syncthreads();

    float* stg = (float*)smc;
    const float* biasS = (const float*)(smc + TM_BIAS);
    #pragma unroll
    for (int s = 0; s < 8; s++) {
        int col = s * 8 + tig * 2;
        float b0v = biasS[col], b1v = biasS[col + 1];
        int r0 = m0 + g, r1 = m0 + g + 8;
        stg[r0 * 68 + col]     = acc[s][0] + b0v;
        stg[r0 * 68 + col + 1] = acc[s][1] + b1v;
        stg[r1 * 68 + col]     = acc[s][2] + b0v;
        stg[r1 * 68 + col + 1] = acc[s][3] + b1v;
    }
    __syncthreads();

    {
        int g2 = tid >> 6, c2 = tid & 63;
        float s = 0.f, qq = 0.f;
        #pragma unroll 8
        for (int i2 = 0; i2 < 32; i2++) {
            float v = stg[(g2 * 32 + i2) * 68 + c2];
            s += v; qq = fmaf(v, v, qq);
        }
        float* ps = (float*)(smc + TM_PART);
        ps[g2 * 64 + c2] = s;
        ps[256 + g2 * 64 + c2] = qq;
    }
    __syncthreads();
    {
        const float* ps = (const float*)(smc + TM_PART);
        if (tid < 64)
            atomicAdd(&g_stats[statOff + tid], ps[tid] + ps[64 + tid] + ps[128 + tid] + ps[192 + tid]);
        else if (tid < 128) {
            int c = tid - 64;
            atomicAdd(&g_stats[statOff + 64 + c],
                      ps[256 + c] + ps[320 + c] + ps[384 + c] + ps[448 + c]);
        }
    }

    float4* out4 = (float4*)out;
    long rb16 = (long)(b * 1024 + mt * 128) * 16;
    #pragma unroll
    for (int jj = 0; jj < 8; jj++) {
        int idx = jj * 256 + tid;
        int mm = idx >> 4, q = idx & 15;
        out4[rb16 + mm * 16 + q] = *(const float4*)&stg[mm * 68 + q * 4];
    }
}

// ---------------- layer-1 epilogue fused with layer-2 GEMM ----------------
// Block = (b, n). z written directly into the bf16 A-image (no fp32 staging).
#define F2_AH   0
#define F2_AL   16384
#define F2_OW   32768
#define F2_GW   49152
#define F2_MISC 65536                      // sc64, sh64, obs64, dv128 floats
#define F2_SMEM (F2_MISC + 1280)           // 66816

__global__ void __launch_bounds__(256, 2)
fused_gemm2_kernel(const float* __restrict__ tmp, const __nv_bfloat16* __restrict__ owt,
                   const __nv_bfloat16* __restrict__ gwt, const float* __restrict__ ob,
                   const float* __restrict__ gam, const float* __restrict__ beta,
                   float* __restrict__ hs2) {
    extern __shared__ char smc[];
    unsigned sb = smem_u32(smc);
    int tid = threadIdx.x;
    int wid = tid >> 5, lane = tid & 31;
    int p = blockIdx.x;                 // 1024
    int b = p >> 3, n = p & 7;

    float* scS = (float*)(smc + F2_MISC);
    float* shS = scS + 64;
    float* obsS = scS + 128;
    float* dvS = scS + 192;             // [128]

    if (tid < 64) {
        const float inv_cnt = 1.0f / 131072.0f;
        float mu = g_stats[tid] * inv_cnt;
        float var = g_stats[64 + tid] * inv_cnt - mu * mu;
        float scv = gam[tid] * rsqrtf(var + 1e-5f);
        scS[tid] = scv;
        shS[tid] = beta[tid] - mu * scv;
        obsS[tid] = ob[tid];
    }
    if (tid < 128)
        dvS[tid] = g_deg[b * 1024 + (tid >> 1) * 16 + n * 2 + (tid & 1)];
    for (int i = tid; i < 1024; i += 256) {
        ((float4*)(smc + F2_OW))[i] = ((const float4*)owt)[i];
        ((float4*)(smc + F2_GW))[i] = ((const float4*)gwt)[i];
    }
    __syncthreads();

    // A image: rows t (0..127), cols c; BN+relu applied, bf16 hi/lo split
    const float4* t4 = (const float4*)tmp;
    for (int i = tid; i < 2048; i += 256) {
        int y = i >> 4, q = i & 15;
        float4 v = t4[((long)(b * 128 + y) * 8 + n) * 16 + q];
        float4 sc4 = *(const float4*)&scS[q * 4];
        float4 sh4 = *(const float4*)&shS[q * 4];
        float4 r;
        r.x = fmaxf(0.f, fmaf(v.x, sc4.x, sh4.x));
        r.y = fmaxf(0.f, fmaf(v.y, sc4.y, sh4.y));
        r.z = fmaxf(0.f, fmaf(v.z, sc4.z, sh4.z));
        r.w = fmaxf(0.f, fmaf(v.w, sc4.w, sh4.w));
        int off = y * 128 + q * 8;
        int sw = off ^ ((off >> 3) & 0x70);
        split_store(smc + F2_AH, smc + F2_AL, sw, r);
    }
    __syncthreads();

    int g = lane >> 2, tig = lane & 3;
    int m0 = wid * 16;

    // GEMM1: y @ o1w^T
    float acc[8][4];
    #pragma unroll
    for (int s = 0; s < 8; s++)
        #pragma unroll
        for (int j = 0; j < 4; j++) acc[s][j] = 0.f;
    mma_3split_64(acc, sb, F2_AH, F2_AL, F2_OW, m0, lane);
    __syncthreads();   // all GEMM1 reads of A image done before overwrite

    // epilogue1: z = tanh(acc + ob) written DIRECTLY into bf16 A image at (zr, t')
    int th = (m0 >= 64) ? 1 : 0;
    int tp0 = (m0 + g) & 63;
    #pragma unroll
    for (int s = 0; s < 8; s++) {
        int c2 = s * 8 + tig * 2;
        float o0 = obsS[c2], o1 = obsS[c2 + 1];
        int zr0 = 2 * c2 + th, zr1 = 2 * (c2 + 1) + th;
        float v00 = tanh_ap(acc[s][0] + o0);
        float v01 = tanh_ap(acc[s][1] + o1);
        float v10 = tanh_ap(acc[s][2] + o0);
        float v11 = tanh_ap(acc[s][3] + o1);
        int o00 = zr0 * 128 + tp0 * 2;       o00 ^= ((o00 >> 3) & 0x70);
        int o01 = zr1 * 128 + tp0 * 2;       o01 ^= ((o01 >> 3) & 0x70);
        int o10 = zr0 * 128 + (tp0 + 8) * 2; o10 ^= ((o10 >> 3) & 0x70);
        int o11 = zr1 * 128 + (tp0 + 8) * 2; o11 ^= ((o11 >> 3) & 0x70);
        split_store1(smc + F2_AH, smc + F2_AL, o00, v00);
        split_store1(smc + F2_AH, smc + F2_AL, o01, v01);
        split_store1(smc + F2_AH, smc + F2_AL, o10, v10);
        split_store1(smc + F2_AH, smc + F2_AL, o11, v11);
    }
    __syncthreads();

    // GEMM2: z @ gcn2_w
    float acc2[8][4];
    #pragma unroll
    for (int s = 0; s < 8; s++)
        #pragma unroll
        for (int j = 0; j < 4; j++) acc2[s][j] = 0.f;
    mma_3split_64(acc2, sb, F2_AH, F2_AL, F2_GW, m0, lane);
    __syncthreads();   // before reusing smem for staging

    // epilogue2: hs2 = acc2 * dinv, stage (stride 68) in now-dead region then store
    float* stgF = (float*)smc;          // 34816 B over AH/AL/part of OW (all dead)
    {
        int zr0 = m0 + g, zr1 = m0 + g + 8;
        float dv0 = dvS[zr0], dv1 = dvS[zr1];
        #pragma unroll
        for (int s = 0; s < 8; s++) {
            int col = s * 8 + tig * 2;
            *(float2*)&stgF[zr0 * 68 + col] = make_float2(acc2[s][0] * dv0, acc2[s][1] * dv0);
            *(float2*)&stgF[zr1 * 68 + col] = make_float2(acc2[s][2] * dv1, acc2[s][3] * dv1);
        }
    }
    __syncthreads();
    float4* o4 = (float4*)hs2;
    long base = (long)b * 1024 + n * 2;
    #pragma unroll
    for (int jj = 0; jj < 8; jj++) {
        int idx = jj * 256 + tid;
        int zr = idx >> 4, q = idx & 15;
        long r2 = base + (zr >> 1) * 16 + (zr & 1);
        o4[r2 * 16 + q] = *(const float4*)&stgF[zr * 68 + q * 4];
    }
}

// ---------------- layer-2 final: bn->relu->1x1->tanh->regression reduce ------------
#define FM_AH 0
#define FM_AL 16384
#define FM_W  32768
#define FM_MISC 49152
#define FM_SRED (FM_MISC + 768)
#define FM_SMEM 50176

__global__ void __launch_bounds__(256, 2)
fused_final_kernel(const float* __restrict__ tmp, const __nv_bfloat16* __restrict__ wt,
                   const float* __restrict__ ob, const float* __restrict__ gam,
                   const float* __restrict__ beta, float* __restrict__ z, int statOff) {
    extern __shared__ char smc[];
    unsigned sb = smem_u32(smc);
    int tid = threadIdx.x;
    int wid = tid >> 5, lane = tid & 31;
    int row0 = blockIdx.x * 128;

    float* scS = (float*)(smc + FM_MISC);
    float* shS = scS + 64;
    float* obsS = scS + 128;
    float* sred = (float*)(smc + FM_SRED);

    if (tid < 64) {
        const float inv_cnt = 1.0f / 131072.0f;
        float mu = g_stats[statOff + tid] * inv_cnt;
        float var = g_stats[statOff + 64 + tid] * inv_cnt - mu * mu;
        float scv = gam[tid] * rsqrtf(var + 1e-5f);
        scS[tid] = scv;
        shS[tid] = beta[tid] - mu * scv;
        obsS[tid] = ob[tid];
        sred[tid] = 0.f;
    }
    for (int i = tid; i < 1024; i += 256)
        ((float4*)(smc + FM_W))[i] = ((const float4*)wt)[i];
    __syncthreads();

    const float4* t4 = (const float4*)tmp;
    for (int i = tid; i < 2048; i += 256) {
        int y = i >> 4, q = i & 15;
        float4 v = t4[(long)(row0 + y) * 16 + q];
        float4 sc4 = *(const float4*)&scS[q * 4];
        float4 sh4 = *(const float4*)&shS[q * 4];
        float4 r;
        r.x = fmaxf(0.f, fmaf(v.x, sc4.x, sh4.x));
        r.y = fmaxf(0.f, fmaf(v.y, sc4.y, sh4.y));
        r.z = fmaxf(0.f, fmaf(v.z, sc4.z, sh4.z));
        r.w = fmaxf(0.f, fmaf(v.w, sc4.w, sh4.w));
        int off = y * 128 + q * 8;
        int sw = off ^ ((off >> 3) & 0x70);
        split_store(smc + FM_AH, smc + FM_AL, sw, r);
    }
    __syncthreads();

    int g = lane >> 2, tig = lane & 3;
    int m0 = wid * 16;

    float acc[8][4];
    #pragma unroll
    for (int s = 0; s < 8; s++)
        #pragma unroll
        for (int j = 0; j < 4; j++) acc[s][j] = 0.f;
    mma_3split_64(acc, sb, FM_AH, FM_AL, FM_W, m0, lane);

    int bq = row0 >> 10;
    int t0 = ((row0 + m0) >> 3) & 127;

    float w0 = g_wbar[t0 & 63] * 0.0078125f;
    float w1 = g_wbar[(t0 + 1) & 63] * 0.0078125f;
    float s0 = 0.f, s1 = 0.f;
    #pragma unroll
    for (int s = 0; s < 8; s++) {
        int c2 = s * 8 + tig * 2;
        float o0 = obsS[c2], o1 = obsS[c2 + 1];
        s0 += tanh_ap(acc[s][0] + o0) + tanh_ap(acc[s][1] + o1);
        s1 += tanh_ap(acc[s][2] + o0) + tanh_ap(acc[s][3] + o1);
    }
    float part = w0 * s0 + w1 * s1;
    part += __shfl_xor_sync(0xffffffffu, part, 1);
    part += __shfl_xor_sync(0xffffffffu, part, 2);
    part += __shfl_xor_sync(0xffffffffu, part, 16);
    int th = (t0 >> 6) & 1;
    if (tig == 0 && g < 4) {
        int idx = (2 * g + th) & 7;
        sred[idx * 8 + wid] = part;
    }
    __syncthreads();
    if (tid < 8) {
        float ssum = 0.f;
        #pragma unroll
        for (int w = 0; w < 8; w++) ssum += sred[tid * 8 + w];
        atomicAdd(&z[bq * 8 + tid], ssum);
    }
}

// ---------------- host launcher ----------------
extern "C" void kernel_launch(void* const* d_in, const int* in_sizes, int n_in,
                              void* d_out, int out_size) {
    const float* x      = (const float*)d_in[0];
    const int*   ei     = (const int*)d_in[1];
    const float* gcn1_w = (const float*)d_in[2];
    const float* gcn1_b = (const float*)d_in[3];
    const float* t1_w   = (const float*)d_in[4];
    const float* t1_b   = (const float*)d_in[5];
    const float* bn1_g  = (const float*)d_in[6];
    const float* bn1_b  = (const float*)d_in[7];
    const float* o1_w   = (const float*)d_in[8];
    const float* o1_b   = (const float*)d_in[9];
    const float* gcn2_w = (const float*)d_in[10];
    const float* gcn2_b = (const float*)d_in[11];
    const float* t2_w   = (const float*)d_in[12];
    const float* t2_b   = (const float*)d_in[13];
    const float* bn2_g  = (const float*)d_in[14];
    const float* bn2_b  = (const float*)d_in[15];
    const float* o2_w   = (const float*)d_in[16];
    const float* o2_b   = (const float*)d_in[17];
    const float* reg_w  = (const float*)d_in[18];
    const float* reg_b  = (const float*)d_in[19];
    float* out = (float*)d_out;

    const int* src = ei;
    const int* dst = ei + EDGES;

    cudaFuncSetAttribute(tconv_mma_kernel, cudaFuncAttributeMaxDynamicSharedMemorySize, TM_SMEM);
    cudaFuncSetAttribute(gemm_mma_kernel<32>, cudaFuncAttributeMaxDynamicSharedMemorySize, GM_SMEM);
    cudaFuncSetAttribute(fused_gemm2_kernel, cudaFuncAttributeMaxDynamicSharedMemorySize, F2_SMEM);
    cudaFuncSetAttribute(fused_final_kernel, cudaFuncAttributeMaxDynamicSharedMemorySize, FM_SMEM);

    float* bufA; cudaGetSymbolAddress((void**)&bufA, g_bufA);
    float* bufB; cudaGetSymbolAddress((void**)&bufB, g_bufB);
    float* bufC; cudaGetSymbolAddress((void**)&bufC, g_bufC);
    __nv_bfloat16* wt1; cudaGetSymbolAddress((void**)&wt1, g_wt1);
    __nv_bfloat16* wt2; cudaGetSymbolAddress((void**)&wt2, g_wt2);
    __nv_bfloat16* gw1; cudaGetSymbolAddress((void**)&gw1, g_gw1);
    __nv_bfloat16* gw2; cudaGetSymbolAddress((void**)&gw2, g_gw2);
    __nv_bfloat16* ow1; cudaGetSymbolAddress((void**)&ow1, g_ow1);
    __nv_bfloat16* ow2; cudaGetSymbolAddress((void**)&ow2, g_ow2);

    prologue_kernel<<<512, 256>>>(reg_w, reg_b, t1_w, t2_w, gcn1_w, gcn2_w, o1_w, o2_w);
    hist_kernel<<<EDGES / 256, 256>>>(dst);
    scan1_kernel<<<128, 256>>>();
    scan3_kernel<<<NROWS / 256, 256>>>(reg_b, out);
    scatter_kernel<<<EDGES / 256, 256>>>(src, dst);

    // -------- layer 1 --------
    gemm_mma_kernel<32><<<NROWS / 128, 256, GM_SMEM>>>(x, gw1, bufA);
    gather_agg_kernel<<<NROWS / 16, 256>>>(bufA, gcn1_b, bufB);
    tconv_mma_kernel<<<1024, 256, TM_SMEM>>>(bufB, wt1, t1_b, bufC, 0);
    fused_gemm2_kernel<<<1024, 256, F2_SMEM>>>(bufC, ow1, gw2, o1_b, bn1_g, bn1_b, bufA);

    // -------- layer 2 --------
    gather_agg_kernel<<<NROWS / 16, 256>>>(bufA, gcn2_b, bufB);
    tconv_mma_kernel<<<1024, 256, TM_SMEM>>>(bufB, wt2, t2_b, bufC, 128);
    fused_final_kernel<<<NROWS / 128, 256, FM_SMEM>>>(bufC, ow2, o2_b, bn2_g, bn2_b, out, 128);
}